// round 1
// baseline (speedup 1.0000x reference)
#include <cuda_runtime.h>
#include <math.h>

#define Nn 4
#define Kk 1024
#define Mm 1024
#define Hh 16
#define Dd 64
#define Ff 4096
#define NK 4096   // Nn*Kk

// ---------------- scratch (no allocations allowed) ----------------
__device__ float g_wp[6 * Mm * Mm];     // repacked qkv weights (self q,k,v ; cross q,k,v)
__device__ float g_q[NK * Mm];
__device__ float g_k[NK * Mm];
__device__ float g_v[NK * Mm];
__device__ float g_att[NK * Mm];
__device__ float g_x[NK * Mm];
__device__ float g_y[NK * Mm];
__device__ float g_hid[NK * Ff];

// ---------------- weight repack: W[h,m,d] -> Wp[m, h*D+d] ----------------
__global__ void pack_kernel(const float* __restrict__ W, float* __restrict__ Wp) {
    int idx = blockIdx.x * 256 + threadIdx.x;   // < Mm*Mm
    int m = idx >> 10;
    int j = idx & 1023;
    int h = j >> 6;
    int d = j & 63;
    Wp[idx] = W[h * (Mm * Dd) + m * Dd + d];
}

// ---------------- generic fp32 GEMM: C[I,J] = A[I,Kd] @ B[Kd,J] (+bias +res, relu) ----
// BM=BN=64, BK=16, 256 threads, 4x4 micro-tile
__global__ void gemm_kernel(const float* __restrict__ A, const float* __restrict__ B,
                            const float* __restrict__ bias, const float* __restrict__ res,
                            float* __restrict__ C, int Kd, int J, int relu)
{
    __shared__ float As[16][68];   // [k][m], padded
    __shared__ float Bs[16][64];   // [k][n]

    int tid = threadIdx.x;
    int tx = tid & 15, ty = tid >> 4;
    int i0 = blockIdx.y * 64, j0 = blockIdx.x * 64;

    float acc[4][4] = {};

    const float* Ab = A + (size_t)i0 * Kd;
    const float* Bb = B + j0;

    for (int k0 = 0; k0 < Kd; k0 += 16) {
        // A tile 64x16 -> As[k][m]
        {
            int r  = tid >> 2;
            int c4 = (tid & 3) << 2;
            float4 a = *(const float4*)(Ab + (size_t)r * Kd + k0 + c4);
            As[c4 + 0][r] = a.x;
            As[c4 + 1][r] = a.y;
            As[c4 + 2][r] = a.z;
            As[c4 + 3][r] = a.w;
            // B tile 16x64
            int rr = tid >> 4;
            int cc = (tid & 15) << 2;
            float4 b = *(const float4*)(Bb + (size_t)(k0 + rr) * J + cc);
            *(float4*)&Bs[rr][cc] = b;
        }
        __syncthreads();
        #pragma unroll
        for (int kk = 0; kk < 16; kk++) {
            float4 a4 = *(const float4*)&As[kk][ty * 4];
            float4 b4 = *(const float4*)&Bs[kk][tx * 4];
            float a[4] = {a4.x, a4.y, a4.z, a4.w};
            float b[4] = {b4.x, b4.y, b4.z, b4.w};
            #pragma unroll
            for (int i = 0; i < 4; i++)
                #pragma unroll
                for (int j = 0; j < 4; j++)
                    acc[i][j] += a[i] * b[j];
        }
        __syncthreads();
    }

    #pragma unroll
    for (int i = 0; i < 4; i++) {
        int gi = i0 + ty * 4 + i;
        #pragma unroll
        for (int j = 0; j < 4; j++) {
            int gj = j0 + tx * 4 + j;
            float v = acc[i][j];
            if (bias) v += bias[gj];
            if (res)  v += res[(size_t)gi * J + gj];
            if (relu) v = fmaxf(v, 0.f);
            C[(size_t)gi * J + gj] = v;
        }
    }
}

// ---------------- fused attention (flash-style online softmax) ----------------
// grid: (Kk/64, Nn*Hh), block 256. Q/K/V stored as [NK, M] with head at col h*D.
#define AP 68
#define ATTN_SMEM (4 * 64 * AP * 4 + 3 * 64 * 4)

__global__ void attn_kernel(const float* __restrict__ Q, const float* __restrict__ Kb,
                            const float* __restrict__ Vb, const int* __restrict__ mask,
                            float* __restrict__ O)
{
    extern __shared__ float sm[];
    float* sQt = sm;                 // [d][r]  64x68
    float* sKt = sQt + 64 * AP;      // [d][c]
    float* sS  = sKt + 64 * AP;      // [r][c]
    float* sV  = sS  + 64 * AP;      // [l][d]
    float* sM  = sV  + 64 * AP;      // 64
    float* sL  = sM + 64;
    float* sSc = sL + 64;

    int tid = threadIdx.x;
    int tx = tid & 15, ty = tid >> 4;
    int nh = blockIdx.y;
    int n = nh >> 4, h = nh & 15;
    int q0 = blockIdx.x * 64;

    size_t baseQ  = ((size_t)n * Kk + q0) * Mm + h * Dd;
    size_t baseKV = ((size_t)n * Kk) * Mm + h * Dd;

    // load Q tile transposed
    #pragma unroll
    for (int it = 0; it < 4; it++) {
        int r  = it * 16 + (tid >> 4);
        int d4 = (tid & 15) << 2;
        float4 qv = *(const float4*)(Q + baseQ + (size_t)r * Mm + d4);
        sQt[(d4 + 0) * AP + r] = qv.x;
        sQt[(d4 + 1) * AP + r] = qv.y;
        sQt[(d4 + 2) * AP + r] = qv.z;
        sQt[(d4 + 3) * AP + r] = qv.w;
    }
    if (tid < 64) { sM[tid] = -1e30f; sL[tid] = 0.f; }

    float o[4][4] = {};
    const float scale = 0.125f;   // 1/sqrt(64)

    for (int l0 = 0; l0 < Kk; l0 += 64) {
        // load K (transposed) and V tiles
        #pragma unroll
        for (int it = 0; it < 4; it++) {
            int r  = it * 16 + (tid >> 4);
            int d4 = (tid & 15) << 2;
            float4 kv = *(const float4*)(Kb + baseKV + (size_t)(l0 + r) * Mm + d4);
            sKt[(d4 + 0) * AP + r] = kv.x;
            sKt[(d4 + 1) * AP + r] = kv.y;
            sKt[(d4 + 2) * AP + r] = kv.z;
            sKt[(d4 + 3) * AP + r] = kv.w;
            float4 vv = *(const float4*)(Vb + baseKV + (size_t)(l0 + r) * Mm + d4);
            *(float4*)&sV[r * AP + d4] = vv;
        }
        __syncthreads();

        // S = Q K^T (4x4 per thread)
        float s[4][4] = {};
        #pragma unroll
        for (int d = 0; d < 64; d++) {
            float4 a4 = *(const float4*)&sQt[d * AP + ty * 4];
            float4 b4 = *(const float4*)&sKt[d * AP + tx * 4];
            float a[4] = {a4.x, a4.y, a4.z, a4.w};
            float b[4] = {b4.x, b4.y, b4.z, b4.w};
            #pragma unroll
            for (int i = 0; i < 4; i++)
                #pragma unroll
                for (int j = 0; j < 4; j++)
                    s[i][j] += a[i] * b[j];
        }
        #pragma unroll
        for (int i = 0; i < 4; i++) {
            int qg = q0 + ty * 4 + i;
            #pragma unroll
            for (int j = 0; j < 4; j++) {
                float v = s[i][j] * scale;
                if (mask) {
                    int lg = l0 + tx * 4 + j;
                    if (mask[((size_t)n * Kk + qg) * Kk + lg] == 0) v = -1e30f;
                }
                sS[(ty * 4 + i) * AP + tx * 4 + j] = v;
            }
        }
        __syncthreads();

        // row max + rescale factor (4 lanes per row)
        {
            int r = tid >> 2, qt = tid & 3;
            float tm = -1e30f;
            #pragma unroll
            for (int c = 0; c < 16; c++) tm = fmaxf(tm, sS[r * AP + qt * 16 + c]);
            tm = fmaxf(tm, __shfl_xor_sync(0xffffffff, tm, 1));
            tm = fmaxf(tm, __shfl_xor_sync(0xffffffff, tm, 2));
            if (qt == 0) {
                float mold = sM[r];
                float mnew = fmaxf(mold, tm);
                sSc[r] = __expf(mold - mnew);
                sM[r] = mnew;
            }
        }
        __syncthreads();

        // exponentiate
        #pragma unroll
        for (int i = 0; i < 4; i++) {
            int r = ty * 4 + i;
            float mnew = sM[r];
            #pragma unroll
            for (int j = 0; j < 4; j++) {
                int c = tx * 4 + j;
                sS[r * AP + c] = __expf(sS[r * AP + c] - mnew);
            }
        }
        __syncthreads();

        // row sums
        {
            int r = tid >> 2, qt = tid & 3;
            float sum = 0.f;
            #pragma unroll
            for (int c = 0; c < 16; c++) sum += sS[r * AP + qt * 16 + c];
            sum += __shfl_xor_sync(0xffffffff, sum, 1);
            sum += __shfl_xor_sync(0xffffffff, sum, 2);
            if (qt == 0) sL[r] = sL[r] * sSc[r] + sum;
        }

        // O = O*scale + P @ V
        float sc[4];
        #pragma unroll
        for (int i = 0; i < 4; i++) sc[i] = sSc[ty * 4 + i];
        #pragma unroll
        for (int i = 0; i < 4; i++)
            #pragma unroll
            for (int j = 0; j < 4; j++)
                o[i][j] *= sc[i];

        #pragma unroll
        for (int l = 0; l < 64; l++) {
            float4 v4 = *(const float4*)&sV[l * AP + tx * 4];
            float vb[4] = {v4.x, v4.y, v4.z, v4.w};
            float p[4];
            #pragma unroll
            for (int i = 0; i < 4; i++) p[i] = sS[(ty * 4 + i) * AP + l];
            #pragma unroll
            for (int i = 0; i < 4; i++)
                #pragma unroll
                for (int j = 0; j < 4; j++)
                    o[i][j] += p[i] * vb[j];
        }
        __syncthreads();
    }

    // normalize and store
    #pragma unroll
    for (int i = 0; i < 4; i++) {
        float invl = 1.f / sL[ty * 4 + i];
        size_t rowbase = ((size_t)n * Kk + q0 + ty * 4 + i) * Mm + h * Dd + tx * 4;
        #pragma unroll
        for (int j = 0; j < 4; j++)
            O[rowbase + j] = o[i][j] * invl;
    }
}

// ---------------- LayerNorm (block per row, M=1024) ----------------
__global__ void ln_kernel(const float* __restrict__ X, const float* __restrict__ g,
                          const float* __restrict__ b, float* __restrict__ Y)
{
    int row = blockIdx.x;
    int tid = threadIdx.x;
    const float* x = X + (size_t)row * Mm;
    float4 v = *(const float4*)(x + tid * 4);

    __shared__ float red[256];
    red[tid] = v.x + v.y + v.z + v.w;
    __syncthreads();
    for (int o = 128; o > 0; o >>= 1) {
        if (tid < o) red[tid] += red[tid + o];
        __syncthreads();
    }
    float mu = red[0] * (1.f / 1024.f);
    __syncthreads();

    float d0 = v.x - mu, d1 = v.y - mu, d2 = v.z - mu, d3 = v.w - mu;
    red[tid] = d0 * d0 + d1 * d1 + d2 * d2 + d3 * d3;
    __syncthreads();
    for (int o = 128; o > 0; o >>= 1) {
        if (tid < o) red[tid] += red[tid + o];
        __syncthreads();
    }
    float inv = rsqrtf(red[0] * (1.f / 1024.f) + 1e-5f);

    float4 gg = *(const float4*)(g + tid * 4);
    float4 bb = *(const float4*)(b + tid * 4);
    float4 y;
    y.x = d0 * inv * gg.x + bb.x;
    y.y = d1 * inv * gg.y + bb.y;
    y.z = d2 * inv * gg.z + bb.z;
    y.w = d3 * inv * gg.w + bb.w;
    *(float4*)(Y + (size_t)row * Mm + tid * 4) = y;
}

// ---------------- host ----------------
static void launch_gemm(const float* A, const float* B, const float* bias,
                        const float* res, float* C, int I, int Kd, int J, int relu)
{
    dim3 grid(J / 64, I / 64);
    gemm_kernel<<<grid, 256>>>(A, B, bias, res, C, Kd, J, relu);
}

extern "C" void kernel_launch(void* const* d_in, const int* in_sizes, int n_in,
                              void* d_out, int out_size)
{
    const float* dec  = (const float*)d_in[0];
    const float* enc  = (const float*)d_in[1];
    const int*   mask = (const int*)  d_in[2];
    const float* Wq_s = (const float*)d_in[3];  const float* bq_s = (const float*)d_in[4];
    const float* Wk_s = (const float*)d_in[5];  const float* bk_s = (const float*)d_in[6];
    const float* Wv_s = (const float*)d_in[7];  const float* bv_s = (const float*)d_in[8];
    const float* Wo_s = (const float*)d_in[9];  const float* bo_s = (const float*)d_in[10];
    const float* Wq_c = (const float*)d_in[11]; const float* bq_c = (const float*)d_in[12];
    const float* Wk_c = (const float*)d_in[13]; const float* bk_c = (const float*)d_in[14];
    const float* Wv_c = (const float*)d_in[15]; const float* bv_c = (const float*)d_in[16];
    const float* Wo_c = (const float*)d_in[17]; const float* bo_c = (const float*)d_in[18];
    const float* W1   = (const float*)d_in[19]; const float* b1   = (const float*)d_in[20];
    const float* W2   = (const float*)d_in[21]; const float* b2   = (const float*)d_in[22];
    const float* g1   = (const float*)d_in[23]; const float* be1  = (const float*)d_in[24];
    const float* g2   = (const float*)d_in[25]; const float* be2  = (const float*)d_in[26];
    const float* g3   = (const float*)d_in[27]; const float* be3  = (const float*)d_in[28];
    float* out = (float*)d_out;

    cudaFuncSetAttribute(attn_kernel, cudaFuncAttributeMaxDynamicSharedMemorySize, ATTN_SMEM);

    float *wp, *q, *k, *v, *att, *x, *y, *hid;
    cudaGetSymbolAddress((void**)&wp,  g_wp);
    cudaGetSymbolAddress((void**)&q,   g_q);
    cudaGetSymbolAddress((void**)&k,   g_k);
    cudaGetSymbolAddress((void**)&v,   g_v);
    cudaGetSymbolAddress((void**)&att, g_att);
    cudaGetSymbolAddress((void**)&x,   g_x);
    cudaGetSymbolAddress((void**)&y,   g_y);
    cudaGetSymbolAddress((void**)&hid, g_hid);

    const int MM = Mm * Mm;
    int packBlocks = MM / 256;
    pack_kernel<<<packBlocks, 256>>>(Wq_s, wp + 0 * MM);
    pack_kernel<<<packBlocks, 256>>>(Wk_s, wp + 1 * MM);
    pack_kernel<<<packBlocks, 256>>>(Wv_s, wp + 2 * MM);
    pack_kernel<<<packBlocks, 256>>>(Wq_c, wp + 3 * MM);
    pack_kernel<<<packBlocks, 256>>>(Wk_c, wp + 4 * MM);
    pack_kernel<<<packBlocks, 256>>>(Wv_c, wp + 5 * MM);

    dim3 agrid(Kk / 64, Nn * Hh);

    // ---- self attention ----
    launch_gemm(dec, wp + 0 * MM, bq_s, nullptr, q, NK, Mm, Mm, 0);
    launch_gemm(dec, wp + 1 * MM, bk_s, nullptr, k, NK, Mm, Mm, 0);
    launch_gemm(dec, wp + 2 * MM, bv_s, nullptr, v, NK, Mm, Mm, 0);
    attn_kernel<<<agrid, 256, ATTN_SMEM>>>(q, k, v, mask, att);
    launch_gemm(att, Wo_s, bo_s, dec, x, NK, Mm, Mm, 0);       // out1 + dec
    ln_kernel<<<NK, 256>>>(x, g1, be1, y);                      // out2 -> y

    // ---- cross attention ----
    launch_gemm(y,   wp + 3 * MM, bq_c, nullptr, q, NK, Mm, Mm, 0);
    launch_gemm(enc, wp + 4 * MM, bk_c, nullptr, k, NK, Mm, Mm, 0);
    launch_gemm(enc, wp + 5 * MM, bv_c, nullptr, v, NK, Mm, Mm, 0);
    attn_kernel<<<agrid, 256, ATTN_SMEM>>>(q, k, v, nullptr, att);
    launch_gemm(att, Wo_c, bo_c, y, x, NK, Mm, Mm, 0);          // out3 + out2
    ln_kernel<<<NK, 256>>>(x, g2, be2, att);                     // out4 -> att

    // ---- feedforward ----
    launch_gemm(att, W1, b1, nullptr, hid, NK, Mm, Ff, 1);      // relu(out4@W1+b1)
    launch_gemm(hid, W2, b2, att, x, NK, Ff, Mm, 0);            // + out4
    ln_kernel<<<NK, 256>>>(x, g3, be3, out);
}

// round 7
// speedup vs baseline: 1.7540x; 1.7540x over previous
#include <cuda_runtime.h>
#include <cuda_bf16.h>
#include <stdint.h>
#include <math.h>

#define Nn 4
#define Kk 1024
#define Mm 1024
#define Hh 16
#define Dd 64
#define Ff 4096
#define NK 4096   // Nn*Kk

typedef __nv_bfloat16 bf16;

// ---------------- scratch (no allocations allowed) ----------------
__device__ float g_q[NK * Mm];
__device__ float g_k[NK * Mm];
__device__ float g_v[NK * Mm];
__device__ float g_x[NK * Mm];
__device__ float g_y[NK * Mm];
__device__ float g_z[NK * Mm];

__device__ __align__(256) bf16 g_dh[NK * Mm], g_dl[NK * Mm];   // dec hi/lo
__device__ __align__(256) bf16 g_eh[NK * Mm], g_el[NK * Mm];   // enc hi/lo
__device__ __align__(256) bf16 g_yh[NK * Mm], g_yl[NK * Mm];   // ln1 out hi/lo
__device__ __align__(256) bf16 g_zh[NK * Mm], g_zl[NK * Mm];   // ln2 out hi/lo
__device__ __align__(256) bf16 g_ah[NK * Mm], g_al[NK * Mm];   // attn out hi/lo
__device__ __align__(256) bf16 g_hh[NK * Ff], g_hl[NK * Ff];   // ffn hidden hi/lo
__device__ __align__(256) bf16 g_wh[16 * 1024 * 1024];         // transposed weights hi
__device__ __align__(256) bf16 g_wl[16 * 1024 * 1024];         // transposed weights lo

// weight offsets (elements) in g_wh/g_wl
#define WOFF_QS (0 * 1048576)
#define WOFF_KS (1 * 1048576)
#define WOFF_VS (2 * 1048576)
#define WOFF_QC (3 * 1048576)
#define WOFF_KC (4 * 1048576)
#define WOFF_VC (5 * 1048576)
#define WOFF_OS (6 * 1048576)
#define WOFF_OC (7 * 1048576)
#define WOFF_W1 (8 * 1048576)
#define WOFF_W2 (12 * 1048576)

// ---------------- PTX helpers (family-safe: mma.sync / ldmatrix / cp.async) ----------------
__device__ __forceinline__ uint32_t smem_u32(const void* p) {
    uint32_t a;
    asm("{ .reg .u64 t; cvta.to.shared.u64 t, %1; cvt.u32.u64 %0, t; }" : "=r"(a) : "l"(p));
    return a;
}

__device__ __forceinline__ void cp16(uint32_t s, const void* g) {
    asm volatile("cp.async.cg.shared.global [%0], [%1], 16;" :: "r"(s), "l"(g));
}

__device__ __forceinline__ void ldm4(uint32_t* r, uint32_t addr) {
    asm volatile("ldmatrix.sync.aligned.m8n8.x4.shared.b16 {%0,%1,%2,%3}, [%4];"
                 : "=r"(r[0]), "=r"(r[1]), "=r"(r[2]), "=r"(r[3]) : "r"(addr));
}

__device__ __forceinline__ void mma16816(float* c, const uint32_t* a, const uint32_t* b) {
    asm volatile(
        "mma.sync.aligned.m16n8k16.row.col.f32.bf16.bf16.f32 "
        "{%0,%1,%2,%3}, {%4,%5,%6,%7}, {%8,%9}, {%0,%1,%2,%3};"
        : "+f"(c[0]), "+f"(c[1]), "+f"(c[2]), "+f"(c[3])
        : "r"(a[0]), "r"(a[1]), "r"(a[2]), "r"(a[3]), "r"(b[0]), "r"(b[1]));
}

// ---------------- tensor-core GEMM: C[I,J] = (Ah+Al)[I,Kd] @ (Bh+Bl)^T ----------------
// A: [I,Kd] K-major bf16 hi/lo. B: [J,Kd] K-major bf16 hi/lo (pre-transposed weight).
// 128x128x32 CTA tile, 256 threads (8 warps, 2x4), warp tile 64x32. 3-term split.
#define ROWB 80                 // smem row stride bytes (32 bf16 = 64B data + 16B pad)
#define OPBYTES (128 * ROWB)    // 10240 per operand tile
#define STAGEB (4 * OPBYTES)    // 40960 per stage (Ah, Al, Bh, Bl)
#define GSM_SIZE (2 * STAGEB)   // 81920

__global__ __launch_bounds__(256) void gemm_tc(
    const bf16* __restrict__ Ah, const bf16* __restrict__ Al,
    const bf16* __restrict__ Bh, const bf16* __restrict__ Bl,
    const float* __restrict__ bias, const float* __restrict__ res,
    float* __restrict__ Cf, bf16* __restrict__ Ch, bf16* __restrict__ Cl,
    int Kd, int J, int relu)
{
    extern __shared__ char smem[];
    uint32_t sb = smem_u32(smem);
    int tid = threadIdx.x;
    int wid = tid >> 5, lane = tid & 31;
    int wm = wid >> 2, wn = wid & 3;            // warp grid 2 (M) x 4 (N)
    int i0 = blockIdx.y << 7, j0 = blockIdx.x << 7;

    size_t rowBytes = (size_t)Kd * 2;
    const char* gp[4] = {
        (const char*)(Ah + (size_t)i0 * Kd),
        (const char*)(Al + (size_t)i0 * Kd),
        (const char*)(Bh + (size_t)j0 * Kd),
        (const char*)(Bl + (size_t)j0 * Kd)
    };

    // per-thread staging: 512 16B-chunks per operand; 2 per thread per operand
    int r0c = tid >> 2, c0c = tid & 3;              // chunk 0: row tid/4, col tid%4
    int r1c = (tid + 256) >> 2, c1c = tid & 3;      // chunk 1

    auto load_stage = [&](int s, int k0) {
        uint32_t base = sb + (s & 1) * STAGEB;
        size_t gk = (size_t)k0 * 2;
        #pragma unroll
        for (int op = 0; op < 4; op++) {
            cp16(base + op * OPBYTES + r0c * ROWB + c0c * 16,
                 gp[op] + (size_t)r0c * rowBytes + gk + c0c * 16);
            cp16(base + op * OPBYTES + r1c * ROWB + c1c * 16,
                 gp[op] + (size_t)r1c * rowBytes + gk + c1c * 16);
        }
        asm volatile("cp.async.commit_group;" ::: "memory");
    };

    float acc[4][4][4] = {};

    // ldmatrix lane addressing (precomputed row/byte offsets)
    int aRow = wm * 64 + (lane & 7) + ((lane >> 3) & 1) * 8;   // + fm*16
    int aByte = ((lane >> 4) & 1) * 16;                         // + ks*32
    int bRow = wn * 32 + (lane & 7) + ((lane >> 4) & 1) * 8;   // + pair*16
    int bByte = ((lane >> 3) & 1) * 16;                         // + ks*32

    int S = Kd >> 5;
    load_stage(0, 0);

    for (int s = 0; s < S; s++) {
        if (s + 1 < S) {
            load_stage(s + 1, (s + 1) << 5);
            asm volatile("cp.async.wait_group 1;" ::: "memory");
        } else {
            asm volatile("cp.async.wait_group 0;" ::: "memory");
        }
        __syncthreads();

        uint32_t aB  = sb + (s & 1) * STAGEB;
        uint32_t alB = aB + OPBYTES;
        uint32_t bB  = aB + 2 * OPBYTES;
        uint32_t blB = aB + 3 * OPBYTES;

        #pragma unroll
        for (int ks = 0; ks < 2; ks++) {
            uint32_t ah[4][4], al_[4][4];
            #pragma unroll
            for (int fm = 0; fm < 4; fm++) {
                uint32_t off = (uint32_t)(aRow + fm * 16) * ROWB + ks * 32 + aByte;
                ldm4(ah[fm],  aB  + off);
                ldm4(al_[fm], alB + off);
            }
            uint32_t bh[4][2], bl[4][2];   // [fn][2]
            #pragma unroll
            for (int p = 0; p < 2; p++) {  // x4 covers n-frags 2p, 2p+1
                uint32_t off = (uint32_t)(bRow + p * 16) * ROWB + ks * 32 + bByte;
                uint32_t t[4];
                ldm4(t, bB + off);
                bh[2 * p][0] = t[0]; bh[2 * p][1] = t[1];
                bh[2 * p + 1][0] = t[2]; bh[2 * p + 1][1] = t[3];
                ldm4(t, blB + off);
                bl[2 * p][0] = t[0]; bl[2 * p][1] = t[1];
                bl[2 * p + 1][0] = t[2]; bl[2 * p + 1][1] = t[3];
            }
            #pragma unroll
            for (int fm = 0; fm < 4; fm++)
                #pragma unroll
                for (int fn = 0; fn < 4; fn++) {
                    mma16816(acc[fm][fn], ah[fm],  bh[fn]);
                    mma16816(acc[fm][fn], ah[fm],  bl[fn]);
                    mma16816(acc[fm][fn], al_[fm], bh[fn]);
                }
        }
        __syncthreads();
    }

    // ---- epilogue ----
    bool hb = bias != nullptr, hr = res != nullptr, hf = Cf != nullptr, hh = Ch != nullptr;
    int g = lane >> 2, q = lane & 3;
    #pragma unroll
    for (int fm = 0; fm < 4; fm++) {
        #pragma unroll
        for (int fn = 0; fn < 4; fn++) {
            int col = j0 + wn * 32 + fn * 8 + q * 2;
            #pragma unroll
            for (int half = 0; half < 2; half++) {
                int row = i0 + wm * 64 + fm * 16 + g + half * 8;
                size_t base = (size_t)row * J + col;
                #pragma unroll
                for (int e = 0; e < 2; e++) {
                    float v = acc[fm][fn][half * 2 + e];
                    if (hb) v += bias[col + e];
                    if (hr) v += res[base + e];
                    if (relu) v = fmaxf(v, 0.f);
                    if (hf) Cf[base + e] = v;
                    if (hh) {
                        bf16 h = __float2bfloat16(v);
                        Ch[base + e] = h;
                        Cl[base + e] = __float2bfloat16(v - __bfloat162float(h));
                    }
                }
            }
        }
    }
}

// ---------------- transpose + hi/lo convert: out[c][r] = in[r][c] ----------------
__global__ void trans_conv(const float* __restrict__ in, bf16* __restrict__ oh,
                           bf16* __restrict__ ol, int R, int C,
                           size_t inStrideZ, size_t outStrideZ)
{
    __shared__ float t[32][33];
    int c0 = blockIdx.x * 32, r0 = blockIdx.y * 32;
    const float* ip = in + (size_t)blockIdx.z * inStrideZ;
    int tx = threadIdx.x, ty = threadIdx.y;
    #pragma unroll
    for (int i = 0; i < 4; i++)
        t[ty + i * 8][tx] = ip[(size_t)(r0 + ty + i * 8) * C + c0 + tx];
    __syncthreads();
    size_t ob = (size_t)blockIdx.z * outStrideZ;
    #pragma unroll
    for (int i = 0; i < 4; i++) {
        float v = t[tx][ty + i * 8];
        size_t o = ob + (size_t)(c0 + ty + i * 8) * R + r0 + tx;
        bf16 h = __float2bfloat16(v);
        oh[o] = h;
        ol[o] = __float2bfloat16(v - __bfloat162float(h));
    }
}

// ---------------- elementwise fp32 -> bf16 hi/lo ----------------
__global__ void conv_hl(const float* __restrict__ in, bf16* __restrict__ oh,
                        bf16* __restrict__ ol)
{
    int i = (blockIdx.x * 256 + threadIdx.x) * 4;
    float4 v = *(const float4*)(in + i);
    float vv[4] = {v.x, v.y, v.z, v.w};
    #pragma unroll
    for (int c = 0; c < 4; c++) {
        bf16 h = __float2bfloat16(vv[c]);
        oh[i + c] = h;
        ol[i + c] = __float2bfloat16(vv[c] - __bfloat162float(h));
    }
}

// ---------------- fused attention (flash-style online softmax, fp32) ----------------
#define AP 68
#define ATTN_SMEM (4 * 64 * AP * 4 + 3 * 64 * 4)

__global__ void attn_kernel(const float* __restrict__ Q, const float* __restrict__ Kb,
                            const float* __restrict__ Vb, const int* __restrict__ mask,
                            bf16* __restrict__ Oh, bf16* __restrict__ Ol)
{
    extern __shared__ float sm[];
    float* sQt = sm;                 // [d][r]  64x68
    float* sKt = sQt + 64 * AP;      // [d][c]
    float* sS  = sKt + 64 * AP;      // [r][c]
    float* sV  = sS  + 64 * AP;      // [l][d]
    float* sM  = sV  + 64 * AP;      // 64
    float* sL  = sM + 64;
    float* sSc = sL + 64;

    int tid = threadIdx.x;
    int tx = tid & 15, ty = tid >> 4;
    int nh = blockIdx.y;
    int n = nh >> 4, h = nh & 15;
    int q0 = blockIdx.x * 64;

    size_t baseQ  = ((size_t)n * Kk + q0) * Mm + h * Dd;
    size_t baseKV = ((size_t)n * Kk) * Mm + h * Dd;

    #pragma unroll
    for (int it = 0; it < 4; it++) {
        int r  = it * 16 + (tid >> 4);
        int d4 = (tid & 15) << 2;
        float4 qv = *(const float4*)(Q + baseQ + (size_t)r * Mm + d4);
        sQt[(d4 + 0) * AP + r] = qv.x;
        sQt[(d4 + 1) * AP + r] = qv.y;
        sQt[(d4 + 2) * AP + r] = qv.z;
        sQt[(d4 + 3) * AP + r] = qv.w;
    }
    if (tid < 64) { sM[tid] = -1e30f; sL[tid] = 0.f; }

    float o[4][4] = {};
    const float scale = 0.125f;

    for (int l0 = 0; l0 < Kk; l0 += 64) {
        #pragma unroll
        for (int it = 0; it < 4; it++) {
            int r  = it * 16 + (tid >> 4);
            int d4 = (tid & 15) << 2;
            float4 kv = *(const float4*)(Kb + baseKV + (size_t)(l0 + r) * Mm + d4);
            sKt[(d4 + 0) * AP + r] = kv.x;
            sKt[(d4 + 1) * AP + r] = kv.y;
            sKt[(d4 + 2) * AP + r] = kv.z;
            sKt[(d4 + 3) * AP + r] = kv.w;
            float4 vv = *(const float4*)(Vb + baseKV + (size_t)(l0 + r) * Mm + d4);
            *(float4*)&sV[r * AP + d4] = vv;
        }
        __syncthreads();

        float s[4][4] = {};
        #pragma unroll
        for (int d = 0; d < 64; d++) {
            float4 a4 = *(const float4*)&sQt[d * AP + ty * 4];
            float4 b4 = *(const float4*)&sKt[d * AP + tx * 4];
            float a[4] = {a4.x, a4.y, a4.z, a4.w};
            float b[4] = {b4.x, b4.y, b4.z, b4.w};
            #pragma unroll
            for (int i = 0; i < 4; i++)
                #pragma unroll
                for (int j = 0; j < 4; j++)
                    s[i][j] += a[i] * b[j];
        }
        #pragma unroll
        for (int i = 0; i < 4; i++) {
            int qg = q0 + ty * 4 + i;
            #pragma unroll
            for (int j = 0; j < 4; j++) {
                float v = s[i][j] * scale;
                if (mask) {
                    int lg = l0 + tx * 4 + j;
                    if (mask[((size_t)n * Kk + qg) * Kk + lg] == 0) v = -1e30f;
                }
                sS[(ty * 4 + i) * AP + tx * 4 + j] = v;
            }
        }
        __syncthreads();

        {
            int r = tid >> 2, qt = tid & 3;
            float tm = -1e30f;
            #pragma unroll
            for (int c = 0; c < 16; c++) tm = fmaxf(tm, sS[r * AP + qt * 16 + c]);
            tm = fmaxf(tm, __shfl_xor_sync(0xffffffff, tm, 1));
            tm = fmaxf(tm, __shfl_xor_sync(0xffffffff, tm, 2));
            if (qt == 0) {
                float mold = sM[r];
                float mnew = fmaxf(mold, tm);
                sSc[r] = __expf(mold - mnew);
                sM[r] = mnew;
            }
        }
        __syncthreads();

        #pragma unroll
        for (int i = 0; i < 4; i++) {
            int r = ty * 4 + i;
            float mnew = sM[r];
            #pragma unroll
            for (int j = 0; j < 4; j++) {
                int c = tx * 4 + j;
                sS[r * AP + c] = __expf(sS[r * AP + c] - mnew);
            }
        }
        __syncthreads();

        {
            int r = tid >> 2, qt = tid & 3;
            float sum = 0.f;
            #pragma unroll
            for (int c = 0; c < 16; c++) sum += sS[r * AP + qt * 16 + c];
            sum += __shfl_xor_sync(0xffffffff, sum, 1);
            sum += __shfl_xor_sync(0xffffffff, sum, 2);
            if (qt == 0) sL[r] = sL[r] * sSc[r] + sum;
        }

        float sc[4];
        #pragma unroll
        for (int i = 0; i < 4; i++) sc[i] = sSc[ty * 4 + i];
        #pragma unroll
        for (int i = 0; i < 4; i++)
            #pragma unroll
            for (int j = 0; j < 4; j++)
                o[i][j] *= sc[i];

        #pragma unroll
        for (int l = 0; l < 64; l++) {
            float4 v4 = *(const float4*)&sV[l * AP + tx * 4];
            float vb[4] = {v4.x, v4.y, v4.z, v4.w};
            float p[4];
            #pragma unroll
            for (int i = 0; i < 4; i++) p[i] = sS[(ty * 4 + i) * AP + l];
            #pragma unroll
            for (int i = 0; i < 4; i++)
                #pragma unroll
                for (int j = 0; j < 4; j++)
                    o[i][j] += p[i] * vb[j];
        }
        __syncthreads();
    }

    #pragma unroll
    for (int i = 0; i < 4; i++) {
        float invl = 1.f / sL[ty * 4 + i];
        size_t rowbase = ((size_t)n * Kk + q0 + ty * 4 + i) * Mm + h * Dd + tx * 4;
        #pragma unroll
        for (int j = 0; j < 4; j++) {
            float val = o[i][j] * invl;
            bf16 hv = __float2bfloat16(val);
            Oh[rowbase + j] = hv;
            Ol[rowbase + j] = __float2bfloat16(val - __bfloat162float(hv));
        }
    }
}

// ---------------- LayerNorm (block per row, M=1024), optional hi/lo out ----------------
__global__ void ln_kernel(const float* __restrict__ X, const float* __restrict__ g,
                          const float* __restrict__ b, float* __restrict__ Y,
                          bf16* __restrict__ Yh, bf16* __restrict__ Yl)
{
    int row = blockIdx.x;
    int tid = threadIdx.x;
    const float* x = X + (size_t)row * Mm;
    float4 v = *(const float4*)(x + tid * 4);

    __shared__ float red[256];
    red[tid] = v.x + v.y + v.z + v.w;
    __syncthreads();
    for (int o = 128; o > 0; o >>= 1) {
        if (tid < o) red[tid] += red[tid + o];
        __syncthreads();
    }
    float mu = red[0] * (1.f / 1024.f);
    __syncthreads();

    float d0 = v.x - mu, d1 = v.y - mu, d2 = v.z - mu, d3 = v.w - mu;
    red[tid] = d0 * d0 + d1 * d1 + d2 * d2 + d3 * d3;
    __syncthreads();
    for (int o = 128; o > 0; o >>= 1) {
        if (tid < o) red[tid] += red[tid + o];
        __syncthreads();
    }
    float inv = rsqrtf(red[0] * (1.f / 1024.f) + 1e-5f);

    float4 gg = *(const float4*)(g + tid * 4);
    float4 bb = *(const float4*)(b + tid * 4);
    float y0 = d0 * inv * gg.x + bb.x;
    float y1 = d1 * inv * gg.y + bb.y;
    float y2 = d2 * inv * gg.z + bb.z;
    float y3 = d3 * inv * gg.w + bb.w;
    float4 yv = {y0, y1, y2, y3};
    *(float4*)(Y + (size_t)row * Mm + tid * 4) = yv;
    if (Yh) {
        float yy[4] = {y0, y1, y2, y3};
        size_t base = (size_t)row * Mm + tid * 4;
        #pragma unroll
        for (int c = 0; c < 4; c++) {
            bf16 h = __float2bfloat16(yy[c]);
            Yh[base + c] = h;
            Yl[base + c] = __float2bfloat16(yy[c] - __bfloat162float(h));
        }
    }
}

// ---------------- host ----------------
static void launch_gemm(const bf16* Ah, const bf16* Al, const bf16* Bh, const bf16* Bl,
                        const float* bias, const float* res,
                        float* Cf, bf16* Ch, bf16* Cl,
                        int I, int Kd, int J, int relu)
{
    dim3 grid(J / 128, I / 128);
    gemm_tc<<<grid, 256, GSM_SIZE>>>(Ah, Al, Bh, Bl, bias, res, Cf, Ch, Cl, Kd, J, relu);
}

extern "C" void kernel_launch(void* const* d_in, const int* in_sizes, int n_in,
                              void* d_out, int out_size)
{
    const float* dec  = (const float*)d_in[0];
    const float* enc  = (const float*)d_in[1];
    const int*   mask = (const int*)  d_in[2];
    const float* Wq_s = (const float*)d_in[3];  const float* bq_s = (const float*)d_in[4];
    const float* Wk_s = (const float*)d_in[5];  const float* bk_s = (const float*)d_in[6];
    const float* Wv_s = (const float*)d_in[7];  const float* bv_s = (const float*)d_in[8];
    const float* Wo_s = (const float*)d_in[9];  const float* bo_s = (const float*)d_in[10];
    const float* Wq_c = (const float*)d_in[11]; const float* bq_c = (const float*)d_in[12];
    const float* Wk_c = (const float*)d_in[13]; const float* bk_c = (const float*)d_in[14];
    const float* Wv_c = (const float*)d_in[15]; const float* bv_c = (const float*)d_in[16];
    const float* Wo_c = (const float*)d_in[17]; const float* bo_c = (const float*)d_in[18];
    const float* W1   = (const float*)d_in[19]; const float* b1   = (const float*)d_in[20];
    const float* W2   = (const float*)d_in[21]; const float* b2   = (const float*)d_in[22];
    const float* g1   = (const float*)d_in[23]; const float* be1  = (const float*)d_in[24];
    const float* g2   = (const float*)d_in[25]; const float* be2  = (const float*)d_in[26];
    const float* g3   = (const float*)d_in[27]; const float* be3  = (const float*)d_in[28];
    float* out = (float*)d_out;

    cudaFuncSetAttribute(attn_kernel, cudaFuncAttributeMaxDynamicSharedMemorySize, ATTN_SMEM);
    cudaFuncSetAttribute(gemm_tc, cudaFuncAttributeMaxDynamicSharedMemorySize, GSM_SIZE);

    float *q, *k, *v, *x, *y, *z;
    bf16 *dh, *dl, *eh, *el, *yh, *yl, *zh, *zl, *ah, *al, *hh, *hl, *wh, *wl;
    cudaGetSymbolAddress((void**)&q, g_q);   cudaGetSymbolAddress((void**)&k, g_k);
    cudaGetSymbolAddress((void**)&v, g_v);   cudaGetSymbolAddress((void**)&x, g_x);
    cudaGetSymbolAddress((void**)&y, g_y);   cudaGetSymbolAddress((void**)&z, g_z);
    cudaGetSymbolAddress((void**)&dh, g_dh); cudaGetSymbolAddress((void**)&dl, g_dl);
    cudaGetSymbolAddress((void**)&eh, g_eh); cudaGetSymbolAddress((void**)&el, g_el);
    cudaGetSymbolAddress((void**)&yh, g_yh); cudaGetSymbolAddress((void**)&yl, g_yl);
    cudaGetSymbolAddress((void**)&zh, g_zh); cudaGetSymbolAddress((void**)&zl, g_zl);
    cudaGetSymbolAddress((void**)&ah, g_ah); cudaGetSymbolAddress((void**)&al, g_al);
    cudaGetSymbolAddress((void**)&hh, g_hh); cudaGetSymbolAddress((void**)&hl, g_hl);
    cudaGetSymbolAddress((void**)&wh, g_wh); cudaGetSymbolAddress((void**)&wl, g_wl);

    // ---- input conversions ----
    conv_hl<<<NK * Mm / 1024, 256>>>(dec, dh, dl);
    conv_hl<<<NK * Mm / 1024, 256>>>(enc, eh, el);

    // ---- weight transposes (to K-major [J,K] bf16 hi/lo) ----
    dim3 tb(32, 8);
    dim3 tgq(Dd / 32, Mm / 32, Hh);
    trans_conv<<<tgq, tb>>>(Wq_s, wh + WOFF_QS, wl + WOFF_QS, Mm, Dd, (size_t)Mm * Dd, (size_t)Dd * Mm);
    trans_conv<<<tgq, tb>>>(Wk_s, wh + WOFF_KS, wl + WOFF_KS, Mm, Dd, (size_t)Mm * Dd, (size_t)Dd * Mm);
    trans_conv<<<tgq, tb>>>(Wv_s, wh + WOFF_VS, wl + WOFF_VS, Mm, Dd, (size_t)Mm * Dd, (size_t)Dd * Mm);
    trans_conv<<<tgq, tb>>>(Wq_c, wh + WOFF_QC, wl + WOFF_QC, Mm, Dd, (size_t)Mm * Dd, (size_t)Dd * Mm);
    trans_conv<<<tgq, tb>>>(Wk_c, wh + WOFF_KC, wl + WOFF_KC, Mm, Dd, (size_t)Mm * Dd, (size_t)Dd * Mm);
    trans_conv<<<tgq, tb>>>(Wv_c, wh + WOFF_VC, wl + WOFF_VC, Mm, Dd, (size_t)Mm * Dd, (size_t)Dd * Mm);
    dim3 tgo(Mm / 32, Mm / 32, 1);
    trans_conv<<<tgo, tb>>>(Wo_s, wh + WOFF_OS, wl + WOFF_OS, Mm, Mm, 0, 0);
    trans_conv<<<tgo, tb>>>(Wo_c, wh + WOFF_OC, wl + WOFF_OC, Mm, Mm, 0, 0);
    dim3 tg1(Ff / 32, Mm / 32, 1);
    trans_conv<<<tg1, tb>>>(W1, wh + WOFF_W1, wl + WOFF_W1, Mm, Ff, 0, 0);
    dim3 tg2(Mm / 32, Ff / 32, 1);
    trans_conv<<<tg2, tb>>>(W2, wh + WOFF_W2, wl + WOFF_W2, Ff, Mm, 0, 0);

    dim3 agrid(Kk / 64, Nn * Hh);

    // ---- self attention ----
    launch_gemm(dh, dl, wh + WOFF_QS, wl + WOFF_QS, bq_s, nullptr, q, nullptr, nullptr, NK, Mm, Mm, 0);
    launch_gemm(dh, dl, wh + WOFF_KS, wl + WOFF_KS, bk_s, nullptr, k, nullptr, nullptr, NK, Mm, Mm, 0);
    launch_gemm(dh, dl, wh + WOFF_VS, wl + WOFF_VS, bv_s, nullptr, v, nullptr, nullptr, NK, Mm, Mm, 0);
    attn_kernel<<<agrid, 256, ATTN_SMEM>>>(q, k, v, mask, ah, al);
    launch_gemm(ah, al, wh + WOFF_OS, wl + WOFF_OS, bo_s, dec, x, nullptr, nullptr, NK, Mm, Mm, 0);
    ln_kernel<<<NK, 256>>>(x, g1, be1, y, yh, yl);   // out2 -> y (+hi/lo)

    // ---- cross attention ----
    launch_gemm(yh, yl, wh + WOFF_QC, wl + WOFF_QC, bq_c, nullptr, q, nullptr, nullptr, NK, Mm, Mm, 0);
    launch_gemm(eh, el, wh + WOFF_KC, wl + WOFF_KC, bk_c, nullptr, k, nullptr, nullptr, NK, Mm, Mm, 0);
    launch_gemm(eh, el, wh + WOFF_VC, wl + WOFF_VC, bv_c, nullptr, v, nullptr, nullptr, NK, Mm, Mm, 0);
    attn_kernel<<<agrid, 256, ATTN_SMEM>>>(q, k, v, nullptr, ah, al);
    launch_gemm(ah, al, wh + WOFF_OC, wl + WOFF_OC, bo_c, y, x, nullptr, nullptr, NK, Mm, Mm, 0);
    ln_kernel<<<NK, 256>>>(x, g2, be2, z, zh, zl);   // out4 -> z (+hi/lo)

    // ---- feedforward ----
    launch_gemm(zh, zl, wh + WOFF_W1, wl + WOFF_W1, b1, nullptr, nullptr, hh, hl, NK, Mm, Ff, 1);
    launch_gemm(hh, hl, wh + WOFF_W2, wl + WOFF_W2, b2, z, x, nullptr, nullptr, NK, Ff, Mm, 0);
    ln_kernel<<<NK, 256>>>(x, g3, be3, out, nullptr, nullptr);
}

// round 8
// speedup vs baseline: 2.3333x; 1.3303x over previous
#include <cuda_runtime.h>
#include <cuda_bf16.h>
#include <stdint.h>
#include <math.h>

#define Nn 4
#define Kk 1024
#define Mm 1024
#define Hh 16
#define Dd 64
#define Ff 4096
#define NK 4096   // Nn*Kk

typedef __nv_bfloat16 bf16;

// ---------------- scratch (no allocations allowed) ----------------
__device__ float g_x[NK * Mm];
__device__ float g_y[NK * Mm];
__device__ float g_z[NK * Mm];

__device__ __align__(256) bf16 g_dh[NK * Mm], g_dl[NK * Mm];   // dec hi/lo
__device__ __align__(256) bf16 g_eh[NK * Mm], g_el[NK * Mm];   // enc hi/lo
__device__ __align__(256) bf16 g_yh[NK * Mm], g_yl[NK * Mm];   // ln1 out hi/lo
__device__ __align__(256) bf16 g_zh[NK * Mm], g_zl[NK * Mm];   // ln2 out hi/lo
__device__ __align__(256) bf16 g_ah[NK * Mm], g_al[NK * Mm];   // attn out hi/lo
__device__ __align__(256) bf16 g_hh[NK * Ff], g_hl[NK * Ff];   // ffn hidden hi/lo
__device__ __align__(256) bf16 g_qh[NK * Mm], g_ql[NK * Mm];   // q hi/lo
__device__ __align__(256) bf16 g_kh[NK * Mm], g_kl[NK * Mm];   // k hi/lo
__device__ __align__(256) bf16 g_vh[NK * Mm], g_vl[NK * Mm];   // v hi/lo
__device__ __align__(256) bf16 g_wh[16 * 1024 * 1024];         // transposed weights hi
__device__ __align__(256) bf16 g_wl[16 * 1024 * 1024];         // transposed weights lo

// weight offsets (elements) in g_wh/g_wl
#define WOFF_QS (0 * 1048576)
#define WOFF_KS (1 * 1048576)
#define WOFF_VS (2 * 1048576)
#define WOFF_QC (3 * 1048576)
#define WOFF_KC (4 * 1048576)
#define WOFF_VC (5 * 1048576)
#define WOFF_OS (6 * 1048576)
#define WOFF_OC (7 * 1048576)
#define WOFF_W1 (8 * 1048576)
#define WOFF_W2 (12 * 1048576)

// ---------------- PTX helpers (family-safe: mma.sync / ldmatrix / cp.async) ----------------
__device__ __forceinline__ uint32_t smem_u32(const void* p) {
    uint32_t a;
    asm("{ .reg .u64 t; cvta.to.shared.u64 t, %1; cvt.u32.u64 %0, t; }" : "=r"(a) : "l"(p));
    return a;
}

__device__ __forceinline__ void cp16(uint32_t s, const void* g) {
    asm volatile("cp.async.cg.shared.global [%0], [%1], 16;" :: "r"(s), "l"(g));
}

__device__ __forceinline__ void ldm4(uint32_t* r, uint32_t addr) {
    asm volatile("ldmatrix.sync.aligned.m8n8.x4.shared.b16 {%0,%1,%2,%3}, [%4];"
                 : "=r"(r[0]), "=r"(r[1]), "=r"(r[2]), "=r"(r[3]) : "r"(addr));
}

__device__ __forceinline__ void ldm4t(uint32_t* r, uint32_t addr) {
    asm volatile("ldmatrix.sync.aligned.m8n8.x4.trans.shared.b16 {%0,%1,%2,%3}, [%4];"
                 : "=r"(r[0]), "=r"(r[1]), "=r"(r[2]), "=r"(r[3]) : "r"(addr));
}

__device__ __forceinline__ void mma16816(float* c, const uint32_t* a, const uint32_t* b) {
    asm volatile(
        "mma.sync.aligned.m16n8k16.row.col.f32.bf16.bf16.f32 "
        "{%0,%1,%2,%3}, {%4,%5,%6,%7}, {%8,%9}, {%0,%1,%2,%3};"
        : "+f"(c[0]), "+f"(c[1]), "+f"(c[2]), "+f"(c[3])
        : "r"(a[0]), "r"(a[1]), "r"(a[2]), "r"(a[3]), "r"(b[0]), "r"(b[1]));
}

// pack two f32 -> bf16x2: low half = lo, high half = hi
__device__ __forceinline__ uint32_t packbf(float lo, float hi) {
    uint32_t r;
    asm("cvt.rn.bf16x2.f32 %0, %1, %2;" : "=r"(r) : "f"(hi), "f"(lo));
    return r;
}

// ---------------- tensor-core GEMM: C[I,J] = (Ah+Al)[I,Kd] @ (Bh+Bl)^T ----------------
#define ROWB 80                 // smem row stride bytes (32 bf16 = 64B data + 16B pad)
#define OPBYTES (128 * ROWB)    // 10240 per operand tile
#define STAGEB (4 * OPBYTES)    // 40960 per stage (Ah, Al, Bh, Bl)
#define GSM_SIZE (2 * STAGEB)   // 81920

__global__ __launch_bounds__(256) void gemm_tc(
    const bf16* __restrict__ Ah, const bf16* __restrict__ Al,
    const bf16* __restrict__ Bh, const bf16* __restrict__ Bl,
    const float* __restrict__ bias, const float* __restrict__ res,
    float* __restrict__ Cf, bf16* __restrict__ Ch, bf16* __restrict__ Cl,
    int Kd, int J, int relu)
{
    extern __shared__ char smem[];
    uint32_t sb = smem_u32(smem);
    int tid = threadIdx.x;
    int wid = tid >> 5, lane = tid & 31;
    int wm = wid >> 2, wn = wid & 3;            // warp grid 2 (M) x 4 (N)
    int i0 = blockIdx.y << 7, j0 = blockIdx.x << 7;

    size_t rowBytes = (size_t)Kd * 2;
    const char* gp[4] = {
        (const char*)(Ah + (size_t)i0 * Kd),
        (const char*)(Al + (size_t)i0 * Kd),
        (const char*)(Bh + (size_t)j0 * Kd),
        (const char*)(Bl + (size_t)j0 * Kd)
    };

    int r0c = tid >> 2, c0c = tid & 3;
    int r1c = (tid + 256) >> 2, c1c = tid & 3;

    auto load_stage = [&](int s, int k0) {
        uint32_t base = sb + (s & 1) * STAGEB;
        size_t gk = (size_t)k0 * 2;
        #pragma unroll
        for (int op = 0; op < 4; op++) {
            cp16(base + op * OPBYTES + r0c * ROWB + c0c * 16,
                 gp[op] + (size_t)r0c * rowBytes + gk + c0c * 16);
            cp16(base + op * OPBYTES + r1c * ROWB + c1c * 16,
                 gp[op] + (size_t)r1c * rowBytes + gk + c1c * 16);
        }
        asm volatile("cp.async.commit_group;" ::: "memory");
    };

    float acc[4][4][4] = {};

    int aRow = wm * 64 + (lane & 7) + ((lane >> 3) & 1) * 8;
    int aByte = ((lane >> 4) & 1) * 16;
    int bRow = wn * 32 + (lane & 7) + ((lane >> 4) & 1) * 8;
    int bByte = ((lane >> 3) & 1) * 16;

    int S = Kd >> 5;
    load_stage(0, 0);

    for (int s = 0; s < S; s++) {
        if (s + 1 < S) {
            load_stage(s + 1, (s + 1) << 5);
            asm volatile("cp.async.wait_group 1;" ::: "memory");
        } else {
            asm volatile("cp.async.wait_group 0;" ::: "memory");
        }
        __syncthreads();

        uint32_t aB  = sb + (s & 1) * STAGEB;
        uint32_t alB = aB + OPBYTES;
        uint32_t bB  = aB + 2 * OPBYTES;
        uint32_t blB = aB + 3 * OPBYTES;

        #pragma unroll
        for (int ks = 0; ks < 2; ks++) {
            uint32_t ah[4][4], al_[4][4];
            #pragma unroll
            for (int fm = 0; fm < 4; fm++) {
                uint32_t off = (uint32_t)(aRow + fm * 16) * ROWB + ks * 32 + aByte;
                ldm4(ah[fm],  aB  + off);
                ldm4(al_[fm], alB + off);
            }
            uint32_t bh[4][2], bl[4][2];
            #pragma unroll
            for (int p = 0; p < 2; p++) {
                uint32_t off = (uint32_t)(bRow + p * 16) * ROWB + ks * 32 + bByte;
                uint32_t t[4];
                ldm4(t, bB + off);
                bh[2 * p][0] = t[0]; bh[2 * p][1] = t[1];
                bh[2 * p + 1][0] = t[2]; bh[2 * p + 1][1] = t[3];
                ldm4(t, blB + off);
                bl[2 * p][0] = t[0]; bl[2 * p][1] = t[1];
                bl[2 * p + 1][0] = t[2]; bl[2 * p + 1][1] = t[3];
            }
            #pragma unroll
            for (int fm = 0; fm < 4; fm++)
                #pragma unroll
                for (int fn = 0; fn < 4; fn++) {
                    mma16816(acc[fm][fn], ah[fm],  bh[fn]);
                    mma16816(acc[fm][fn], ah[fm],  bl[fn]);
                    mma16816(acc[fm][fn], al_[fm], bh[fn]);
                }
        }
        __syncthreads();
    }

    bool hb = bias != nullptr, hr = res != nullptr, hf = Cf != nullptr, hh = Ch != nullptr;
    int g = lane >> 2, q = lane & 3;
    #pragma unroll
    for (int fm = 0; fm < 4; fm++) {
        #pragma unroll
        for (int fn = 0; fn < 4; fn++) {
            int col = j0 + wn * 32 + fn * 8 + q * 2;
            #pragma unroll
            for (int half = 0; half < 2; half++) {
                int row = i0 + wm * 64 + fm * 16 + g + half * 8;
                size_t base = (size_t)row * J + col;
                #pragma unroll
                for (int e = 0; e < 2; e++) {
                    float v = acc[fm][fn][half * 2 + e];
                    if (hb) v += bias[col + e];
                    if (hr) v += res[base + e];
                    if (relu) v = fmaxf(v, 0.f);
                    if (hf) Cf[base + e] = v;
                    if (hh) {
                        bf16 h = __float2bfloat16(v);
                        Ch[base + e] = h;
                        Cl[base + e] = __float2bfloat16(v - __bfloat162float(h));
                    }
                }
            }
        }
    }
}

// ---------------- tensor-core flash attention ----------------
// Q/K/V: [NK, M] bf16 hi/lo, head slice at col h*64 (d contiguous).
// Block: 256 thr (8 warps, 16 q-rows each), 128 q-rows/CTA, 64-key tiles.
#define AROWB 144                        // 64 d * 2B = 128B + 16B pad (conflict-free ldmatrix)
#define AQ_BYTES (128 * AROWB)           // 18432
#define AKV_BYTES (64 * AROWB)           // 9216
#define ASTAGE (4 * AKV_BYTES)           // 36864: Kh,Kl,Vh,Vl
#define ATTN_SMEM2 (2 * AQ_BYTES + 2 * ASTAGE)   // 110592

__global__ __launch_bounds__(256) void attn_tc(
    const bf16* __restrict__ Qh, const bf16* __restrict__ Ql,
    const bf16* __restrict__ Kph, const bf16* __restrict__ Kpl,
    const bf16* __restrict__ Vph, const bf16* __restrict__ Vpl,
    int causal, bf16* __restrict__ Oh, bf16* __restrict__ Ol)
{
    extern __shared__ char smem[];
    uint32_t sb = smem_u32(smem);
    int tid = threadIdx.x, lane = tid & 31, wm = tid >> 5;
    int g = lane >> 2, qd = lane & 3;
    int nh = blockIdx.y;
    int n = nh >> 4, h = nh & 15;
    int q0 = blockIdx.x << 7;

    uint32_t sQ = sb;
    uint32_t sKV0 = sb + 2 * AQ_BYTES;

    const char* qptr[2] = {(const char*)Qh, (const char*)Ql};
    const char* kvptr[4] = {(const char*)Kph, (const char*)Kpl,
                            (const char*)Vph, (const char*)Vpl};
    size_t rowOff0 = ((size_t)n * Kk) * Mm + (size_t)h * Dd;  // elements

    // ---- load Q tile (2 arrays x 128 rows x 8 chunks) ----
    #pragma unroll
    for (int c = 0; c < 8; c++) {
        int idx = c * 256 + tid;
        int arr = idx >> 10, rem = idx & 1023, row = rem >> 3, col = rem & 7;
        cp16(sQ + arr * AQ_BYTES + row * AROWB + col * 16,
             qptr[arr] + (rowOff0 + (size_t)(q0 + row) * Mm) * 2 + col * 16);
    }

    auto load_kv = [&](int s, int l0) {
        uint32_t base = sKV0 + (s & 1) * ASTAGE;
        #pragma unroll
        for (int c = 0; c < 8; c++) {
            int idx = c * 256 + tid;
            int arr = idx >> 9, rem = idx & 511, row = rem >> 3, col = rem & 7;
            cp16(base + arr * AKV_BYTES + row * AROWB + col * 16,
                 kvptr[arr] + (rowOff0 + (size_t)(l0 + row) * Mm) * 2 + col * 16);
        }
        asm volatile("cp.async.commit_group;" ::: "memory");
    };
    load_kv(0, 0);   // Q chunks ride in group 0 too

    int nt = causal ? ((q0 + 128) >> 6) : (Kk >> 6);

    int aRow = (lane & 7) + ((lane >> 3) & 1) * 8;
    int aByte = ((lane >> 4) & 1) * 16;
    int bRow = (lane & 7) + ((lane >> 4) & 1) * 8;
    int bByte = ((lane >> 3) & 1) * 16;
    int vRow = lane & 15;
    int vByte = ((lane >> 4) & 1) * 16;

    uint32_t qf[2][4][4];     // [hi/lo][kc][reg]
    float Oacc[8][4] = {};
    float mrow[2] = {-1e30f, -1e30f};
    float lrow[2] = {0.f, 0.f};
    const float scale = 0.125f;   // 1/sqrt(64)

    for (int t = 0; t < nt; t++) {
        if (t + 1 < nt) {
            load_kv(t + 1, (t + 1) << 6);
            asm volatile("cp.async.wait_group 1;" ::: "memory");
        } else {
            asm volatile("cp.async.wait_group 0;" ::: "memory");
        }
        __syncthreads();

        if (t == 0) {
            #pragma unroll
            for (int hl = 0; hl < 2; hl++)
                #pragma unroll
                for (int kc = 0; kc < 4; kc++)
                    ldm4(qf[hl][kc], sQ + hl * AQ_BYTES +
                         (uint32_t)(wm * 16 + aRow) * AROWB + kc * 32 + aByte);
        }

        uint32_t kb = sKV0 + (t & 1) * ASTAGE;
        int l0 = t << 6;

        // ---- S = Q K^T (3-term hi/lo) ----
        float S[8][4] = {};
        #pragma unroll
        for (int kc = 0; kc < 4; kc++) {
            #pragma unroll
            for (int p = 0; p < 4; p++) {
                uint32_t off = (uint32_t)(p * 16 + bRow) * AROWB + kc * 32 + bByte;
                uint32_t th[4], tl[4];
                ldm4(th, kb + off);
                ldm4(tl, kb + AKV_BYTES + off);
                mma16816(S[2 * p],     qf[0][kc], th);
                mma16816(S[2 * p + 1], qf[0][kc], th + 2);
                mma16816(S[2 * p],     qf[0][kc], tl);
                mma16816(S[2 * p + 1], qf[0][kc], tl + 2);
                mma16816(S[2 * p],     qf[1][kc], th);
                mma16816(S[2 * p + 1], qf[1][kc], th + 2);
            }
        }

        // ---- scale + causal mask ----
        int qr0 = q0 + wm * 16 + g;
        bool needMask = causal && (l0 + 63 > q0 + wm * 16);
        #pragma unroll
        for (int j = 0; j < 8; j++) {
            int lg = l0 + j * 8 + 2 * qd;
            #pragma unroll
            for (int c = 0; c < 4; c++) {
                float v = S[j][c] * scale;
                if (needMask) {
                    int lq = lg + (c & 1);
                    int qq = qr0 + (c >> 1) * 8;
                    if (lq > qq) v = -1e30f;
                }
                S[j][c] = v;
            }
        }

        // ---- online softmax (register-resident) ----
        float alpha[2];
        #pragma unroll
        for (int hf = 0; hf < 2; hf++) {
            float tm = -1e30f;
            #pragma unroll
            for (int j = 0; j < 8; j++) {
                tm = fmaxf(tm, S[j][2 * hf]);
                tm = fmaxf(tm, S[j][2 * hf + 1]);
            }
            tm = fmaxf(tm, __shfl_xor_sync(0xffffffffu, tm, 1));
            tm = fmaxf(tm, __shfl_xor_sync(0xffffffffu, tm, 2));
            float mnew = fmaxf(mrow[hf], tm);
            alpha[hf] = __expf(mrow[hf] - mnew);
            mrow[hf] = mnew;
            float rs = 0.f;
            #pragma unroll
            for (int j = 0; j < 8; j++) {
                float e0 = __expf(S[j][2 * hf] - mnew);
                float e1 = __expf(S[j][2 * hf + 1] - mnew);
                S[j][2 * hf] = e0; S[j][2 * hf + 1] = e1;
                rs += e0 + e1;
            }
            rs += __shfl_xor_sync(0xffffffffu, rs, 1);
            rs += __shfl_xor_sync(0xffffffffu, rs, 2);
            lrow[hf] = lrow[hf] * alpha[hf] + rs;
        }
        #pragma unroll
        for (int j = 0; j < 8; j++) {
            Oacc[j][0] *= alpha[0]; Oacc[j][1] *= alpha[0];
            Oacc[j][2] *= alpha[1]; Oacc[j][3] *= alpha[1];
        }

        // ---- O += P V (P hi/lo, V hi/lo via ldmatrix.trans) ----
        uint32_t vb = kb + 2 * AKV_BYTES;
        #pragma unroll
        for (int kc = 0; kc < 4; kc++) {
            uint32_t ph[4], pl[4];
            #pragma unroll
            for (int r = 0; r < 2; r++) {
                int j = 2 * kc + r;
                uint32_t h0 = packbf(S[j][0], S[j][1]);
                float f0 = __uint_as_float(h0 << 16);
                float f1 = __uint_as_float(h0 & 0xffff0000u);
                uint32_t l0r = packbf(S[j][0] - f0, S[j][1] - f1);
                uint32_t h1 = packbf(S[j][2], S[j][3]);
                float f2 = __uint_as_float(h1 << 16);
                float f3 = __uint_as_float(h1 & 0xffff0000u);
                uint32_t l1r = packbf(S[j][2] - f2, S[j][3] - f3);
                ph[2 * r] = h0; ph[2 * r + 1] = h1;
                pl[2 * r] = l0r; pl[2 * r + 1] = l1r;
            }
            #pragma unroll
            for (int p = 0; p < 4; p++) {
                uint32_t off = (uint32_t)(kc * 16 + vRow) * AROWB + p * 32 + vByte;
                uint32_t tvh[4], tvl[4];
                ldm4t(tvh, vb + off);
                ldm4t(tvl, vb + AKV_BYTES + off);
                mma16816(Oacc[2 * p],     ph, tvh);
                mma16816(Oacc[2 * p + 1], ph, tvh + 2);
                mma16816(Oacc[2 * p],     ph, tvl);
                mma16816(Oacc[2 * p + 1], ph, tvl + 2);
                mma16816(Oacc[2 * p],     pl, tvh);
                mma16816(Oacc[2 * p + 1], pl, tvh + 2);
            }
        }
        __syncthreads();
    }

    // ---- epilogue: normalize, emit hi/lo bf16 ----
    float inv0 = 1.f / lrow[0], inv1 = 1.f / lrow[1];
    #pragma unroll
    for (int j = 0; j < 8; j++) {
        int d = j * 8 + 2 * qd;
        size_t base0 = ((size_t)n * Kk + q0 + wm * 16 + g) * Mm + (size_t)h * Dd + d;
        size_t base1 = base0 + (size_t)8 * Mm;
        float v0 = Oacc[j][0] * inv0, v1 = Oacc[j][1] * inv0;
        float v2 = Oacc[j][2] * inv1, v3 = Oacc[j][3] * inv1;
        uint32_t h0 = packbf(v0, v1);
        *(uint32_t*)(Oh + base0) = h0;
        float f0 = __uint_as_float(h0 << 16), f1 = __uint_as_float(h0 & 0xffff0000u);
        *(uint32_t*)(Ol + base0) = packbf(v0 - f0, v1 - f1);
        uint32_t h1 = packbf(v2, v3);
        *(uint32_t*)(Oh + base1) = h1;
        float f2 = __uint_as_float(h1 << 16), f3 = __uint_as_float(h1 & 0xffff0000u);
        *(uint32_t*)(Ol + base1) = packbf(v2 - f2, v3 - f3);
    }
}

// ---------------- transpose + hi/lo convert: out[c][r] = in[r][c] ----------------
__global__ void trans_conv(const float* __restrict__ in, bf16* __restrict__ oh,
                           bf16* __restrict__ ol, int R, int C,
                           size_t inStrideZ, size_t outStrideZ)
{
    __shared__ float t[32][33];
    int c0 = blockIdx.x * 32, r0 = blockIdx.y * 32;
    const float* ip = in + (size_t)blockIdx.z * inStrideZ;
    int tx = threadIdx.x, ty = threadIdx.y;
    #pragma unroll
    for (int i = 0; i < 4; i++)
        t[ty + i * 8][tx] = ip[(size_t)(r0 + ty + i * 8) * C + c0 + tx];
    __syncthreads();
    size_t ob = (size_t)blockIdx.z * outStrideZ;
    #pragma unroll
    for (int i = 0; i < 4; i++) {
        float v = t[tx][ty + i * 8];
        size_t o = ob + (size_t)(c0 + ty + i * 8) * R + r0 + tx;
        bf16 h = __float2bfloat16(v);
        oh[o] = h;
        ol[o] = __float2bfloat16(v - __bfloat162float(h));
    }
}

// ---------------- elementwise fp32 -> bf16 hi/lo ----------------
__global__ void conv_hl(const float* __restrict__ in, bf16* __restrict__ oh,
                        bf16* __restrict__ ol)
{
    int i = (blockIdx.x * 256 + threadIdx.x) * 4;
    float4 v = *(const float4*)(in + i);
    float vv[4] = {v.x, v.y, v.z, v.w};
    #pragma unroll
    for (int c = 0; c < 4; c++) {
        bf16 h = __float2bfloat16(vv[c]);
        oh[i + c] = h;
        ol[i + c] = __float2bfloat16(vv[c] - __bfloat162float(h));
    }
}

// ---------------- LayerNorm (block per row, M=1024), optional hi/lo out ----------------
__global__ void ln_kernel(const float* __restrict__ X, const float* __restrict__ g,
                          const float* __restrict__ b, float* __restrict__ Y,
                          bf16* __restrict__ Yh, bf16* __restrict__ Yl)
{
    int row = blockIdx.x;
    int tid = threadIdx.x;
    const float* x = X + (size_t)row * Mm;
    float4 v = *(const float4*)(x + tid * 4);

    __shared__ float red[256];
    red[tid] = v.x + v.y + v.z + v.w;
    __syncthreads();
    for (int o = 128; o > 0; o >>= 1) {
        if (tid < o) red[tid] += red[tid + o];
        __syncthreads();
    }
    float mu = red[0] * (1.f / 1024.f);
    __syncthreads();

    float d0 = v.x - mu, d1 = v.y - mu, d2 = v.z - mu, d3 = v.w - mu;
    red[tid] = d0 * d0 + d1 * d1 + d2 * d2 + d3 * d3;
    __syncthreads();
    for (int o = 128; o > 0; o >>= 1) {
        if (tid < o) red[tid] += red[tid + o];
        __syncthreads();
    }
    float inv = rsqrtf(red[0] * (1.f / 1024.f) + 1e-5f);

    float4 gg = *(const float4*)(g + tid * 4);
    float4 bb = *(const float4*)(b + tid * 4);
    float y0 = d0 * inv * gg.x + bb.x;
    float y1 = d1 * inv * gg.y + bb.y;
    float y2 = d2 * inv * gg.z + bb.z;
    float y3 = d3 * inv * gg.w + bb.w;
    float4 yv = {y0, y1, y2, y3};
    *(float4*)(Y + (size_t)row * Mm + tid * 4) = yv;
    if (Yh) {
        float yy[4] = {y0, y1, y2, y3};
        size_t base = (size_t)row * Mm + tid * 4;
        #pragma unroll
        for (int c = 0; c < 4; c++) {
            bf16 h = __float2bfloat16(yy[c]);
            Yh[base + c] = h;
            Yl[base + c] = __float2bfloat16(yy[c] - __bfloat162float(h));
        }
    }
}

// ---------------- host ----------------
static void launch_gemm(const bf16* Ah, const bf16* Al, const bf16* Bh, const bf16* Bl,
                        const float* bias, const float* res,
                        float* Cf, bf16* Ch, bf16* Cl,
                        int I, int Kd, int J, int relu)
{
    dim3 grid(J / 128, I / 128);
    gemm_tc<<<grid, 256, GSM_SIZE>>>(Ah, Al, Bh, Bl, bias, res, Cf, Ch, Cl, Kd, J, relu);
}

extern "C" void kernel_launch(void* const* d_in, const int* in_sizes, int n_in,
                              void* d_out, int out_size)
{
    const float* dec  = (const float*)d_in[0];
    const float* enc  = (const float*)d_in[1];
    const float* Wq_s = (const float*)d_in[3];  const float* bq_s = (const float*)d_in[4];
    const float* Wk_s = (const float*)d_in[5];  const float* bk_s = (const float*)d_in[6];
    const float* Wv_s = (const float*)d_in[7];  const float* bv_s = (const float*)d_in[8];
    const float* Wo_s = (const float*)d_in[9];  const float* bo_s = (const float*)d_in[10];
    const float* Wq_c = (const float*)d_in[11]; const float* bq_c = (const float*)d_in[12];
    const float* Wk_c = (const float*)d_in[13]; const float* bk_c = (const float*)d_in[14];
    const float* Wv_c = (const float*)d_in[15]; const float* bv_c = (const float*)d_in[16];
    const float* Wo_c = (const float*)d_in[17]; const float* bo_c = (const float*)d_in[18];
    const float* W1   = (const float*)d_in[19]; const float* b1   = (const float*)d_in[20];
    const float* W2   = (const float*)d_in[21]; const float* b2   = (const float*)d_in[22];
    const float* g1   = (const float*)d_in[23]; const float* be1  = (const float*)d_in[24];
    const float* g2   = (const float*)d_in[25]; const float* be2  = (const float*)d_in[26];
    const float* g3   = (const float*)d_in[27]; const float* be3  = (const float*)d_in[28];
    float* out = (float*)d_out;

    cudaFuncSetAttribute(gemm_tc, cudaFuncAttributeMaxDynamicSharedMemorySize, GSM_SIZE);
    cudaFuncSetAttribute(attn_tc, cudaFuncAttributeMaxDynamicSharedMemorySize, ATTN_SMEM2);

    float *x, *y, *z;
    bf16 *dh, *dl, *eh, *el, *yh, *yl, *zh, *zl, *ah, *al, *hh, *hl, *wh, *wl;
    bf16 *qh, *ql, *kh, *kl, *vh, *vl;
    cudaGetSymbolAddress((void**)&x, g_x);
    cudaGetSymbolAddress((void**)&y, g_y);   cudaGetSymbolAddress((void**)&z, g_z);
    cudaGetSymbolAddress((void**)&dh, g_dh); cudaGetSymbolAddress((void**)&dl, g_dl);
    cudaGetSymbolAddress((void**)&eh, g_eh); cudaGetSymbolAddress((void**)&el, g_el);
    cudaGetSymbolAddress((void**)&yh, g_yh); cudaGetSymbolAddress((void**)&yl, g_yl);
    cudaGetSymbolAddress((void**)&zh, g_zh); cudaGetSymbolAddress((void**)&zl, g_zl);
    cudaGetSymbolAddress((void**)&ah, g_ah); cudaGetSymbolAddress((void**)&al, g_al);
    cudaGetSymbolAddress((void**)&hh, g_hh); cudaGetSymbolAddress((void**)&hl, g_hl);
    cudaGetSymbolAddress((void**)&wh, g_wh); cudaGetSymbolAddress((void**)&wl, g_wl);
    cudaGetSymbolAddress((void**)&qh, g_qh); cudaGetSymbolAddress((void**)&ql, g_ql);
    cudaGetSymbolAddress((void**)&kh, g_kh); cudaGetSymbolAddress((void**)&kl, g_kl);
    cudaGetSymbolAddress((void**)&vh, g_vh); cudaGetSymbolAddress((void**)&vl, g_vl);

    // ---- input conversions ----
    conv_hl<<<NK * Mm / 1024, 256>>>(dec, dh, dl);
    conv_hl<<<NK * Mm / 1024, 256>>>(enc, eh, el);

    // ---- weight transposes (to K-major [J,K] bf16 hi/lo) ----
    dim3 tb(32, 8);
    dim3 tgq(Dd / 32, Mm / 32, Hh);
    trans_conv<<<tgq, tb>>>(Wq_s, wh + WOFF_QS, wl + WOFF_QS, Mm, Dd, (size_t)Mm * Dd, (size_t)Dd * Mm);
    trans_conv<<<tgq, tb>>>(Wk_s, wh + WOFF_KS, wl + WOFF_KS, Mm, Dd, (size_t)Mm * Dd, (size_t)Dd * Mm);
    trans_conv<<<tgq, tb>>>(Wv_s, wh + WOFF_VS, wl + WOFF_VS, Mm, Dd, (size_t)Mm * Dd, (size_t)Dd * Mm);
    trans_conv<<<tgq, tb>>>(Wq_c, wh + WOFF_QC, wl + WOFF_QC, Mm, Dd, (size_t)Mm * Dd, (size_t)Dd * Mm);
    trans_conv<<<tgq, tb>>>(Wk_c, wh + WOFF_KC, wl + WOFF_KC, Mm, Dd, (size_t)Mm * Dd, (size_t)Dd * Mm);
    trans_conv<<<tgq, tb>>>(Wv_c, wh + WOFF_VC, wl + WOFF_VC, Mm, Dd, (size_t)Mm * Dd, (size_t)Dd * Mm);
    dim3 tgo(Mm / 32, Mm / 32, 1);
    trans_conv<<<tgo, tb>>>(Wo_s, wh + WOFF_OS, wl + WOFF_OS, Mm, Mm, 0, 0);
    trans_conv<<<tgo, tb>>>(Wo_c, wh + WOFF_OC, wl + WOFF_OC, Mm, Mm, 0, 0);
    dim3 tg1(Ff / 32, Mm / 32, 1);
    trans_conv<<<tg1, tb>>>(W1, wh + WOFF_W1, wl + WOFF_W1, Mm, Ff, 0, 0);
    dim3 tg2(Mm / 32, Ff / 32, 1);
    trans_conv<<<tg2, tb>>>(W2, wh + WOFF_W2, wl + WOFF_W2, Ff, Mm, 0, 0);

    dim3 agrid(Kk / 128, Nn * Hh);

    // ---- self attention ----
    launch_gemm(dh, dl, wh + WOFF_QS, wl + WOFF_QS, bq_s, nullptr, nullptr, qh, ql, NK, Mm, Mm, 0);
    launch_gemm(dh, dl, wh + WOFF_KS, wl + WOFF_KS, bk_s, nullptr, nullptr, kh, kl, NK, Mm, Mm, 0);
    launch_gemm(dh, dl, wh + WOFF_VS, wl + WOFF_VS, bv_s, nullptr, nullptr, vh, vl, NK, Mm, Mm, 0);
    attn_tc<<<agrid, 256, ATTN_SMEM2>>>(qh, ql, kh, kl, vh, vl, 1, ah, al);
    launch_gemm(ah, al, wh + WOFF_OS, wl + WOFF_OS, bo_s, dec, x, nullptr, nullptr, NK, Mm, Mm, 0);
    ln_kernel<<<NK, 256>>>(x, g1, be1, y, yh, yl);   // out2 -> y (+hi/lo)

    // ---- cross attention ----
    launch_gemm(yh, yl, wh + WOFF_QC, wl + WOFF_QC, bq_c, nullptr, nullptr, qh, ql, NK, Mm, Mm, 0);
    launch_gemm(eh, el, wh + WOFF_KC, wl + WOFF_KC, bk_c, nullptr, nullptr, kh, kl, NK, Mm, Mm, 0);
    launch_gemm(eh, el, wh + WOFF_VC, wl + WOFF_VC, bv_c, nullptr, nullptr, vh, vl, NK, Mm, Mm, 0);
    attn_tc<<<agrid, 256, ATTN_SMEM2>>>(qh, ql, kh, kl, vh, vl, 0, ah, al);
    launch_gemm(ah, al, wh + WOFF_OC, wl + WOFF_OC, bo_c, y, x, nullptr, nullptr, NK, Mm, Mm, 0);
    ln_kernel<<<NK, 256>>>(x, g2, be2, z, zh, zl);   // out4 -> z (+hi/lo)

    // ---- feedforward ----
    launch_gemm(zh, zl, wh + WOFF_W1, wl + WOFF_W1, b1, nullptr, nullptr, hh, hl, NK, Mm, Ff, 1);
    launch_gemm(hh, hl, wh + WOFF_W2, wl + WOFF_W2, b2, z, x, nullptr, nullptr, NK, Ff, Mm, 0);
    ln_kernel<<<NK, 256>>>(x, g3, be3, out, nullptr, nullptr);
}

// round 9
// speedup vs baseline: 2.5085x; 1.0750x over previous
#include <cuda_runtime.h>
#include <cuda_bf16.h>
#include <stdint.h>
#include <math.h>

#define Nn 4
#define Kk 1024
#define Mm 1024
#define Hh 16
#define Dd 64
#define Ff 4096
#define NK 4096   // Nn*Kk

typedef __nv_bfloat16 bf16;

// ---------------- scratch (no allocations allowed) ----------------
__device__ float g_x[NK * Mm];
__device__ float g_y[NK * Mm];
__device__ float g_z[NK * Mm];
__device__ float g_b3[3 * Mm];
__device__ float g_b2[2 * Mm];

__device__ __align__(256) bf16 g_dh[NK * Mm], g_dl[NK * Mm];       // dec hi/lo
__device__ __align__(256) bf16 g_eh[NK * Mm], g_el[NK * Mm];       // enc hi/lo
__device__ __align__(256) bf16 g_yh[NK * Mm], g_yl[NK * Mm];       // ln1 out hi/lo
__device__ __align__(256) bf16 g_zh[NK * Mm], g_zl[NK * Mm];       // ln2 out hi/lo
__device__ __align__(256) bf16 g_ah[NK * Mm], g_al[NK * Mm];       // attn out hi/lo
__device__ __align__(256) bf16 g_hh[NK * Ff], g_hl[NK * Ff];       // ffn hidden hi/lo
__device__ __align__(256) bf16 g_qkvh[NK * 3 * Mm], g_qkvl[NK * 3 * Mm]; // fused qkv
__device__ __align__(256) bf16 g_kvh[NK * 2 * Mm], g_kvl[NK * 2 * Mm];   // fused cross kv
__device__ __align__(256) bf16 g_qh[NK * Mm], g_ql[NK * Mm];       // cross q
__device__ __align__(256) bf16 g_wh[16 * 1024 * 1024];             // transposed weights hi
__device__ __align__(256) bf16 g_wl[16 * 1024 * 1024];             // transposed weights lo

// weight offsets (elements) in g_wh/g_wl
#define WOFF_QS (0 * 1048576)
#define WOFF_KS (1 * 1048576)
#define WOFF_VS (2 * 1048576)
#define WOFF_QC (3 * 1048576)
#define WOFF_KC (4 * 1048576)
#define WOFF_VC (5 * 1048576)
#define WOFF_OS (6 * 1048576)
#define WOFF_OC (7 * 1048576)
#define WOFF_W1 (8 * 1048576)
#define WOFF_W2 (12 * 1048576)

// ---------------- PTX helpers ----------------
__device__ __forceinline__ uint32_t smem_u32(const void* p) {
    uint32_t a;
    asm("{ .reg .u64 t; cvta.to.shared.u64 t, %1; cvt.u32.u64 %0, t; }" : "=r"(a) : "l"(p));
    return a;
}

__device__ __forceinline__ void cp16(uint32_t s, const void* g) {
    asm volatile("cp.async.cg.shared.global [%0], [%1], 16;" :: "r"(s), "l"(g));
}

__device__ __forceinline__ void ldm4(uint32_t* r, uint32_t addr) {
    asm volatile("ldmatrix.sync.aligned.m8n8.x4.shared.b16 {%0,%1,%2,%3}, [%4];"
                 : "=r"(r[0]), "=r"(r[1]), "=r"(r[2]), "=r"(r[3]) : "r"(addr));
}

__device__ __forceinline__ void ldm4t(uint32_t* r, uint32_t addr) {
    asm volatile("ldmatrix.sync.aligned.m8n8.x4.trans.shared.b16 {%0,%1,%2,%3}, [%4];"
                 : "=r"(r[0]), "=r"(r[1]), "=r"(r[2]), "=r"(r[3]) : "r"(addr));
}

__device__ __forceinline__ void mma16816(float* c, const uint32_t* a, const uint32_t* b) {
    asm volatile(
        "mma.sync.aligned.m16n8k16.row.col.f32.bf16.bf16.f32 "
        "{%0,%1,%2,%3}, {%4,%5,%6,%7}, {%8,%9}, {%0,%1,%2,%3};"
        : "+f"(c[0]), "+f"(c[1]), "+f"(c[2]), "+f"(c[3])
        : "r"(a[0]), "r"(a[1]), "r"(a[2]), "r"(a[3]), "r"(b[0]), "r"(b[1]));
}

__device__ __forceinline__ uint32_t packbf(float lo, float hi) {
    uint32_t r;
    asm("cvt.rn.bf16x2.f32 %0, %1, %2;" : "=r"(r) : "f"(hi), "f"(lo));
    return r;
}

// ---------------- tensor-core GEMM v2: C[I,J] = (Ah+Al)[I,Kd] @ (Bh+Bl)^T ----------------
// CTA tile 128x256, 8 warps (2m x 4n) of 64x64, BK=32, 3-stage cp.async pipeline.
#define G_ROWB 80
#define G_AB (128 * G_ROWB)           // 10240
#define G_BB (256 * G_ROWB)           // 20480
#define G_STAGE (2 * G_AB + 2 * G_BB) // 61440
#define GSM_SIZE (3 * G_STAGE)        // 184320

__global__ __launch_bounds__(256, 1) void gemm_tc(
    const bf16* __restrict__ Ah, const bf16* __restrict__ Al,
    const bf16* __restrict__ Bh, const bf16* __restrict__ Bl,
    const float* __restrict__ bias, const float* __restrict__ res,
    float* __restrict__ Cf, bf16* __restrict__ Ch, bf16* __restrict__ Cl,
    int Kd, int J, int relu)
{
    extern __shared__ char smem[];
    uint32_t sb = smem_u32(smem);
    int tid = threadIdx.x;
    int wid = tid >> 5, lane = tid & 31;
    int wm = wid >> 2, wn = wid & 3;            // warp grid 2 (M) x 4 (N)
    int i0 = blockIdx.y << 7, j0 = blockIdx.x << 8;

    size_t rowBytes = (size_t)Kd * 2;
    const char* gpA[2] = {
        (const char*)(Ah + (size_t)i0 * Kd),
        (const char*)(Al + (size_t)i0 * Kd)
    };
    const char* gpB[2] = {
        (const char*)(Bh + (size_t)j0 * Kd),
        (const char*)(Bl + (size_t)j0 * Kd)
    };

    auto load_stage = [&](int s, int k0) {
        uint32_t base = sb + (s % 3) * G_STAGE;
        size_t gk = (size_t)k0 * 2;
        #pragma unroll
        for (int c = 0; c < 12; c++) {
            int idx = c * 256 + tid;
            if (c < 4) {   // A: 1024 chunks (2 arrays x 128 rows x 4 cols)
                int arr = idx >> 9, rem = idx & 511, row = rem >> 2, col = rem & 3;
                cp16(base + arr * G_AB + row * G_ROWB + col * 16,
                     gpA[arr] + (size_t)row * rowBytes + gk + col * 16);
            } else {       // B: 2048 chunks (2 arrays x 256 rows x 4 cols)
                int i2 = idx - 1024;
                int arr = i2 >> 10, rem = i2 & 1023, row = rem >> 2, col = rem & 3;
                cp16(base + 2 * G_AB + arr * G_BB + row * G_ROWB + col * 16,
                     gpB[arr] + (size_t)row * rowBytes + gk + col * 16);
            }
        }
        asm volatile("cp.async.commit_group;" ::: "memory");
    };

    float acc[4][8][4] = {};

    int aRow = wm * 64 + (lane & 7) + ((lane >> 3) & 1) * 8;
    int aByte = ((lane >> 4) & 1) * 16;
    int bRow = wn * 64 + (lane & 7) + ((lane >> 4) & 1) * 8;
    int bByte = ((lane >> 3) & 1) * 16;

    int S = Kd >> 5;
    load_stage(0, 0);
    load_stage(1, 32);

    for (int s = 0; s < S; s++) {
        if (s + 2 < S) {
            load_stage(s + 2, (s + 2) << 5);
            asm volatile("cp.async.wait_group 2;" ::: "memory");
        } else if (s + 1 < S) {
            asm volatile("cp.async.wait_group 1;" ::: "memory");
        } else {
            asm volatile("cp.async.wait_group 0;" ::: "memory");
        }
        __syncthreads();

        uint32_t stb = sb + (s % 3) * G_STAGE;

        #pragma unroll
        for (int ks = 0; ks < 2; ks++) {
            uint32_t ah[4][4], al_[4][4];
            #pragma unroll
            for (int fm = 0; fm < 4; fm++) {
                uint32_t off = (uint32_t)(aRow + fm * 16) * G_ROWB + ks * 32 + aByte;
                ldm4(ah[fm],  stb + off);
                ldm4(al_[fm], stb + G_AB + off);
            }
            #pragma unroll
            for (int p = 0; p < 4; p++) {
                uint32_t off = (uint32_t)(bRow + p * 16) * G_ROWB + ks * 32 + bByte;
                uint32_t th[4], tl[4];
                ldm4(th, stb + 2 * G_AB + off);
                ldm4(tl, stb + 2 * G_AB + G_BB + off);
                #pragma unroll
                for (int fm = 0; fm < 4; fm++) {
                    mma16816(acc[fm][2 * p],     ah[fm],  th);
                    mma16816(acc[fm][2 * p + 1], ah[fm],  th + 2);
                    mma16816(acc[fm][2 * p],     ah[fm],  tl);
                    mma16816(acc[fm][2 * p + 1], ah[fm],  tl + 2);
                    mma16816(acc[fm][2 * p],     al_[fm], th);
                    mma16816(acc[fm][2 * p + 1], al_[fm], th + 2);
                }
            }
        }
        __syncthreads();
    }

    bool hb = bias != nullptr, hr = res != nullptr, hf = Cf != nullptr, hh = Ch != nullptr;
    int g = lane >> 2, q = lane & 3;
    #pragma unroll
    for (int fm = 0; fm < 4; fm++) {
        #pragma unroll
        for (int fn = 0; fn < 8; fn++) {
            int col = j0 + wn * 64 + fn * 8 + q * 2;
            #pragma unroll
            for (int half = 0; half < 2; half++) {
                int row = i0 + wm * 64 + fm * 16 + g + half * 8;
                size_t base = (size_t)row * J + col;
                #pragma unroll
                for (int e = 0; e < 2; e++) {
                    float v = acc[fm][fn][half * 2 + e];
                    if (hb) v += bias[col + e];
                    if (hr) v += res[base + e];
                    if (relu) v = fmaxf(v, 0.f);
                    if (hf) Cf[base + e] = v;
                    if (hh) {
                        bf16 h = __float2bfloat16(v);
                        Ch[base + e] = h;
                        Cl[base + e] = __float2bfloat16(v - __bfloat162float(h));
                    }
                }
            }
        }
    }
}

// ---------------- tensor-core flash attention (strided layouts) ----------------
#define AROWB 144
#define AQ_BYTES (128 * AROWB)
#define AKV_BYTES (64 * AROWB)
#define ASTAGE (4 * AKV_BYTES)
#define ATTN_SMEM2 (2 * AQ_BYTES + 2 * ASTAGE)   // 110592

__global__ __launch_bounds__(256) void attn_tc(
    const bf16* __restrict__ Qh, const bf16* __restrict__ Ql,
    const bf16* __restrict__ Kph, const bf16* __restrict__ Kpl,
    const bf16* __restrict__ Vph, const bf16* __restrict__ Vpl,
    int ldq, int ldkv,
    int causal, bf16* __restrict__ Oh, bf16* __restrict__ Ol)
{
    extern __shared__ char smem[];
    uint32_t sb = smem_u32(smem);
    int tid = threadIdx.x, lane = tid & 31, wm = tid >> 5;
    int g = lane >> 2, qd = lane & 3;
    int nh = blockIdx.y;
    int n = nh >> 4, h = nh & 15;
    int q0 = blockIdx.x << 7;

    uint32_t sQ = sb;
    uint32_t sKV0 = sb + 2 * AQ_BYTES;

    const char* qptr[2] = {(const char*)Qh, (const char*)Ql};
    const char* kvptr[4] = {(const char*)Kph, (const char*)Kpl,
                            (const char*)Vph, (const char*)Vpl};
    size_t qOff0  = ((size_t)n * Kk) * ldq  + (size_t)h * Dd;
    size_t kvOff0 = ((size_t)n * Kk) * ldkv + (size_t)h * Dd;

    #pragma unroll
    for (int c = 0; c < 8; c++) {
        int idx = c * 256 + tid;
        int arr = idx >> 10, rem = idx & 1023, row = rem >> 3, col = rem & 7;
        cp16(sQ + arr * AQ_BYTES + row * AROWB + col * 16,
             qptr[arr] + (qOff0 + (size_t)(q0 + row) * ldq) * 2 + col * 16);
    }

    auto load_kv = [&](int s, int l0) {
        uint32_t base = sKV0 + (s & 1) * ASTAGE;
        #pragma unroll
        for (int c = 0; c < 8; c++) {
            int idx = c * 256 + tid;
            int arr = idx >> 9, rem = idx & 511, row = rem >> 3, col = rem & 7;
            cp16(base + arr * AKV_BYTES + row * AROWB + col * 16,
                 kvptr[arr] + (kvOff0 + (size_t)(l0 + row) * ldkv) * 2 + col * 16);
        }
        asm volatile("cp.async.commit_group;" ::: "memory");
    };
    load_kv(0, 0);

    int nt = causal ? ((q0 + 128) >> 6) : (Kk >> 6);

    int aRow = (lane & 7) + ((lane >> 3) & 1) * 8;
    int aByte = ((lane >> 4) & 1) * 16;
    int bRow = (lane & 7) + ((lane >> 4) & 1) * 8;
    int bByte = ((lane >> 3) & 1) * 16;
    int vRow = lane & 15;
    int vByte = ((lane >> 4) & 1) * 16;

    uint32_t qf[2][4][4];
    float Oacc[8][4] = {};
    float mrow[2] = {-1e30f, -1e30f};
    float lrow[2] = {0.f, 0.f};
    const float scale = 0.125f;

    for (int t = 0; t < nt; t++) {
        if (t + 1 < nt) {
            load_kv(t + 1, (t + 1) << 6);
            asm volatile("cp.async.wait_group 1;" ::: "memory");
        } else {
            asm volatile("cp.async.wait_group 0;" ::: "memory");
        }
        __syncthreads();

        if (t == 0) {
            #pragma unroll
            for (int hl = 0; hl < 2; hl++)
                #pragma unroll
                for (int kc = 0; kc < 4; kc++)
                    ldm4(qf[hl][kc], sQ + hl * AQ_BYTES +
                         (uint32_t)(wm * 16 + aRow) * AROWB + kc * 32 + aByte);
        }

        uint32_t kb = sKV0 + (t & 1) * ASTAGE;
        int l0 = t << 6;

        float S[8][4] = {};
        #pragma unroll
        for (int kc = 0; kc < 4; kc++) {
            #pragma unroll
            for (int p = 0; p < 4; p++) {
                uint32_t off = (uint32_t)(p * 16 + bRow) * AROWB + kc * 32 + bByte;
                uint32_t th[4], tl[4];
                ldm4(th, kb + off);
                ldm4(tl, kb + AKV_BYTES + off);
                mma16816(S[2 * p],     qf[0][kc], th);
                mma16816(S[2 * p + 1], qf[0][kc], th + 2);
                mma16816(S[2 * p],     qf[0][kc], tl);
                mma16816(S[2 * p + 1], qf[0][kc], tl + 2);
                mma16816(S[2 * p],     qf[1][kc], th);
                mma16816(S[2 * p + 1], qf[1][kc], th + 2);
            }
        }

        int qr0 = q0 + wm * 16 + g;
        bool needMask = causal && (l0 + 63 > q0 + wm * 16);
        #pragma unroll
        for (int j = 0; j < 8; j++) {
            int lg = l0 + j * 8 + 2 * qd;
            #pragma unroll
            for (int c = 0; c < 4; c++) {
                float v = S[j][c] * scale;
                if (needMask) {
                    int lq = lg + (c & 1);
                    int qq = qr0 + (c >> 1) * 8;
                    if (lq > qq) v = -1e30f;
                }
                S[j][c] = v;
            }
        }

        float alpha[2];
        #pragma unroll
        for (int hf = 0; hf < 2; hf++) {
            float tm = -1e30f;
            #pragma unroll
            for (int j = 0; j < 8; j++) {
                tm = fmaxf(tm, S[j][2 * hf]);
                tm = fmaxf(tm, S[j][2 * hf + 1]);
            }
            tm = fmaxf(tm, __shfl_xor_sync(0xffffffffu, tm, 1));
            tm = fmaxf(tm, __shfl_xor_sync(0xffffffffu, tm, 2));
            float mnew = fmaxf(mrow[hf], tm);
            alpha[hf] = __expf(mrow[hf] - mnew);
            mrow[hf] = mnew;
            float rs = 0.f;
            #pragma unroll
            for (int j = 0; j < 8; j++) {
                float e0 = __expf(S[j][2 * hf] - mnew);
                float e1 = __expf(S[j][2 * hf + 1] - mnew);
                S[j][2 * hf] = e0; S[j][2 * hf + 1] = e1;
                rs += e0 + e1;
            }
            rs += __shfl_xor_sync(0xffffffffu, rs, 1);
            rs += __shfl_xor_sync(0xffffffffu, rs, 2);
            lrow[hf] = lrow[hf] * alpha[hf] + rs;
        }
        #pragma unroll
        for (int j = 0; j < 8; j++) {
            Oacc[j][0] *= alpha[0]; Oacc[j][1] *= alpha[0];
            Oacc[j][2] *= alpha[1]; Oacc[j][3] *= alpha[1];
        }

        uint32_t vb = kb + 2 * AKV_BYTES;
        #pragma unroll
        for (int kc = 0; kc < 4; kc++) {
            uint32_t ph[4], pl[4];
            #pragma unroll
            for (int r = 0; r < 2; r++) {
                int j = 2 * kc + r;
                uint32_t h0 = packbf(S[j][0], S[j][1]);
                float f0 = __uint_as_float(h0 << 16);
                float f1 = __uint_as_float(h0 & 0xffff0000u);
                uint32_t l0r = packbf(S[j][0] - f0, S[j][1] - f1);
                uint32_t h1 = packbf(S[j][2], S[j][3]);
                float f2 = __uint_as_float(h1 << 16);
                float f3 = __uint_as_float(h1 & 0xffff0000u);
                uint32_t l1r = packbf(S[j][2] - f2, S[j][3] - f3);
                ph[2 * r] = h0; ph[2 * r + 1] = h1;
                pl[2 * r] = l0r; pl[2 * r + 1] = l1r;
            }
            #pragma unroll
            for (int p = 0; p < 4; p++) {
                uint32_t off = (uint32_t)(kc * 16 + vRow) * AROWB + p * 32 + vByte;
                uint32_t tvh[4], tvl[4];
                ldm4t(tvh, vb + off);
                ldm4t(tvl, vb + AKV_BYTES + off);
                mma16816(Oacc[2 * p],     ph, tvh);
                mma16816(Oacc[2 * p + 1], ph, tvh + 2);
                mma16816(Oacc[2 * p],     ph, tvl);
                mma16816(Oacc[2 * p + 1], ph, tvl + 2);
                mma16816(Oacc[2 * p],     pl, tvh);
                mma16816(Oacc[2 * p + 1], pl, tvh + 2);
            }
        }
        __syncthreads();
    }

    float inv0 = 1.f / lrow[0], inv1 = 1.f / lrow[1];
    #pragma unroll
    for (int j = 0; j < 8; j++) {
        int d = j * 8 + 2 * qd;
        size_t base0 = ((size_t)n * Kk + q0 + wm * 16 + g) * Mm + (size_t)h * Dd + d;
        size_t base1 = base0 + (size_t)8 * Mm;
        float v0 = Oacc[j][0] * inv0, v1 = Oacc[j][1] * inv0;
        float v2 = Oacc[j][2] * inv1, v3 = Oacc[j][3] * inv1;
        uint32_t h0 = packbf(v0, v1);
        *(uint32_t*)(Oh + base0) = h0;
        float f0 = __uint_as_float(h0 << 16), f1 = __uint_as_float(h0 & 0xffff0000u);
        *(uint32_t*)(Ol + base0) = packbf(v0 - f0, v1 - f1);
        uint32_t h1 = packbf(v2, v3);
        *(uint32_t*)(Oh + base1) = h1;
        float f2 = __uint_as_float(h1 << 16), f3 = __uint_as_float(h1 & 0xffff0000u);
        *(uint32_t*)(Ol + base1) = packbf(v2 - f2, v3 - f3);
    }
}

// ---------------- transpose + hi/lo convert: out[c][r] = in[r][c] ----------------
__global__ void trans_conv(const float* __restrict__ in, bf16* __restrict__ oh,
                           bf16* __restrict__ ol, int R, int C,
                           size_t inStrideZ, size_t outStrideZ)
{
    __shared__ float t[32][33];
    int c0 = blockIdx.x * 32, r0 = blockIdx.y * 32;
    const float* ip = in + (size_t)blockIdx.z * inStrideZ;
    int tx = threadIdx.x, ty = threadIdx.y;
    #pragma unroll
    for (int i = 0; i < 4; i++)
        t[ty + i * 8][tx] = ip[(size_t)(r0 + ty + i * 8) * C + c0 + tx];
    __syncthreads();
    size_t ob = (size_t)blockIdx.z * outStrideZ;
    #pragma unroll
    for (int i = 0; i < 4; i++) {
        float v = t[tx][ty + i * 8];
        size_t o = ob + (size_t)(c0 + ty + i * 8) * R + r0 + tx;
        bf16 h = __float2bfloat16(v);
        oh[o] = h;
        ol[o] = __float2bfloat16(v - __bfloat162float(h));
    }
}

// ---------------- elementwise fp32 -> bf16 hi/lo ----------------
__global__ void conv_hl(const float* __restrict__ in, bf16* __restrict__ oh,
                        bf16* __restrict__ ol)
{
    int i = (blockIdx.x * 256 + threadIdx.x) * 4;
    float4 v = *(const float4*)(in + i);
    float vv[4] = {v.x, v.y, v.z, v.w};
    #pragma unroll
    for (int c = 0; c < 4; c++) {
        bf16 h = __float2bfloat16(vv[c]);
        oh[i + c] = h;
        ol[i + c] = __float2bfloat16(vv[c] - __bfloat162float(h));
    }
}

// ---------------- bias concat ----------------
__global__ void concat3(float* __restrict__ d, const float* __restrict__ a,
                        const float* __restrict__ b, const float* __restrict__ c)
{
    int i = blockIdx.x * 256 + threadIdx.x;   // < 3072
    d[i] = (i < 1024) ? a[i] : ((i < 2048) ? b[i - 1024] : c[i - 2048]);
}
__global__ void concat2(float* __restrict__ d, const float* __restrict__ a,
                        const float* __restrict__ b)
{
    int i = blockIdx.x * 256 + threadIdx.x;   // < 2048
    d[i] = (i < 1024) ? a[i] : b[i - 1024];
}

// ---------------- LayerNorm (block per row, M=1024), optional hi/lo out ----------------
__global__ void ln_kernel(const float* __restrict__ X, const float* __restrict__ g,
                          const float* __restrict__ b, float* __restrict__ Y,
                          bf16* __restrict__ Yh, bf16* __restrict__ Yl)
{
    int row = blockIdx.x;
    int tid = threadIdx.x;
    const float* x = X + (size_t)row * Mm;
    float4 v = *(const float4*)(x + tid * 4);

    __shared__ float red[256];
    red[tid] = v.x + v.y + v.z + v.w;
    __syncthreads();
    for (int o = 128; o > 0; o >>= 1) {
        if (tid < o) red[tid] += red[tid + o];
        __syncthreads();
    }
    float mu = red[0] * (1.f / 1024.f);
    __syncthreads();

    float d0 = v.x - mu, d1 = v.y - mu, d2 = v.z - mu, d3 = v.w - mu;
    red[tid] = d0 * d0 + d1 * d1 + d2 * d2 + d3 * d3;
    __syncthreads();
    for (int o = 128; o > 0; o >>= 1) {
        if (tid < o) red[tid] += red[tid + o];
        __syncthreads();
    }
    float inv = rsqrtf(red[0] * (1.f / 1024.f) + 1e-5f);

    float4 gg = *(const float4*)(g + tid * 4);
    float4 bb = *(const float4*)(b + tid * 4);
    float y0 = d0 * inv * gg.x + bb.x;
    float y1 = d1 * inv * gg.y + bb.y;
    float y2 = d2 * inv * gg.z + bb.z;
    float y3 = d3 * inv * gg.w + bb.w;
    float4 yv = {y0, y1, y2, y3};
    *(float4*)(Y + (size_t)row * Mm + tid * 4) = yv;
    if (Yh) {
        float yy[4] = {y0, y1, y2, y3};
        size_t base = (size_t)row * Mm + tid * 4;
        #pragma unroll
        for (int c = 0; c < 4; c++) {
            bf16 h = __float2bfloat16(yy[c]);
            Yh[base + c] = h;
            Yl[base + c] = __float2bfloat16(yy[c] - __bfloat162float(h));
        }
    }
}

// ---------------- host ----------------
static void launch_gemm(const bf16* Ah, const bf16* Al, const bf16* Bh, const bf16* Bl,
                        const float* bias, const float* res,
                        float* Cf, bf16* Ch, bf16* Cl,
                        int I, int Kd, int J, int relu)
{
    dim3 grid(J / 256, I / 128);
    gemm_tc<<<grid, 256, GSM_SIZE>>>(Ah, Al, Bh, Bl, bias, res, Cf, Ch, Cl, Kd, J, relu);
}

extern "C" void kernel_launch(void* const* d_in, const int* in_sizes, int n_in,
                              void* d_out, int out_size)
{
    const float* dec  = (const float*)d_in[0];
    const float* enc  = (const float*)d_in[1];
    const float* Wq_s = (const float*)d_in[3];  const float* bq_s = (const float*)d_in[4];
    const float* Wk_s = (const float*)d_in[5];  const float* bk_s = (const float*)d_in[6];
    const float* Wv_s = (const float*)d_in[7];  const float* bv_s = (const float*)d_in[8];
    const float* Wo_s = (const float*)d_in[9];  const float* bo_s = (const float*)d_in[10];
    const float* Wq_c = (const float*)d_in[11]; const float* bq_c = (const float*)d_in[12];
    const float* Wk_c = (const float*)d_in[13]; const float* bk_c = (const float*)d_in[14];
    const float* Wv_c = (const float*)d_in[15]; const float* bv_c = (const float*)d_in[16];
    const float* Wo_c = (const float*)d_in[17]; const float* bo_c = (const float*)d_in[18];
    const float* W1   = (const float*)d_in[19]; const float* b1   = (const float*)d_in[20];
    const float* W2   = (const float*)d_in[21]; const float* b2   = (const float*)d_in[22];
    const float* g1   = (const float*)d_in[23]; const float* be1  = (const float*)d_in[24];
    const float* g2   = (const float*)d_in[25]; const float* be2  = (const float*)d_in[26];
    const float* g3   = (const float*)d_in[27]; const float* be3  = (const float*)d_in[28];
    float* out = (float*)d_out;

    cudaFuncSetAttribute(gemm_tc, cudaFuncAttributeMaxDynamicSharedMemorySize, GSM_SIZE);
    cudaFuncSetAttribute(attn_tc, cudaFuncAttributeMaxDynamicSharedMemorySize, ATTN_SMEM2);

    float *x, *y, *z, *b3, *b2c;
    bf16 *dh, *dl, *eh, *el, *yh, *yl, *zh, *zl, *ah, *al, *hh, *hl, *wh, *wl;
    bf16 *qkvh, *qkvl, *kvh, *kvl, *qh, *ql;
    cudaGetSymbolAddress((void**)&x, g_x);
    cudaGetSymbolAddress((void**)&y, g_y);   cudaGetSymbolAddress((void**)&z, g_z);
    cudaGetSymbolAddress((void**)&b3, g_b3); cudaGetSymbolAddress((void**)&b2c, g_b2);
    cudaGetSymbolAddress((void**)&dh, g_dh); cudaGetSymbolAddress((void**)&dl, g_dl);
    cudaGetSymbolAddress((void**)&eh, g_eh); cudaGetSymbolAddress((void**)&el, g_el);
    cudaGetSymbolAddress((void**)&yh, g_yh); cudaGetSymbolAddress((void**)&yl, g_yl);
    cudaGetSymbolAddress((void**)&zh, g_zh); cudaGetSymbolAddress((void**)&zl, g_zl);
    cudaGetSymbolAddress((void**)&ah, g_ah); cudaGetSymbolAddress((void**)&al, g_al);
    cudaGetSymbolAddress((void**)&hh, g_hh); cudaGetSymbolAddress((void**)&hl, g_hl);
    cudaGetSymbolAddress((void**)&wh, g_wh); cudaGetSymbolAddress((void**)&wl, g_wl);
    cudaGetSymbolAddress((void**)&qkvh, g_qkvh); cudaGetSymbolAddress((void**)&qkvl, g_qkvl);
    cudaGetSymbolAddress((void**)&kvh, g_kvh);   cudaGetSymbolAddress((void**)&kvl, g_kvl);
    cudaGetSymbolAddress((void**)&qh, g_qh);     cudaGetSymbolAddress((void**)&ql, g_ql);

    // ---- input conversions + bias concat ----
    conv_hl<<<NK * Mm / 1024, 256>>>(dec, dh, dl);
    conv_hl<<<NK * Mm / 1024, 256>>>(enc, eh, el);
    concat3<<<12, 256>>>(b3, bq_s, bk_s, bv_s);
    concat2<<<8, 256>>>(b2c, bk_c, bv_c);

    // ---- weight transposes (to K-major [J,K] bf16 hi/lo) ----
    dim3 tb(32, 8);
    dim3 tgq(Dd / 32, Mm / 32, Hh);
    trans_conv<<<tgq, tb>>>(Wq_s, wh + WOFF_QS, wl + WOFF_QS, Mm, Dd, (size_t)Mm * Dd, (size_t)Dd * Mm);
    trans_conv<<<tgq, tb>>>(Wk_s, wh + WOFF_KS, wl + WOFF_KS, Mm, Dd, (size_t)Mm * Dd, (size_t)Dd * Mm);
    trans_conv<<<tgq, tb>>>(Wv_s, wh + WOFF_VS, wl + WOFF_VS, Mm, Dd, (size_t)Mm * Dd, (size_t)Dd * Mm);
    trans_conv<<<tgq, tb>>>(Wq_c, wh + WOFF_QC, wl + WOFF_QC, Mm, Dd, (size_t)Mm * Dd, (size_t)Dd * Mm);
    trans_conv<<<tgq, tb>>>(Wk_c, wh + WOFF_KC, wl + WOFF_KC, Mm, Dd, (size_t)Mm * Dd, (size_t)Dd * Mm);
    trans_conv<<<tgq, tb>>>(Wv_c, wh + WOFF_VC, wl + WOFF_VC, Mm, Dd, (size_t)Mm * Dd, (size_t)Dd * Mm);
    dim3 tgo(Mm / 32, Mm / 32, 1);
    trans_conv<<<tgo, tb>>>(Wo_s, wh + WOFF_OS, wl + WOFF_OS, Mm, Mm, 0, 0);
    trans_conv<<<tgo, tb>>>(Wo_c, wh + WOFF_OC, wl + WOFF_OC, Mm, Mm, 0, 0);
    dim3 tg1(Ff / 32, Mm / 32, 1);
    trans_conv<<<tg1, tb>>>(W1, wh + WOFF_W1, wl + WOFF_W1, Mm, Ff, 0, 0);
    dim3 tg2(Mm / 32, Ff / 32, 1);
    trans_conv<<<tg2, tb>>>(W2, wh + WOFF_W2, wl + WOFF_W2, Ff, Mm, 0, 0);

    dim3 agrid(Kk / 128, Nn * Hh);

    // ---- self attention (fused QKV: J=3072) ----
    launch_gemm(dh, dl, wh + WOFF_QS, wl + WOFF_QS, b3, nullptr, nullptr, qkvh, qkvl, NK, Mm, 3 * Mm, 0);
    attn_tc<<<agrid, 256, ATTN_SMEM2>>>(qkvh, qkvl, qkvh + 1024, qkvl + 1024,
                                        qkvh + 2048, qkvl + 2048, 3072, 3072, 1, ah, al);
    launch_gemm(ah, al, wh + WOFF_OS, wl + WOFF_OS, bo_s, dec, x, nullptr, nullptr, NK, Mm, Mm, 0);
    ln_kernel<<<NK, 256>>>(x, g1, be1, y, yh, yl);

    // ---- cross attention (fused KV: J=2048) ----
    launch_gemm(yh, yl, wh + WOFF_QC, wl + WOFF_QC, bq_c, nullptr, nullptr, qh, ql, NK, Mm, Mm, 0);
    launch_gemm(eh, el, wh + WOFF_KC, wl + WOFF_KC, b2c, nullptr, nullptr, kvh, kvl, NK, Mm, 2 * Mm, 0);
    attn_tc<<<agrid, 256, ATTN_SMEM2>>>(qh, ql, kvh, kvl, kvh + 1024, kvl + 1024,
                                        1024, 2048, 0, ah, al);
    launch_gemm(ah, al, wh + WOFF_OC, wl + WOFF_OC, bo_c, y, x, nullptr, nullptr, NK, Mm, Mm, 0);
    ln_kernel<<<NK, 256>>>(x, g2, be2, z, zh, zl);

    // ---- feedforward ----
    launch_gemm(zh, zl, wh + WOFF_W1, wl + WOFF_W1, b1, nullptr, nullptr, hh, hl, NK, Mm, Ff, 1);
    launch_gemm(hh, hl, wh + WOFF_W2, wl + WOFF_W2, b2, z, x, nullptr, nullptr, NK, Ff, Mm, 0);
    ln_kernel<<<NK, 256>>>(x, g3, be3, out, nullptr, nullptr);
}

// round 10
// speedup vs baseline: 3.1794x; 1.2675x over previous
#include <cuda_runtime.h>
#include <cuda_fp16.h>
#include <stdint.h>
#include <math.h>

#define Nn 4
#define Kk 1024
#define Mm 1024
#define Hh 16
#define Dd 64
#define Ff 4096
#define NK 4096   // Nn*Kk

typedef __half hf;

// ---------------- scratch (no allocations allowed) ----------------
__device__ float g_x[NK * Mm];
__device__ float g_y[NK * Mm];
__device__ float g_z[NK * Mm];
__device__ float g_b3[3 * Mm];
__device__ float g_b2[2 * Mm];

__device__ __align__(256) hf g_dh[NK * Mm], g_dl[NK * Mm];       // dec hi/lo
__device__ __align__(256) hf g_eh[NK * Mm], g_el[NK * Mm];       // enc hi/lo
__device__ __align__(256) hf g_yh[NK * Mm], g_yl[NK * Mm];       // ln1 out hi/lo
__device__ __align__(256) hf g_zh[NK * Mm], g_zl[NK * Mm];       // ln2 out hi/lo
__device__ __align__(256) hf g_ah[NK * Mm], g_al[NK * Mm];       // attn out hi/lo
__device__ __align__(256) hf g_hh[NK * Ff], g_hl[NK * Ff];       // ffn hidden hi/lo
__device__ __align__(256) hf g_qkvh[NK * 3 * Mm], g_qkvl[NK * 3 * Mm]; // fused qkv
__device__ __align__(256) hf g_kvh[NK * 2 * Mm], g_kvl[NK * 2 * Mm];   // fused cross kv
__device__ __align__(256) hf g_qh[NK * Mm], g_ql[NK * Mm];       // cross q
__device__ __align__(256) hf g_wh[16 * 1024 * 1024];             // transposed weights (single fp16)

// weight offsets (elements) in g_wh
#define WOFF_QS (0 * 1048576)
#define WOFF_KS (1 * 1048576)
#define WOFF_VS (2 * 1048576)
#define WOFF_QC (3 * 1048576)
#define WOFF_KC (4 * 1048576)
#define WOFF_VC (5 * 1048576)
#define WOFF_OS (6 * 1048576)
#define WOFF_OC (7 * 1048576)
#define WOFF_W1 (8 * 1048576)
#define WOFF_W2 (12 * 1048576)

// ---------------- PTX helpers ----------------
__device__ __forceinline__ uint32_t smem_u32(const void* p) {
    uint32_t a;
    asm("{ .reg .u64 t; cvta.to.shared.u64 t, %1; cvt.u32.u64 %0, t; }" : "=r"(a) : "l"(p));
    return a;
}

__device__ __forceinline__ void cp16(uint32_t s, const void* g) {
    asm volatile("cp.async.cg.shared.global [%0], [%1], 16;" :: "r"(s), "l"(g));
}

__device__ __forceinline__ void ldm4(uint32_t* r, uint32_t addr) {
    asm volatile("ldmatrix.sync.aligned.m8n8.x4.shared.b16 {%0,%1,%2,%3}, [%4];"
                 : "=r"(r[0]), "=r"(r[1]), "=r"(r[2]), "=r"(r[3]) : "r"(addr));
}

__device__ __forceinline__ void ldm4t(uint32_t* r, uint32_t addr) {
    asm volatile("ldmatrix.sync.aligned.m8n8.x4.trans.shared.b16 {%0,%1,%2,%3}, [%4];"
                 : "=r"(r[0]), "=r"(r[1]), "=r"(r[2]), "=r"(r[3]) : "r"(addr));
}

__device__ __forceinline__ void mma16816(float* c, const uint32_t* a, const uint32_t* b) {
    asm volatile(
        "mma.sync.aligned.m16n8k16.row.col.f32.f16.f16.f32 "
        "{%0,%1,%2,%3}, {%4,%5,%6,%7}, {%8,%9}, {%0,%1,%2,%3};"
        : "+f"(c[0]), "+f"(c[1]), "+f"(c[2]), "+f"(c[3])
        : "r"(a[0]), "r"(a[1]), "r"(a[2]), "r"(a[3]), "r"(b[0]), "r"(b[1]));
}

// pack two f32 -> f16x2: lower half = lo, upper half = hi
__device__ __forceinline__ uint32_t packhf(float lo, float hi) {
    uint32_t r;
    asm("cvt.rn.f16x2.f32 %0, %1, %2;" : "=r"(r) : "f"(hi), "f"(lo));
    return r;
}

__device__ __forceinline__ float lo_half_f(uint32_t p) {
    return __half2float(__ushort_as_half((unsigned short)(p & 0xffffu)));
}
__device__ __forceinline__ float hi_half_f(uint32_t p) {
    return __half2float(__ushort_as_half((unsigned short)(p >> 16)));
}

// ---------------- tensor-core GEMM: C[I,J] = (Ah+Al)[I,Kd] @ B^T  (2-term fp16) ----------------
// A: [I,Kd] K-major fp16 hi/lo. B: [J,Kd] K-major fp16 single (pre-transposed weight).
// CTA 128x256, 8 warps (2m x 4n) of 64x64, BK=32, 3-stage cp.async pipeline.
#define G_ROWB 80
#define G_AARR (128 * G_ROWB)               // 10240 per A array
#define G_BARR (256 * G_ROWB)               // 20480
#define G_STAGE (2 * G_AARR + G_BARR)       // 40960
#define GSM_SIZE (3 * G_STAGE)              // 122880

__global__ __launch_bounds__(256, 1) void gemm_tc(
    const hf* __restrict__ Ah, const hf* __restrict__ Al,
    const hf* __restrict__ B,
    const float* __restrict__ bias, const float* __restrict__ res,
    float* __restrict__ Cf, hf* __restrict__ Ch, hf* __restrict__ Cl,
    int Kd, int J, int relu)
{
    extern __shared__ char smem[];
    uint32_t sb = smem_u32(smem);
    int tid = threadIdx.x;
    int wid = tid >> 5, lane = tid & 31;
    int wm = wid >> 2, wn = wid & 3;            // warp grid 2 (M) x 4 (N)
    int i0 = blockIdx.y << 7, j0 = blockIdx.x << 8;

    size_t rowBytes = (size_t)Kd * 2;
    const char* gpA[2] = {
        (const char*)(Ah + (size_t)i0 * Kd),
        (const char*)(Al + (size_t)i0 * Kd)
    };
    const char* gpB = (const char*)(B + (size_t)j0 * Kd);

    auto load_stage = [&](int s, int k0) {
        uint32_t base = sb + (s % 3) * G_STAGE;
        size_t gk = (size_t)k0 * 2;
        #pragma unroll
        for (int c = 0; c < 8; c++) {
            int idx = c * 256 + tid;
            if (c < 4) {   // A: 1024 chunks (2 arrays x 128 rows x 4 cols)
                int arr = idx >> 9, rem = idx & 511, row = rem >> 2, col = rem & 3;
                cp16(base + arr * G_AARR + row * G_ROWB + col * 16,
                     gpA[arr] + (size_t)row * rowBytes + gk + col * 16);
            } else {       // B: 1024 chunks (256 rows x 4 cols)
                int i2 = idx - 1024;
                int row = i2 >> 2, col = i2 & 3;
                cp16(base + 2 * G_AARR + row * G_ROWB + col * 16,
                     gpB + (size_t)row * rowBytes + gk + col * 16);
            }
        }
        asm volatile("cp.async.commit_group;" ::: "memory");
    };

    float acc[4][8][4] = {};

    int aRow = wm * 64 + (lane & 7) + ((lane >> 3) & 1) * 8;
    int aByte = ((lane >> 4) & 1) * 16;
    int bRow = wn * 64 + (lane & 7) + ((lane >> 4) & 1) * 8;
    int bByte = ((lane >> 3) & 1) * 16;

    int S = Kd >> 5;
    load_stage(0, 0);
    load_stage(1, 32);

    for (int s = 0; s < S; s++) {
        if (s + 2 < S) {
            load_stage(s + 2, (s + 2) << 5);
            asm volatile("cp.async.wait_group 2;" ::: "memory");
        } else if (s + 1 < S) {
            asm volatile("cp.async.wait_group 1;" ::: "memory");
        } else {
            asm volatile("cp.async.wait_group 0;" ::: "memory");
        }
        __syncthreads();

        uint32_t stb = sb + (s % 3) * G_STAGE;

        #pragma unroll
        for (int ks = 0; ks < 2; ks++) {
            uint32_t ah[4][4], al_[4][4];
            #pragma unroll
            for (int fm = 0; fm < 4; fm++) {
                uint32_t off = (uint32_t)(aRow + fm * 16) * G_ROWB + ks * 32 + aByte;
                ldm4(ah[fm],  stb + off);
                ldm4(al_[fm], stb + G_AARR + off);
            }
            #pragma unroll
            for (int p = 0; p < 4; p++) {
                uint32_t off = (uint32_t)(bRow + p * 16) * G_ROWB + ks * 32 + bByte;
                uint32_t th[4];
                ldm4(th, stb + 2 * G_AARR + off);
                #pragma unroll
                for (int fm = 0; fm < 4; fm++) {
                    mma16816(acc[fm][2 * p],     ah[fm],  th);
                    mma16816(acc[fm][2 * p + 1], ah[fm],  th + 2);
                    mma16816(acc[fm][2 * p],     al_[fm], th);
                    mma16816(acc[fm][2 * p + 1], al_[fm], th + 2);
                }
            }
        }
        __syncthreads();
    }

    bool hb = bias != nullptr, hr = res != nullptr, hf_ = Cf != nullptr, hh = Ch != nullptr;
    int g = lane >> 2, q = lane & 3;
    #pragma unroll
    for (int fm = 0; fm < 4; fm++) {
        #pragma unroll
        for (int fn = 0; fn < 8; fn++) {
            int col = j0 + wn * 64 + fn * 8 + q * 2;
            #pragma unroll
            for (int half = 0; half < 2; half++) {
                int row = i0 + wm * 64 + fm * 16 + g + half * 8;
                size_t base = (size_t)row * J + col;
                #pragma unroll
                for (int e = 0; e < 2; e++) {
                    float v = acc[fm][fn][half * 2 + e];
                    if (hb) v += bias[col + e];
                    if (hr) v += res[base + e];
                    if (relu) v = fmaxf(v, 0.f);
                    if (hf_) Cf[base + e] = v;
                    if (hh) {
                        hf h = __float2half_rn(v);
                        Ch[base + e] = h;
                        Cl[base + e] = __float2half_rn(v - __half2float(h));
                    }
                }
            }
        }
    }
}

// ---------------- tensor-core flash attention (3-term fp16, strided layouts) ----------------
#define AROWB 144
#define AQ_BYTES (128 * AROWB)
#define AKV_BYTES (64 * AROWB)
#define ASTAGE (4 * AKV_BYTES)
#define ATTN_SMEM2 (2 * AQ_BYTES + 2 * ASTAGE)   // 110592

__global__ __launch_bounds__(256) void attn_tc(
    const hf* __restrict__ Qh, const hf* __restrict__ Ql,
    const hf* __restrict__ Kph, const hf* __restrict__ Kpl,
    const hf* __restrict__ Vph, const hf* __restrict__ Vpl,
    int ldq, int ldkv,
    int causal, hf* __restrict__ Oh, hf* __restrict__ Ol)
{
    extern __shared__ char smem[];
    uint32_t sb = smem_u32(smem);
    int tid = threadIdx.x, lane = tid & 31, wm = tid >> 5;
    int g = lane >> 2, qd = lane & 3;
    int nh = blockIdx.y;
    int n = nh >> 4, h = nh & 15;
    int q0 = blockIdx.x << 7;

    uint32_t sQ = sb;
    uint32_t sKV0 = sb + 2 * AQ_BYTES;

    const char* qptr[2] = {(const char*)Qh, (const char*)Ql};
    const char* kvptr[4] = {(const char*)Kph, (const char*)Kpl,
                            (const char*)Vph, (const char*)Vpl};
    size_t qOff0  = ((size_t)n * Kk) * ldq  + (size_t)h * Dd;
    size_t kvOff0 = ((size_t)n * Kk) * ldkv + (size_t)h * Dd;

    #pragma unroll
    for (int c = 0; c < 8; c++) {
        int idx = c * 256 + tid;
        int arr = idx >> 10, rem = idx & 1023, row = rem >> 3, col = rem & 7;
        cp16(sQ + arr * AQ_BYTES + row * AROWB + col * 16,
             qptr[arr] + (qOff0 + (size_t)(q0 + row) * ldq) * 2 + col * 16);
    }

    auto load_kv = [&](int s, int l0) {
        uint32_t base = sKV0 + (s & 1) * ASTAGE;
        #pragma unroll
        for (int c = 0; c < 8; c++) {
            int idx = c * 256 + tid;
            int arr = idx >> 9, rem = idx & 511, row = rem >> 3, col = rem & 7;
            cp16(base + arr * AKV_BYTES + row * AROWB + col * 16,
                 kvptr[arr] + (kvOff0 + (size_t)(l0 + row) * ldkv) * 2 + col * 16);
        }
        asm volatile("cp.async.commit_group;" ::: "memory");
    };
    load_kv(0, 0);

    int nt = causal ? ((q0 + 128) >> 6) : (Kk >> 6);

    int aRow = (lane & 7) + ((lane >> 3) & 1) * 8;
    int aByte = ((lane >> 4) & 1) * 16;
    int bRow = (lane & 7) + ((lane >> 4) & 1) * 8;
    int bByte = ((lane >> 3) & 1) * 16;
    int vRow = lane & 15;
    int vByte = ((lane >> 4) & 1) * 16;

    uint32_t qf[2][4][4];
    float Oacc[8][4] = {};
    float mrow[2] = {-1e30f, -1e30f};
    float lrow[2] = {0.f, 0.f};
    const float scale = 0.125f;

    for (int t = 0; t < nt; t++) {
        if (t + 1 < nt) {
            load_kv(t + 1, (t + 1) << 6);
            asm volatile("cp.async.wait_group 1;" ::: "memory");
        } else {
            asm volatile("cp.async.wait_group 0;" ::: "memory");
        }
        __syncthreads();

        if (t == 0) {
            #pragma unroll
            for (int hl = 0; hl < 2; hl++)
                #pragma unroll
                for (int kc = 0; kc < 4; kc++)
                    ldm4(qf[hl][kc], sQ + hl * AQ_BYTES +
                         (uint32_t)(wm * 16 + aRow) * AROWB + kc * 32 + aByte);
        }

        uint32_t kb = sKV0 + (t & 1) * ASTAGE;
        int l0 = t << 6;

        float S[8][4] = {};
        #pragma unroll
        for (int kc = 0; kc < 4; kc++) {
            #pragma unroll
            for (int p = 0; p < 4; p++) {
                uint32_t off = (uint32_t)(p * 16 + bRow) * AROWB + kc * 32 + bByte;
                uint32_t th[4], tl[4];
                ldm4(th, kb + off);
                ldm4(tl, kb + AKV_BYTES + off);
                mma16816(S[2 * p],     qf[0][kc], th);
                mma16816(S[2 * p + 1], qf[0][kc], th + 2);
                mma16816(S[2 * p],     qf[0][kc], tl);
                mma16816(S[2 * p + 1], qf[0][kc], tl + 2);
                mma16816(S[2 * p],     qf[1][kc], th);
                mma16816(S[2 * p + 1], qf[1][kc], th + 2);
            }
        }

        int qr0 = q0 + wm * 16 + g;
        bool needMask = causal && (l0 + 63 > q0 + wm * 16);
        #pragma unroll
        for (int j = 0; j < 8; j++) {
            int lg = l0 + j * 8 + 2 * qd;
            #pragma unroll
            for (int c = 0; c < 4; c++) {
                float v = S[j][c] * scale;
                if (needMask) {
                    int lq = lg + (c & 1);
                    int qq = qr0 + (c >> 1) * 8;
                    if (lq > qq) v = -1e30f;
                }
                S[j][c] = v;
            }
        }

        float alpha[2];
        #pragma unroll
        for (int hfi = 0; hfi < 2; hfi++) {
            float tm = -1e30f;
            #pragma unroll
            for (int j = 0; j < 8; j++) {
                tm = fmaxf(tm, S[j][2 * hfi]);
                tm = fmaxf(tm, S[j][2 * hfi + 1]);
            }
            tm = fmaxf(tm, __shfl_xor_sync(0xffffffffu, tm, 1));
            tm = fmaxf(tm, __shfl_xor_sync(0xffffffffu, tm, 2));
            float mnew = fmaxf(mrow[hfi], tm);
            alpha[hfi] = __expf(mrow[hfi] - mnew);
            mrow[hfi] = mnew;
            float rs = 0.f;
            #pragma unroll
            for (int j = 0; j < 8; j++) {
                float e0 = __expf(S[j][2 * hfi] - mnew);
                float e1 = __expf(S[j][2 * hfi + 1] - mnew);
                S[j][2 * hfi] = e0; S[j][2 * hfi + 1] = e1;
                rs += e0 + e1;
            }
            rs += __shfl_xor_sync(0xffffffffu, rs, 1);
            rs += __shfl_xor_sync(0xffffffffu, rs, 2);
            lrow[hfi] = lrow[hfi] * alpha[hfi] + rs;
        }
        #pragma unroll
        for (int j = 0; j < 8; j++) {
            Oacc[j][0] *= alpha[0]; Oacc[j][1] *= alpha[0];
            Oacc[j][2] *= alpha[1]; Oacc[j][3] *= alpha[1];
        }

        uint32_t vb = kb + 2 * AKV_BYTES;
        #pragma unroll
        for (int kc = 0; kc < 4; kc++) {
            uint32_t ph[4], pl[4];
            #pragma unroll
            for (int r = 0; r < 2; r++) {
                int j = 2 * kc + r;
                uint32_t h0 = packhf(S[j][0], S[j][1]);
                uint32_t l0r = packhf(S[j][0] - lo_half_f(h0), S[j][1] - hi_half_f(h0));
                uint32_t h1 = packhf(S[j][2], S[j][3]);
                uint32_t l1r = packhf(S[j][2] - lo_half_f(h1), S[j][3] - hi_half_f(h1));
                ph[2 * r] = h0; ph[2 * r + 1] = h1;
                pl[2 * r] = l0r; pl[2 * r + 1] = l1r;
            }
            #pragma unroll
            for (int p = 0; p < 4; p++) {
                uint32_t off = (uint32_t)(kc * 16 + vRow) * AROWB + p * 32 + vByte;
                uint32_t tvh[4], tvl[4];
                ldm4t(tvh, vb + off);
                ldm4t(tvl, vb + AKV_BYTES + off);
                mma16816(Oacc[2 * p],     ph, tvh);
                mma16816(Oacc[2 * p + 1], ph, tvh + 2);
                mma16816(Oacc[2 * p],     ph, tvl);
                mma16816(Oacc[2 * p + 1], ph, tvl + 2);
                mma16816(Oacc[2 * p],     pl, tvh);
                mma16816(Oacc[2 * p + 1], pl, tvh + 2);
            }
        }
        __syncthreads();
    }

    float inv0 = 1.f / lrow[0], inv1 = 1.f / lrow[1];
    #pragma unroll
    for (int j = 0; j < 8; j++) {
        int d = j * 8 + 2 * qd;
        size_t base0 = ((size_t)n * Kk + q0 + wm * 16 + g) * Mm + (size_t)h * Dd + d;
        size_t base1 = base0 + (size_t)8 * Mm;
        float v0 = Oacc[j][0] * inv0, v1 = Oacc[j][1] * inv0;
        float v2 = Oacc[j][2] * inv1, v3 = Oacc[j][3] * inv1;
        uint32_t h0 = packhf(v0, v1);
        *(uint32_t*)(Oh + base0) = h0;
        *(uint32_t*)(Ol + base0) = packhf(v0 - lo_half_f(h0), v1 - hi_half_f(h0));
        uint32_t h1 = packhf(v2, v3);
        *(uint32_t*)(Oh + base1) = h1;
        *(uint32_t*)(Ol + base1) = packhf(v2 - lo_half_f(h1), v3 - hi_half_f(h1));
    }
}

// ---------------- transpose + fp16 convert: out[c][r] = in[r][c] ----------------
__global__ void trans_conv(const float* __restrict__ in, hf* __restrict__ oh,
                           int R, int C, size_t inStrideZ, size_t outStrideZ)
{
    __shared__ float t[32][33];
    int c0 = blockIdx.x * 32, r0 = blockIdx.y * 32;
    const float* ip = in + (size_t)blockIdx.z * inStrideZ;
    int tx = threadIdx.x, ty = threadIdx.y;
    #pragma unroll
    for (int i = 0; i < 4; i++)
        t[ty + i * 8][tx] = ip[(size_t)(r0 + ty + i * 8) * C + c0 + tx];
    __syncthreads();
    size_t ob = (size_t)blockIdx.z * outStrideZ;
    #pragma unroll
    for (int i = 0; i < 4; i++) {
        float v = t[tx][ty + i * 8];
        size_t o = ob + (size_t)(c0 + ty + i * 8) * R + r0 + tx;
        oh[o] = __float2half_rn(v);
    }
}

// ---------------- elementwise fp32 -> fp16 hi/lo ----------------
__global__ void conv_hl(const float* __restrict__ in, hf* __restrict__ oh,
                        hf* __restrict__ ol)
{
    int i = (blockIdx.x * 256 + threadIdx.x) * 4;
    float4 v = *(const float4*)(in + i);
    float vv[4] = {v.x, v.y, v.z, v.w};
    #pragma unroll
    for (int c = 0; c < 4; c++) {
        hf h = __float2half_rn(vv[c]);
        oh[i + c] = h;
        ol[i + c] = __float2half_rn(vv[c] - __half2float(h));
    }
}

// ---------------- bias concat ----------------
__global__ void concat3(float* __restrict__ d, const float* __restrict__ a,
                        const float* __restrict__ b, const float* __restrict__ c)
{
    int i = blockIdx.x * 256 + threadIdx.x;   // < 3072
    d[i] = (i < 1024) ? a[i] : ((i < 2048) ? b[i - 1024] : c[i - 2048]);
}
__global__ void concat2(float* __restrict__ d, const float* __restrict__ a,
                        const float* __restrict__ b)
{
    int i = blockIdx.x * 256 + threadIdx.x;   // < 2048
    d[i] = (i < 1024) ? a[i] : b[i - 1024];
}

// ---------------- LayerNorm (block per row, M=1024), optional fp16 hi/lo out ----------------
__global__ void ln_kernel(const float* __restrict__ X, const float* __restrict__ g,
                          const float* __restrict__ b, float* __restrict__ Y,
                          hf* __restrict__ Yh, hf* __restrict__ Yl)
{
    int row = blockIdx.x;
    int tid = threadIdx.x;
    const float* x = X + (size_t)row * Mm;
    float4 v = *(const float4*)(x + tid * 4);

    __shared__ float red[256];
    red[tid] = v.x + v.y + v.z + v.w;
    __syncthreads();
    for (int o = 128; o > 0; o >>= 1) {
        if (tid < o) red[tid] += red[tid + o];
        __syncthreads();
    }
    float mu = red[0] * (1.f / 1024.f);
    __syncthreads();

    float d0 = v.x - mu, d1 = v.y - mu, d2 = v.z - mu, d3 = v.w - mu;
    red[tid] = d0 * d0 + d1 * d1 + d2 * d2 + d3 * d3;
    __syncthreads();
    for (int o = 128; o > 0; o >>= 1) {
        if (tid < o) red[tid] += red[tid + o];
        __syncthreads();
    }
    float inv = rsqrtf(red[0] * (1.f / 1024.f) + 1e-5f);

    float4 gg = *(const float4*)(g + tid * 4);
    float4 bb = *(const float4*)(b + tid * 4);
    float y0 = d0 * inv * gg.x + bb.x;
    float y1 = d1 * inv * gg.y + bb.y;
    float y2 = d2 * inv * gg.z + bb.z;
    float y3 = d3 * inv * gg.w + bb.w;
    float4 yv = {y0, y1, y2, y3};
    *(float4*)(Y + (size_t)row * Mm + tid * 4) = yv;
    if (Yh) {
        float yy[4] = {y0, y1, y2, y3};
        size_t base = (size_t)row * Mm + tid * 4;
        #pragma unroll
        for (int c = 0; c < 4; c++) {
            hf h = __float2half_rn(yy[c]);
            Yh[base + c] = h;
            Yl[base + c] = __float2half_rn(yy[c] - __half2float(h));
        }
    }
}

// ---------------- host ----------------
static void launch_gemm(const hf* Ah, const hf* Al, const hf* B,
                        const float* bias, const float* res,
                        float* Cf, hf* Ch, hf* Cl,
                        int I, int Kd, int J, int relu)
{
    dim3 grid(J / 256, I / 128);
    gemm_tc<<<grid, 256, GSM_SIZE>>>(Ah, Al, B, bias, res, Cf, Ch, Cl, Kd, J, relu);
}

extern "C" void kernel_launch(void* const* d_in, const int* in_sizes, int n_in,
                              void* d_out, int out_size)
{
    const float* dec  = (const float*)d_in[0];
    const float* enc  = (const float*)d_in[1];
    const float* Wq_s = (const float*)d_in[3];  const float* bq_s = (const float*)d_in[4];
    const float* Wk_s = (const float*)d_in[5];  const float* bk_s = (const float*)d_in[6];
    const float* Wv_s = (const float*)d_in[7];  const float* bv_s = (const float*)d_in[8];
    const float* Wo_s = (const float*)d_in[9];  const float* bo_s = (const float*)d_in[10];
    const float* Wq_c = (const float*)d_in[11]; const float* bq_c = (const float*)d_in[12];
    const float* Wk_c = (const float*)d_in[13]; const float* bk_c = (const float*)d_in[14];
    const float* Wv_c = (const float*)d_in[15]; const float* bv_c = (const float*)d_in[16];
    const float* Wo_c = (const float*)d_in[17]; const float* bo_c = (const float*)d_in[18];
    const float* W1   = (const float*)d_in[19]; const float* b1   = (const float*)d_in[20];
    const float* W2   = (const float*)d_in[21]; const float* b2   = (const float*)d_in[22];
    const float* g1   = (const float*)d_in[23]; const float* be1  = (const float*)d_in[24];
    const float* g2   = (const float*)d_in[25]; const float* be2  = (const float*)d_in[26];
    const float* g3   = (const float*)d_in[27]; const float* be3  = (const float*)d_in[28];
    float* out = (float*)d_out;

    cudaFuncSetAttribute(gemm_tc, cudaFuncAttributeMaxDynamicSharedMemorySize, GSM_SIZE);
    cudaFuncSetAttribute(attn_tc, cudaFuncAttributeMaxDynamicSharedMemorySize, ATTN_SMEM2);

    float *x, *y, *z, *b3, *b2c;
    hf *dh, *dl, *eh, *el, *yh, *yl, *zh, *zl, *ah, *al, *hh, *hl, *wh;
    hf *qkvh, *qkvl, *kvh, *kvl, *qh, *ql;
    cudaGetSymbolAddress((void**)&x, g_x);
    cudaGetSymbolAddress((void**)&y, g_y);   cudaGetSymbolAddress((void**)&z, g_z);
    cudaGetSymbolAddress((void**)&b3, g_b3); cudaGetSymbolAddress((void**)&b2c, g_b2);
    cudaGetSymbolAddress((void**)&dh, g_dh); cudaGetSymbolAddress((void**)&dl, g_dl);
    cudaGetSymbolAddress((void**)&eh, g_eh); cudaGetSymbolAddress((void**)&el, g_el);
    cudaGetSymbolAddress((void**)&yh, g_yh); cudaGetSymbolAddress((void**)&yl, g_yl);
    cudaGetSymbolAddress((void**)&zh, g_zh); cudaGetSymbolAddress((void**)&zl, g_zl);
    cudaGetSymbolAddress((void**)&ah, g_ah); cudaGetSymbolAddress((void**)&al, g_al);
    cudaGetSymbolAddress((void**)&hh, g_hh); cudaGetSymbolAddress((void**)&hl, g_hl);
    cudaGetSymbolAddress((void**)&wh, g_wh);
    cudaGetSymbolAddress((void**)&qkvh, g_qkvh); cudaGetSymbolAddress((void**)&qkvl, g_qkvl);
    cudaGetSymbolAddress((void**)&kvh, g_kvh);   cudaGetSymbolAddress((void**)&kvl, g_kvl);
    cudaGetSymbolAddress((void**)&qh, g_qh);     cudaGetSymbolAddress((void**)&ql, g_ql);

    // ---- input conversions + bias concat ----
    conv_hl<<<NK * Mm / 1024, 256>>>(dec, dh, dl);
    conv_hl<<<NK * Mm / 1024, 256>>>(enc, eh, el);
    concat3<<<12, 256>>>(b3, bq_s, bk_s, bv_s);
    concat2<<<8, 256>>>(b2c, bk_c, bv_c);

    // ---- weight transposes (to K-major [J,K] single fp16) ----
    dim3 tb(32, 8);
    dim3 tgq(Dd / 32, Mm / 32, Hh);
    trans_conv<<<tgq, tb>>>(Wq_s, wh + WOFF_QS, Mm, Dd, (size_t)Mm * Dd, (size_t)Dd * Mm);
    trans_conv<<<tgq, tb>>>(Wk_s, wh + WOFF_KS, Mm, Dd, (size_t)Mm * Dd, (size_t)Dd * Mm);
    trans_conv<<<tgq, tb>>>(Wv_s, wh + WOFF_VS, Mm, Dd, (size_t)Mm * Dd, (size_t)Dd * Mm);
    trans_conv<<<tgq, tb>>>(Wq_c, wh + WOFF_QC, Mm, Dd, (size_t)Mm * Dd, (size_t)Dd * Mm);
    trans_conv<<<tgq, tb>>>(Wk_c, wh + WOFF_KC, Mm, Dd, (size_t)Mm * Dd, (size_t)Dd * Mm);
    trans_conv<<<tgq, tb>>>(Wv_c, wh + WOFF_VC, Mm, Dd, (size_t)Mm * Dd, (size_t)Dd * Mm);
    dim3 tgo(Mm / 32, Mm / 32, 1);
    trans_conv<<<tgo, tb>>>(Wo_s, wh + WOFF_OS, Mm, Mm, 0, 0);
    trans_conv<<<tgo, tb>>>(Wo_c, wh + WOFF_OC, Mm, Mm, 0, 0);
    dim3 tg1(Ff / 32, Mm / 32, 1);
    trans_conv<<<tg1, tb>>>(W1, wh + WOFF_W1, Mm, Ff, 0, 0);
    dim3 tg2(Mm / 32, Ff / 32, 1);
    trans_conv<<<tg2, tb>>>(W2, wh + WOFF_W2, Ff, Mm, 0, 0);

    dim3 agrid(Kk / 128, Nn * Hh);

    // ---- self attention (fused QKV: J=3072) ----
    launch_gemm(dh, dl, wh + WOFF_QS, b3, nullptr, nullptr, qkvh, qkvl, NK, Mm, 3 * Mm, 0);
    attn_tc<<<agrid, 256, ATTN_SMEM2>>>(qkvh, qkvl, qkvh + 1024, qkvl + 1024,
                                        qkvh + 2048, qkvl + 2048, 3072, 3072, 1, ah, al);
    launch_gemm(ah, al, wh + WOFF_OS, bo_s, dec, x, nullptr, nullptr, NK, Mm, Mm, 0);
    ln_kernel<<<NK, 256>>>(x, g1, be1, y, yh, yl);

    // ---- cross attention (fused KV: J=2048) ----
    launch_gemm(yh, yl, wh + WOFF_QC, bq_c, nullptr, nullptr, qh, ql, NK, Mm, Mm, 0);
    launch_gemm(eh, el, wh + WOFF_KC, b2c, nullptr, nullptr, kvh, kvl, NK, Mm, 2 * Mm, 0);
    attn_tc<<<agrid, 256, ATTN_SMEM2>>>(qh, ql, kvh, kvl, kvh + 1024, kvl + 1024,
                                        1024, 2048, 0, ah, al);
    launch_gemm(ah, al, wh + WOFF_OC, bo_c, y, x, nullptr, nullptr, NK, Mm, Mm, 0);
    ln_kernel<<<NK, 256>>>(x, g2, be2, z, zh, zl);

    // ---- feedforward ----
    launch_gemm(zh, zl, wh + WOFF_W1, b1, nullptr, nullptr, hh, hl, NK, Mm, Ff, 1);
    launch_gemm(hh, hl, wh + WOFF_W2, b2, z, x, nullptr, nullptr, NK, Ff, Mm, 0);
    ln_kernel<<<NK, 256>>>(x, g3, be3, out, nullptr, nullptr);
}

// round 13
// speedup vs baseline: 5.8682x; 1.8457x over previous
#include <cuda_runtime.h>
#include <cuda_fp16.h>
#include <stdint.h>
#include <math.h>

#define Nn 4
#define Kk 1024
#define Mm 1024
#define Hh 16
#define Dd 64
#define Ff 4096
#define NK 4096   // Nn*Kk

typedef __half hf;

// ---------------- scratch (no allocations allowed) ----------------
__device__ float g_x[NK * Mm];
__device__ float g_y[NK * Mm];
__device__ float g_z[NK * Mm];
__device__ float g_b3[3 * Mm];
__device__ float g_b2[2 * Mm];

__device__ __align__(256) hf g_d[NK * Mm];          // dec fp16
__device__ __align__(256) hf g_e[NK * Mm];          // enc fp16
__device__ __align__(256) hf g_yh[NK * Mm];         // ln1 out fp16
__device__ __align__(256) hf g_zh[NK * Mm];         // ln2 out fp16
__device__ __align__(256) hf g_a[NK * Mm];          // attn out fp16
__device__ __align__(256) hf g_h[NK * Ff];          // ffn hidden fp16
__device__ __align__(256) hf g_qkv[NK * 3 * Mm];    // fused qkv
__device__ __align__(256) hf g_kv[NK * 2 * Mm];     // fused cross kv
__device__ __align__(256) hf g_q[NK * Mm];          // cross q
__device__ __align__(256) hf g_w[16 * 1024 * 1024]; // transposed weights fp16

// weight offsets (elements) in g_w
#define WOFF_QS (0 * 1048576)
#define WOFF_KS (1 * 1048576)
#define WOFF_VS (2 * 1048576)
#define WOFF_QC (3 * 1048576)
#define WOFF_KC (4 * 1048576)
#define WOFF_VC (5 * 1048576)
#define WOFF_OS (6 * 1048576)
#define WOFF_OC (7 * 1048576)
#define WOFF_W1 (8 * 1048576)
#define WOFF_W2 (12 * 1048576)

// ---------------- PTX helpers ----------------
__device__ __forceinline__ uint32_t smem_u32(const void* p) {
    uint32_t a;
    asm("{ .reg .u64 t; cvta.to.shared.u64 t, %1; cvt.u32.u64 %0, t; }" : "=r"(a) : "l"(p));
    return a;
}

__device__ __forceinline__ void cp16(uint32_t s, const void* g) {
    asm volatile("cp.async.cg.shared.global [%0], [%1], 16;" :: "r"(s), "l"(g));
}

__device__ __forceinline__ void ldm4(uint32_t* r, uint32_t addr) {
    asm volatile("ldmatrix.sync.aligned.m8n8.x4.shared.b16 {%0,%1,%2,%3}, [%4];"
                 : "=r"(r[0]), "=r"(r[1]), "=r"(r[2]), "=r"(r[3]) : "r"(addr));
}

__device__ __forceinline__ void ldm4t(uint32_t* r, uint32_t addr) {
    asm volatile("ldmatrix.sync.aligned.m8n8.x4.trans.shared.b16 {%0,%1,%2,%3}, [%4];"
                 : "=r"(r[0]), "=r"(r[1]), "=r"(r[2]), "=r"(r[3]) : "r"(addr));
}

__device__ __forceinline__ void mma16816(float* c, const uint32_t* a, const uint32_t* b) {
    asm volatile(
        "mma.sync.aligned.m16n8k16.row.col.f32.f16.f16.f32 "
        "{%0,%1,%2,%3}, {%4,%5,%6,%7}, {%8,%9}, {%0,%1,%2,%3};"
        : "+f"(c[0]), "+f"(c[1]), "+f"(c[2]), "+f"(c[3])
        : "r"(a[0]), "r"(a[1]), "r"(a[2]), "r"(a[3]), "r"(b[0]), "r"(b[1]));
}

// pack two f32 -> f16x2: lower half = first arg
__device__ __forceinline__ uint32_t packhf(float lo, float hi) {
    uint32_t r;
    asm("cvt.rn.f16x2.f32 %0, %1, %2;" : "=r"(r) : "f"(hi), "f"(lo));
    return r;
}

// ---------------- tensor-core GEMM: C[I,J] = A[I,Kd] @ B^T  (single fp16) ----------------
// A: [I,Kd] K-major fp16. B: [J,Kd] K-major fp16 (pre-transposed weight).
// CTA 128x256, 8 warps (2m x 4n) of 64x64, BK=32, 3-stage cp.async pipeline.
#define G_ROWB 80
#define G_AARR (128 * G_ROWB)           // 10240
#define G_BARR (256 * G_ROWB)           // 20480
#define G_STAGE (G_AARR + G_BARR)       // 30720
#define GSM_SIZE (3 * G_STAGE)          // 92160

__global__ __launch_bounds__(256, 1) void gemm_tc(
    const hf* __restrict__ A, const hf* __restrict__ B,
    const float* __restrict__ bias, const float* __restrict__ res,
    float* __restrict__ Cf, hf* __restrict__ Ch,
    int Kd, int J, int relu)
{
    extern __shared__ char smem[];
    uint32_t sb = smem_u32(smem);
    int tid = threadIdx.x;
    int wid = tid >> 5, lane = tid & 31;
    int wm = wid >> 2, wn = wid & 3;            // warp grid 2 (M) x 4 (N)
    int i0 = blockIdx.y << 7, j0 = blockIdx.x << 8;

    size_t rowBytes = (size_t)Kd * 2;
    const char* gpA = (const char*)(A + (size_t)i0 * Kd);
    const char* gpB = (const char*)(B + (size_t)j0 * Kd);

    auto load_stage = [&](int s, int k0) {
        uint32_t base = sb + (s % 3) * G_STAGE;
        size_t gk = (size_t)k0 * 2;
        #pragma unroll
        for (int c = 0; c < 6; c++) {
            int idx = c * 256 + tid;
            if (c < 2) {   // A: 512 chunks (128 rows x 4 cols)
                int row = idx >> 2, col = idx & 3;
                cp16(base + row * G_ROWB + col * 16,
                     gpA + (size_t)row * rowBytes + gk + col * 16);
            } else {       // B: 1024 chunks (256 rows x 4 cols)
                int i2 = idx - 512;
                int row = i2 >> 2, col = i2 & 3;
                cp16(base + G_AARR + row * G_ROWB + col * 16,
                     gpB + (size_t)row * rowBytes + gk + col * 16);
            }
        }
        asm volatile("cp.async.commit_group;" ::: "memory");
    };

    float acc[4][8][4] = {};

    int aRow = wm * 64 + (lane & 7) + ((lane >> 3) & 1) * 8;
    int aByte = ((lane >> 4) & 1) * 16;
    int bRow = wn * 64 + (lane & 7) + ((lane >> 4) & 1) * 8;
    int bByte = ((lane >> 3) & 1) * 16;

    int S = Kd >> 5;
    load_stage(0, 0);
    load_stage(1, 32);

    for (int s = 0; s < S; s++) {
        if (s + 2 < S) {
            load_stage(s + 2, (s + 2) << 5);
            asm volatile("cp.async.wait_group 2;" ::: "memory");
        } else if (s + 1 < S) {
            asm volatile("cp.async.wait_group 1;" ::: "memory");
        } else {
            asm volatile("cp.async.wait_group 0;" ::: "memory");
        }
        __syncthreads();

        uint32_t stb = sb + (s % 3) * G_STAGE;

        #pragma unroll
        for (int ks = 0; ks < 2; ks++) {
            uint32_t ah[4][4];
            #pragma unroll
            for (int fm = 0; fm < 4; fm++) {
                uint32_t off = (uint32_t)(aRow + fm * 16) * G_ROWB + ks * 32 + aByte;
                ldm4(ah[fm], stb + off);
            }
            #pragma unroll
            for (int p = 0; p < 4; p++) {
                uint32_t off = (uint32_t)(bRow + p * 16) * G_ROWB + ks * 32 + bByte;
                uint32_t th[4];
                ldm4(th, stb + G_AARR + off);
                #pragma unroll
                for (int fm = 0; fm < 4; fm++) {
                    mma16816(acc[fm][2 * p],     ah[fm], th);
                    mma16816(acc[fm][2 * p + 1], ah[fm], th + 2);
                }
            }
        }
        __syncthreads();
    }

    bool hb = bias != nullptr, hr = res != nullptr, hf_ = Cf != nullptr, hh = Ch != nullptr;
    int g = lane >> 2, q = lane & 3;
    #pragma unroll
    for (int fm = 0; fm < 4; fm++) {
        #pragma unroll
        for (int fn = 0; fn < 8; fn++) {
            int col = j0 + wn * 64 + fn * 8 + q * 2;
            #pragma unroll
            for (int half = 0; half < 2; half++) {
                int row = i0 + wm * 64 + fm * 16 + g + half * 8;
                size_t base = (size_t)row * J + col;
                float v0 = acc[fm][fn][half * 2 + 0];
                float v1 = acc[fm][fn][half * 2 + 1];
                if (hb) { v0 += bias[col]; v1 += bias[col + 1]; }
                if (hr) { v0 += res[base]; v1 += res[base + 1]; }
                if (relu) { v0 = fmaxf(v0, 0.f); v1 = fmaxf(v1, 0.f); }
                if (hf_) { Cf[base] = v0; Cf[base + 1] = v1; }
                if (hh)  { *(uint32_t*)(Ch + base) = packhf(v0, v1); }
            }
        }
    }
}

// ---------------- tensor-core flash attention (single fp16, strided layouts) ----------------
#define AROWB 144
#define AQ_BYTES (128 * AROWB)          // 18432
#define AKV_BYTES (64 * AROWB)          // 9216
#define ASTAGE (2 * AKV_BYTES)          // 18432: K, V
#define ATTN_SMEM2 (AQ_BYTES + 2 * ASTAGE)   // 55296

__global__ __launch_bounds__(256) void attn_tc(
    const hf* __restrict__ Q, const hf* __restrict__ Kp, const hf* __restrict__ Vp,
    int ldq, int ldkv,
    int causal, hf* __restrict__ O)
{
    extern __shared__ char smem[];
    uint32_t sb = smem_u32(smem);
    int tid = threadIdx.x, lane = tid & 31, wm = tid >> 5;
    int g = lane >> 2, qd = lane & 3;
    int nh = blockIdx.y;
    int n = nh >> 4, h = nh & 15;
    int q0 = blockIdx.x << 7;

    uint32_t sQ = sb;
    uint32_t sKV0 = sb + AQ_BYTES;

    const char* kvptr[2] = {(const char*)Kp, (const char*)Vp};
    size_t qOff0  = ((size_t)n * Kk) * ldq  + (size_t)h * Dd;
    size_t kvOff0 = ((size_t)n * Kk) * ldkv + (size_t)h * Dd;

    // ---- load Q tile (128 rows x 8 cols of 16B) ----
    #pragma unroll
    for (int c = 0; c < 4; c++) {
        int idx = c * 256 + tid;
        int row = idx >> 3, col = idx & 7;
        cp16(sQ + row * AROWB + col * 16,
             (const char*)Q + (qOff0 + (size_t)(q0 + row) * ldq) * 2 + col * 16);
    }

    auto load_kv = [&](int s, int l0) {
        uint32_t base = sKV0 + (s & 1) * ASTAGE;
        #pragma unroll
        for (int c = 0; c < 4; c++) {
            int idx = c * 256 + tid;
            int arr = idx >> 9, rem = idx & 511, row = rem >> 3, col = rem & 7;
            cp16(base + arr * AKV_BYTES + row * AROWB + col * 16,
                 kvptr[arr] + (kvOff0 + (size_t)(l0 + row) * ldkv) * 2 + col * 16);
        }
        asm volatile("cp.async.commit_group;" ::: "memory");
    };
    load_kv(0, 0);

    int nt = causal ? ((q0 + 128) >> 6) : (Kk >> 6);

    int aRow = (lane & 7) + ((lane >> 3) & 1) * 8;
    int aByte = ((lane >> 4) & 1) * 16;
    int bRow = (lane & 7) + ((lane >> 4) & 1) * 8;
    int bByte = ((lane >> 3) & 1) * 16;
    int vRow = lane & 15;
    int vByte = ((lane >> 4) & 1) * 16;

    uint32_t qf[4][4];
    float Oacc[8][4] = {};
    float mrow[2] = {-1e30f, -1e30f};
    float lrow[2] = {0.f, 0.f};
    const float scale = 0.125f;

    for (int t = 0; t < nt; t++) {
        if (t + 1 < nt) {
            load_kv(t + 1, (t + 1) << 6);
            asm volatile("cp.async.wait_group 1;" ::: "memory");
        } else {
            asm volatile("cp.async.wait_group 0;" ::: "memory");
        }
        __syncthreads();

        if (t == 0) {
            #pragma unroll
            for (int kc = 0; kc < 4; kc++)
                ldm4(qf[kc], sQ + (uint32_t)(wm * 16 + aRow) * AROWB + kc * 32 + aByte);
        }

        uint32_t kb = sKV0 + (t & 1) * ASTAGE;
        int l0 = t << 6;

        // ---- S = Q K^T ----
        float S[8][4] = {};
        #pragma unroll
        for (int kc = 0; kc < 4; kc++) {
            #pragma unroll
            for (int p = 0; p < 4; p++) {
                uint32_t off = (uint32_t)(p * 16 + bRow) * AROWB + kc * 32 + bByte;
                uint32_t th[4];
                ldm4(th, kb + off);
                mma16816(S[2 * p],     qf[kc], th);
                mma16816(S[2 * p + 1], qf[kc], th + 2);
            }
        }

        // ---- scale + causal mask ----
        int qr0 = q0 + wm * 16 + g;
        bool needMask = causal && (l0 + 63 > q0 + wm * 16);
        #pragma unroll
        for (int j = 0; j < 8; j++) {
            int lg = l0 + j * 8 + 2 * qd;
            #pragma unroll
            for (int c = 0; c < 4; c++) {
                float v = S[j][c] * scale;
                if (needMask) {
                    int lq = lg + (c & 1);
                    int qq = qr0 + (c >> 1) * 8;
                    if (lq > qq) v = -1e30f;
                }
                S[j][c] = v;
            }
        }

        // ---- online softmax ----
        float alpha[2];
        #pragma unroll
        for (int hfi = 0; hfi < 2; hfi++) {
            float tm = -1e30f;
            #pragma unroll
            for (int j = 0; j < 8; j++) {
                tm = fmaxf(tm, S[j][2 * hfi]);
                tm = fmaxf(tm, S[j][2 * hfi + 1]);
            }
            tm = fmaxf(tm, __shfl_xor_sync(0xffffffffu, tm, 1));
            tm = fmaxf(tm, __shfl_xor_sync(0xffffffffu, tm, 2));
            float mnew = fmaxf(mrow[hfi], tm);
            alpha[hfi] = __expf(mrow[hfi] - mnew);
            mrow[hfi] = mnew;
            float rs = 0.f;
            #pragma unroll
            for (int j = 0; j < 8; j++) {
                float e0 = __expf(S[j][2 * hfi] - mnew);
                float e1 = __expf(S[j][2 * hfi + 1] - mnew);
                S[j][2 * hfi] = e0; S[j][2 * hfi + 1] = e1;
                rs += e0 + e1;
            }
            rs += __shfl_xor_sync(0xffffffffu, rs, 1);
            rs += __shfl_xor_sync(0xffffffffu, rs, 2);
            lrow[hfi] = lrow[hfi] * alpha[hfi] + rs;
        }
        #pragma unroll
        for (int j = 0; j < 8; j++) {
            Oacc[j][0] *= alpha[0]; Oacc[j][1] *= alpha[0];
            Oacc[j][2] *= alpha[1]; Oacc[j][3] *= alpha[1];
        }

        // ---- O += P V ----
        uint32_t vb = kb + AKV_BYTES;
        #pragma unroll
        for (int kc = 0; kc < 4; kc++) {
            uint32_t ph[4];
            #pragma unroll
            for (int r = 0; r < 2; r++) {
                int j = 2 * kc + r;
                ph[2 * r]     = packhf(S[j][0], S[j][1]);
                ph[2 * r + 1] = packhf(S[j][2], S[j][3]);
            }
            #pragma unroll
            for (int p = 0; p < 4; p++) {
                uint32_t off = (uint32_t)(kc * 16 + vRow) * AROWB + p * 32 + vByte;
                uint32_t tvh[4];
                ldm4t(tvh, vb + off);
                mma16816(Oacc[2 * p],     ph, tvh);
                mma16816(Oacc[2 * p + 1], ph, tvh + 2);
            }
        }
        __syncthreads();
    }

    // ---- epilogue: normalize, emit fp16 ----
    float inv0 = 1.f / lrow[0], inv1 = 1.f / lrow[1];
    #pragma unroll
    for (int j = 0; j < 8; j++) {
        int d = j * 8 + 2 * qd;
        size_t base0 = ((size_t)n * Kk + q0 + wm * 16 + g) * Mm + (size_t)h * Dd + d;
        size_t base1 = base0 + (size_t)8 * Mm;
        *(uint32_t*)(O + base0) = packhf(Oacc[j][0] * inv0, Oacc[j][1] * inv0);
        *(uint32_t*)(O + base1) = packhf(Oacc[j][2] * inv1, Oacc[j][3] * inv1);
    }
}

// ---------------- transpose + fp16 convert: out[c][r] = in[r][c] ----------------
__global__ void trans_conv(const float* __restrict__ in, hf* __restrict__ oh,
                           int R, int C, size_t inStrideZ, size_t outStrideZ)
{
    __shared__ float t[32][33];
    int c0 = blockIdx.x * 32, r0 = blockIdx.y * 32;
    const float* ip = in + (size_t)blockIdx.z * inStrideZ;
    int tx = threadIdx.x, ty = threadIdx.y;
    #pragma unroll
    for (int i = 0; i < 4; i++)
        t[ty + i * 8][tx] = ip[(size_t)(r0 + ty + i * 8) * C + c0 + tx];
    __syncthreads();
    size_t ob = (size_t)blockIdx.z * outStrideZ;
    #pragma unroll
    for (int i = 0; i < 4; i++) {
        float v = t[tx][ty + i * 8];
        size_t o = ob + (size_t)(c0 + ty + i * 8) * R + r0 + tx;
        oh[o] = __float2half_rn(v);
    }
}

// ---------------- elementwise fp32 -> fp16 ----------------
__global__ void conv_h(const float* __restrict__ in, hf* __restrict__ oh)
{
    int i = (blockIdx.x * 256 + threadIdx.x) * 4;
    float4 v = *(const float4*)(in + i);
    uint32_t p0 = packhf(v.x, v.y);
    uint32_t p1 = packhf(v.z, v.w);
    *(uint32_t*)(oh + i)     = p0;
    *(uint32_t*)(oh + i + 2) = p1;
}

// ---------------- bias concat ----------------
__global__ void concat3(float* __restrict__ d, const float* __restrict__ a,
                        const float* __restrict__ b, const float* __restrict__ c)
{
    int i = blockIdx.x * 256 + threadIdx.x;   // < 3072
    d[i] = (i < 1024) ? a[i] : ((i < 2048) ? b[i - 1024] : c[i - 2048]);
}
__global__ void concat2(float* __restrict__ d, const float* __restrict__ a,
                        const float* __restrict__ b)
{
    int i = blockIdx.x * 256 + threadIdx.x;   // < 2048
    d[i] = (i < 1024) ? a[i] : b[i - 1024];
}

// ---------------- LayerNorm (block per row, M=1024), optional fp16 out ----------------
__global__ void ln_kernel(const float* __restrict__ X, const float* __restrict__ g,
                          const float* __restrict__ b, float* __restrict__ Y,
                          hf* __restrict__ Yh)
{
    int row = blockIdx.x;
    int tid = threadIdx.x;
    const float* x = X + (size_t)row * Mm;
    float4 v = *(const float4*)(x + tid * 4);

    __shared__ float red[256];
    red[tid] = v.x + v.y + v.z + v.w;
    __syncthreads();
    for (int o = 128; o > 0; o >>= 1) {
        if (tid < o) red[tid] += red[tid + o];
        __syncthreads();
    }
    float mu = red[0] * (1.f / 1024.f);
    __syncthreads();

    float d0 = v.x - mu, d1 = v.y - mu, d2 = v.z - mu, d3 = v.w - mu;
    red[tid] = d0 * d0 + d1 * d1 + d2 * d2 + d3 * d3;
    __syncthreads();
    for (int o = 128; o > 0; o >>= 1) {
        if (tid < o) red[tid] += red[tid + o];
        __syncthreads();
    }
    float inv = rsqrtf(red[0] * (1.f / 1024.f) + 1e-5f);

    float4 gg = *(const float4*)(g + tid * 4);
    float4 bb = *(const float4*)(b + tid * 4);
    float y0 = d0 * inv * gg.x + bb.x;
    float y1 = d1 * inv * gg.y + bb.y;
    float y2 = d2 * inv * gg.z + bb.z;
    float y3 = d3 * inv * gg.w + bb.w;
    float4 yv = {y0, y1, y2, y3};
    *(float4*)(Y + (size_t)row * Mm + tid * 4) = yv;
    if (Yh) {
        size_t base = (size_t)row * Mm + tid * 4;
        *(uint32_t*)(Yh + base)     = packhf(y0, y1);
        *(uint32_t*)(Yh + base + 2) = packhf(y2, y3);
    }
}

// ---------------- host ----------------
static void launch_gemm(const hf* A, const hf* B,
                        const float* bias, const float* res,
                        float* Cf, hf* Ch,
                        int I, int Kd, int J, int relu)
{
    dim3 grid(J / 256, I / 128);
    gemm_tc<<<grid, 256, GSM_SIZE>>>(A, B, bias, res, Cf, Ch, Kd, J, relu);
}

extern "C" void kernel_launch(void* const* d_in, const int* in_sizes, int n_in,
                              void* d_out, int out_size)
{
    const float* dec  = (const float*)d_in[0];
    const float* enc  = (const float*)d_in[1];
    const float* Wq_s = (const float*)d_in[3];  const float* bq_s = (const float*)d_in[4];
    const float* Wk_s = (const float*)d_in[5];  const float* bk_s = (const float*)d_in[6];
    const float* Wv_s = (const float*)d_in[7];  const float* bv_s = (const float*)d_in[8];
    const float* Wo_s = (const float*)d_in[9];  const float* bo_s = (const float*)d_in[10];
    const float* Wq_c = (const float*)d_in[11]; const float* bq_c = (const float*)d_in[12];
    const float* Wk_c = (const float*)d_in[13]; const float* bk_c = (const float*)d_in[14];
    const float* Wv_c = (const float*)d_in[15]; const float* bv_c = (const float*)d_in[16];
    const float* Wo_c = (const float*)d_in[17]; const float* bo_c = (const float*)d_in[18];
    const float* W1   = (const float*)d_in[19]; const float* b1   = (const float*)d_in[20];
    const float* W2   = (const float*)d_in[21]; const float* b2   = (const float*)d_in[22];
    const float* g1   = (const float*)d_in[23]; const float* be1  = (const float*)d_in[24];
    const float* g2   = (const float*)d_in[25]; const float* be2  = (const float*)d_in[26];
    const float* g3   = (const float*)d_in[27]; const float* be3  = (const float*)d_in[28];
    float* out = (float*)d_out;

    cudaFuncSetAttribute(gemm_tc, cudaFuncAttributeMaxDynamicSharedMemorySize, GSM_SIZE);
    cudaFuncSetAttribute(attn_tc, cudaFuncAttributeMaxDynamicSharedMemorySize, ATTN_SMEM2);

    float *x, *y, *z, *b3, *b2c;
    hf *d16, *e16, *yh, *zh, *a16, *h16, *w16, *qkv, *kv, *q16;
    cudaGetSymbolAddress((void**)&x, g_x);
    cudaGetSymbolAddress((void**)&y, g_y);   cudaGetSymbolAddress((void**)&z, g_z);
    cudaGetSymbolAddress((void**)&b3, g_b3); cudaGetSymbolAddress((void**)&b2c, g_b2);
    cudaGetSymbolAddress((void**)&d16, g_d); cudaGetSymbolAddress((void**)&e16, g_e);
    cudaGetSymbolAddress((void**)&yh, g_yh); cudaGetSymbolAddress((void**)&zh, g_zh);
    cudaGetSymbolAddress((void**)&a16, g_a); cudaGetSymbolAddress((void**)&h16, g_h);
    cudaGetSymbolAddress((void**)&w16, g_w);
    cudaGetSymbolAddress((void**)&qkv, g_qkv);
    cudaGetSymbolAddress((void**)&kv, g_kv);
    cudaGetSymbolAddress((void**)&q16, g_q);

    // ---- input conversions + bias concat ----
    conv_h<<<NK * Mm / 1024, 256>>>(dec, d16);
    conv_h<<<NK * Mm / 1024, 256>>>(enc, e16);
    concat3<<<12, 256>>>(b3, bq_s, bk_s, bv_s);
    concat2<<<8, 256>>>(b2c, bk_c, bv_c);

    // ---- weight transposes (to K-major [J,K] fp16) ----
    dim3 tb(32, 8);
    dim3 tgq(Dd / 32, Mm / 32, Hh);
    trans_conv<<<tgq, tb>>>(Wq_s, w16 + WOFF_QS, Mm, Dd, (size_t)Mm * Dd, (size_t)Dd * Mm);
    trans_conv<<<tgq, tb>>>(Wk_s, w16 + WOFF_KS, Mm, Dd, (size_t)Mm * Dd, (size_t)Dd * Mm);
    trans_conv<<<tgq, tb>>>(Wv_s, w16 + WOFF_VS, Mm, Dd, (size_t)Mm * Dd, (size_t)Dd * Mm);
    trans_conv<<<tgq, tb>>>(Wq_c, w16 + WOFF_QC, Mm, Dd, (size_t)Mm * Dd, (size_t)Dd * Mm);
    trans_conv<<<tgq, tb>>>(Wk_c, w16 + WOFF_KC, Mm, Dd, (size_t)Mm * Dd, (size_t)Dd * Mm);
    trans_conv<<<tgq, tb>>>(Wv_c, w16 + WOFF_VC, Mm, Dd, (size_t)Mm * Dd, (size_t)Dd * Mm);
    dim3 tgo(Mm / 32, Mm / 32, 1);
    trans_conv<<<tgo, tb>>>(Wo_s, w16 + WOFF_OS, Mm, Mm, 0, 0);
    trans_conv<<<tgo, tb>>>(Wo_c, w16 + WOFF_OC, Mm, Mm, 0, 0);
    dim3 tg1(Ff / 32, Mm / 32, 1);
    trans_conv<<<tg1, tb>>>(W1, w16 + WOFF_W1, Mm, Ff, 0, 0);
    dim3 tg2(Mm / 32, Ff / 32, 1);
    trans_conv<<<tg2, tb>>>(W2, w16 + WOFF_W2, Ff, Mm, 0, 0);

    dim3 agrid(Kk / 128, Nn * Hh);

    // ---- self attention (fused QKV: J=3072) ----
    launch_gemm(d16, w16 + WOFF_QS, b3, nullptr, nullptr, qkv, NK, Mm, 3 * Mm, 0);
    attn_tc<<<agrid, 256, ATTN_SMEM2>>>(qkv, qkv + 1024, qkv + 2048, 3072, 3072, 1, a16);
    launch_gemm(a16, w16 + WOFF_OS, bo_s, dec, x, nullptr, NK, Mm, Mm, 0);
    ln_kernel<<<NK, 256>>>(x, g1, be1, y, yh);

    // ---- cross attention (fused KV: J=2048) ----
    launch_gemm(yh, w16 + WOFF_QC, bq_c, nullptr, nullptr, q16, NK, Mm, Mm, 0);
    launch_gemm(e16, w16 + WOFF_KC, b2c, nullptr, nullptr, kv, NK, Mm, 2 * Mm, 0);
    attn_tc<<<agrid, 256, ATTN_SMEM2>>>(q16, kv, kv + 1024, 1024, 2048, 0, a16);
    launch_gemm(a16, w16 + WOFF_OC, bo_c, y, x, nullptr, NK, Mm, Mm, 0);
    ln_kernel<<<NK, 256>>>(x, g2, be2, z, zh);

    // ---- feedforward ----
    launch_gemm(zh, w16 + WOFF_W1, b1, nullptr, nullptr, h16, NK, Mm, Ff, 1);
    launch_gemm(h16, w16 + WOFF_W2, b2, z, x, nullptr, NK, Ff, Mm, 0);
    ln_kernel<<<NK, 256>>>(x, g3, be3, out, nullptr);
}

// round 14
// speedup vs baseline: 5.9593x; 1.0155x over previous
#include <cuda_runtime.h>
#include <cuda_fp16.h>
#include <stdint.h>
#include <math.h>

#define Nn 4
#define Kk 1024
#define Mm 1024
#define Hh 16
#define Dd 64
#define Ff 4096
#define NK 4096   // Nn*Kk

typedef __half hf;

// ---------------- scratch (no allocations allowed) ----------------
__device__ float g_x[NK * Mm];
__device__ float g_y[NK * Mm];
__device__ float g_z[NK * Mm];
__device__ float g_b3[3 * Mm];
__device__ float g_b2[2 * Mm];

__device__ __align__(256) hf g_d[NK * Mm];          // dec fp16
__device__ __align__(256) hf g_e[NK * Mm];          // enc fp16
__device__ __align__(256) hf g_yh[NK * Mm];         // ln1 out fp16
__device__ __align__(256) hf g_zh[NK * Mm];         // ln2 out fp16
__device__ __align__(256) hf g_a[NK * Mm];          // attn out fp16
__device__ __align__(256) hf g_h[NK * Ff];          // ffn hidden fp16
__device__ __align__(256) hf g_qkv[NK * 3 * Mm];    // fused qkv
__device__ __align__(256) hf g_kv[NK * 2 * Mm];     // fused cross kv
__device__ __align__(256) hf g_q[NK * Mm];          // cross q
__device__ __align__(256) hf g_w[16 * 1024 * 1024]; // transposed weights fp16

// weight offsets (elements) in g_w
#define WOFF_QS (0 * 1048576)
#define WOFF_KS (1 * 1048576)
#define WOFF_VS (2 * 1048576)
#define WOFF_QC (3 * 1048576)
#define WOFF_KC (4 * 1048576)
#define WOFF_VC (5 * 1048576)
#define WOFF_OS (6 * 1048576)
#define WOFF_OC (7 * 1048576)
#define WOFF_W1 (8 * 1048576)
#define WOFF_W2 (12 * 1048576)

// ---------------- PTX helpers ----------------
__device__ __forceinline__ uint32_t smem_u32(const void* p) {
    uint32_t a;
    asm("{ .reg .u64 t; cvta.to.shared.u64 t, %1; cvt.u32.u64 %0, t; }" : "=r"(a) : "l"(p));
    return a;
}

__device__ __forceinline__ void cp16(uint32_t s, const void* g) {
    asm volatile("cp.async.cg.shared.global [%0], [%1], 16;" :: "r"(s), "l"(g));
}

__device__ __forceinline__ void ldm4(uint32_t* r, uint32_t addr) {
    asm volatile("ldmatrix.sync.aligned.m8n8.x4.shared.b16 {%0,%1,%2,%3}, [%4];"
                 : "=r"(r[0]), "=r"(r[1]), "=r"(r[2]), "=r"(r[3]) : "r"(addr));
}

__device__ __forceinline__ void ldm4t(uint32_t* r, uint32_t addr) {
    asm volatile("ldmatrix.sync.aligned.m8n8.x4.trans.shared.b16 {%0,%1,%2,%3}, [%4];"
                 : "=r"(r[0]), "=r"(r[1]), "=r"(r[2]), "=r"(r[3]) : "r"(addr));
}

__device__ __forceinline__ void mma16816(float* c, const uint32_t* a, const uint32_t* b) {
    asm volatile(
        "mma.sync.aligned.m16n8k16.row.col.f32.f16.f16.f32 "
        "{%0,%1,%2,%3}, {%4,%5,%6,%7}, {%8,%9}, {%0,%1,%2,%3};"
        : "+f"(c[0]), "+f"(c[1]), "+f"(c[2]), "+f"(c[3])
        : "r"(a[0]), "r"(a[1]), "r"(a[2]), "r"(a[3]), "r"(b[0]), "r"(b[1]));
}

// pack two f32 -> f16x2: lower half = first arg
__device__ __forceinline__ uint32_t packhf(float lo, float hi) {
    uint32_t r;
    asm("cvt.rn.f16x2.f32 %0, %1, %2;" : "=r"(r) : "f"(hi), "f"(lo));
    return r;
}

// ---------------- tensor-core GEMM: C[I,J] = A[I,Kd] @ B^T  (single fp16) ----------------
#define G_ROWB 80
#define G_AARR (128 * G_ROWB)           // 10240
#define G_BARR (256 * G_ROWB)           // 20480
#define G_STAGE (G_AARR + G_BARR)       // 30720
#define GSM_SIZE (3 * G_STAGE)          // 92160

__global__ __launch_bounds__(256, 1) void gemm_tc(
    const hf* __restrict__ A, const hf* __restrict__ B,
    const float* __restrict__ bias, const float* __restrict__ res,
    float* __restrict__ Cf, hf* __restrict__ Ch,
    int Kd, int J, int relu)
{
    extern __shared__ char smem[];
    uint32_t sb = smem_u32(smem);
    int tid = threadIdx.x;
    int wid = tid >> 5, lane = tid & 31;
    int wm = wid >> 2, wn = wid & 3;            // warp grid 2 (M) x 4 (N)
    int i0 = blockIdx.y << 7, j0 = blockIdx.x << 8;

    size_t rowBytes = (size_t)Kd * 2;
    const char* gpA = (const char*)(A + (size_t)i0 * Kd);
    const char* gpB = (const char*)(B + (size_t)j0 * Kd);

    auto load_stage = [&](int s, int k0) {
        uint32_t base = sb + (s % 3) * G_STAGE;
        size_t gk = (size_t)k0 * 2;
        #pragma unroll
        for (int c = 0; c < 6; c++) {
            int idx = c * 256 + tid;
            if (c < 2) {
                int row = idx >> 2, col = idx & 3;
                cp16(base + row * G_ROWB + col * 16,
                     gpA + (size_t)row * rowBytes + gk + col * 16);
            } else {
                int i2 = idx - 512;
                int row = i2 >> 2, col = i2 & 3;
                cp16(base + G_AARR + row * G_ROWB + col * 16,
                     gpB + (size_t)row * rowBytes + gk + col * 16);
            }
        }
        asm volatile("cp.async.commit_group;" ::: "memory");
    };

    float acc[4][8][4] = {};

    int aRow = wm * 64 + (lane & 7) + ((lane >> 3) & 1) * 8;
    int aByte = ((lane >> 4) & 1) * 16;
    int bRow = wn * 64 + (lane & 7) + ((lane >> 4) & 1) * 8;
    int bByte = ((lane >> 3) & 1) * 16;

    int S = Kd >> 5;
    load_stage(0, 0);
    load_stage(1, 32);

    for (int s = 0; s < S; s++) {
        if (s + 2 < S) {
            load_stage(s + 2, (s + 2) << 5);
            asm volatile("cp.async.wait_group 2;" ::: "memory");
        } else if (s + 1 < S) {
            asm volatile("cp.async.wait_group 1;" ::: "memory");
        } else {
            asm volatile("cp.async.wait_group 0;" ::: "memory");
        }
        __syncthreads();

        uint32_t stb = sb + (s % 3) * G_STAGE;

        #pragma unroll
        for (int ks = 0; ks < 2; ks++) {
            uint32_t ah[4][4];
            #pragma unroll
            for (int fm = 0; fm < 4; fm++) {
                uint32_t off = (uint32_t)(aRow + fm * 16) * G_ROWB + ks * 32 + aByte;
                ldm4(ah[fm], stb + off);
            }
            #pragma unroll
            for (int p = 0; p < 4; p++) {
                uint32_t off = (uint32_t)(bRow + p * 16) * G_ROWB + ks * 32 + bByte;
                uint32_t th[4];
                ldm4(th, stb + G_AARR + off);
                #pragma unroll
                for (int fm = 0; fm < 4; fm++) {
                    mma16816(acc[fm][2 * p],     ah[fm], th);
                    mma16816(acc[fm][2 * p + 1], ah[fm], th + 2);
                }
            }
        }
        __syncthreads();
    }

    bool hb = bias != nullptr, hr = res != nullptr, hf_ = Cf != nullptr, hh = Ch != nullptr;
    int g = lane >> 2, q = lane & 3;
    #pragma unroll
    for (int fm = 0; fm < 4; fm++) {
        #pragma unroll
        for (int fn = 0; fn < 8; fn++) {
            int col = j0 + wn * 64 + fn * 8 + q * 2;
            #pragma unroll
            for (int half = 0; half < 2; half++) {
                int row = i0 + wm * 64 + fm * 16 + g + half * 8;
                size_t base = (size_t)row * J + col;
                float v0 = acc[fm][fn][half * 2 + 0];
                float v1 = acc[fm][fn][half * 2 + 1];
                if (hb) { v0 += bias[col]; v1 += bias[col + 1]; }
                if (hr) { v0 += res[base]; v1 += res[base + 1]; }
                if (relu) { v0 = fmaxf(v0, 0.f); v1 = fmaxf(v1, 0.f); }
                if (hf_) { Cf[base] = v0; Cf[base + 1] = v1; }
                if (hh)  { *(uint32_t*)(Ch + base) = packhf(v0, v1); }
            }
        }
    }
}

// ---------------- tensor-core flash attention (single fp16, strided layouts) ----------------
#define AROWB 144
#define AQ_BYTES (128 * AROWB)          // 18432
#define AKV_BYTES (64 * AROWB)          // 9216
#define ASTAGE (2 * AKV_BYTES)          // 18432: K, V
#define ATTN_SMEM2 (AQ_BYTES + 2 * ASTAGE)   // 55296

__global__ __launch_bounds__(256) void attn_tc(
    const hf* __restrict__ Q, const hf* __restrict__ Kp, const hf* __restrict__ Vp,
    int ldq, int ldkv,
    int causal, hf* __restrict__ O)
{
    extern __shared__ char smem[];
    uint32_t sb = smem_u32(smem);
    int tid = threadIdx.x, lane = tid & 31, wm = tid >> 5;
    int g = lane >> 2, qd = lane & 3;
    int nh = blockIdx.y;
    int n = nh >> 4, h = nh & 15;
    int q0 = blockIdx.x << 7;

    uint32_t sQ = sb;
    uint32_t sKV0 = sb + AQ_BYTES;

    const char* kvptr[2] = {(const char*)Kp, (const char*)Vp};
    size_t qOff0  = ((size_t)n * Kk) * ldq  + (size_t)h * Dd;
    size_t kvOff0 = ((size_t)n * Kk) * ldkv + (size_t)h * Dd;

    #pragma unroll
    for (int c = 0; c < 4; c++) {
        int idx = c * 256 + tid;
        int row = idx >> 3, col = idx & 7;
        cp16(sQ + row * AROWB + col * 16,
             (const char*)Q + (qOff0 + (size_t)(q0 + row) * ldq) * 2 + col * 16);
    }

    auto load_kv = [&](int s, int l0) {
        uint32_t base = sKV0 + (s & 1) * ASTAGE;
        #pragma unroll
        for (int c = 0; c < 4; c++) {
            int idx = c * 256 + tid;
            int arr = idx >> 9, rem = idx & 511, row = rem >> 3, col = rem & 7;
            cp16(base + arr * AKV_BYTES + row * AROWB + col * 16,
                 kvptr[arr] + (kvOff0 + (size_t)(l0 + row) * ldkv) * 2 + col * 16);
        }
        asm volatile("cp.async.commit_group;" ::: "memory");
    };
    load_kv(0, 0);

    int nt = causal ? ((q0 + 128) >> 6) : (Kk >> 6);

    int aRow = (lane & 7) + ((lane >> 3) & 1) * 8;
    int aByte = ((lane >> 4) & 1) * 16;
    int bRow = (lane & 7) + ((lane >> 4) & 1) * 8;
    int bByte = ((lane >> 3) & 1) * 16;
    int vRow = lane & 15;
    int vByte = ((lane >> 4) & 1) * 16;

    uint32_t qf[4][4];
    float Oacc[8][4] = {};
    float mrow[2] = {-1e30f, -1e30f};
    float lrow[2] = {0.f, 0.f};
    const float scale = 0.125f;

    for (int t = 0; t < nt; t++) {
        if (t + 1 < nt) {
            load_kv(t + 1, (t + 1) << 6);
            asm volatile("cp.async.wait_group 1;" ::: "memory");
        } else {
            asm volatile("cp.async.wait_group 0;" ::: "memory");
        }
        __syncthreads();

        if (t == 0) {
            #pragma unroll
            for (int kc = 0; kc < 4; kc++)
                ldm4(qf[kc], sQ + (uint32_t)(wm * 16 + aRow) * AROWB + kc * 32 + aByte);
        }

        uint32_t kb = sKV0 + (t & 1) * ASTAGE;
        int l0 = t << 6;

        float S[8][4] = {};
        #pragma unroll
        for (int kc = 0; kc < 4; kc++) {
            #pragma unroll
            for (int p = 0; p < 4; p++) {
                uint32_t off = (uint32_t)(p * 16 + bRow) * AROWB + kc * 32 + bByte;
                uint32_t th[4];
                ldm4(th, kb + off);
                mma16816(S[2 * p],     qf[kc], th);
                mma16816(S[2 * p + 1], qf[kc], th + 2);
            }
        }

        int qr0 = q0 + wm * 16 + g;
        bool needMask = causal && (l0 + 63 > q0 + wm * 16);
        #pragma unroll
        for (int j = 0; j < 8; j++) {
            int lg = l0 + j * 8 + 2 * qd;
            #pragma unroll
            for (int c = 0; c < 4; c++) {
                float v = S[j][c] * scale;
                if (needMask) {
                    int lq = lg + (c & 1);
                    int qq = qr0 + (c >> 1) * 8;
                    if (lq > qq) v = -1e30f;
                }
                S[j][c] = v;
            }
        }

        float alpha[2];
        #pragma unroll
        for (int hfi = 0; hfi < 2; hfi++) {
            float tm = -1e30f;
            #pragma unroll
            for (int j = 0; j < 8; j++) {
                tm = fmaxf(tm, S[j][2 * hfi]);
                tm = fmaxf(tm, S[j][2 * hfi + 1]);
            }
            tm = fmaxf(tm, __shfl_xor_sync(0xffffffffu, tm, 1));
            tm = fmaxf(tm, __shfl_xor_sync(0xffffffffu, tm, 2));
            float mnew = fmaxf(mrow[hfi], tm);
            alpha[hfi] = __expf(mrow[hfi] - mnew);
            mrow[hfi] = mnew;
            float rs = 0.f;
            #pragma unroll
            for (int j = 0; j < 8; j++) {
                float e0 = __expf(S[j][2 * hfi] - mnew);
                float e1 = __expf(S[j][2 * hfi + 1] - mnew);
                S[j][2 * hfi] = e0; S[j][2 * hfi + 1] = e1;
                rs += e0 + e1;
            }
            rs += __shfl_xor_sync(0xffffffffu, rs, 1);
            rs += __shfl_xor_sync(0xffffffffu, rs, 2);
            lrow[hfi] = lrow[hfi] * alpha[hfi] + rs;
        }
        #pragma unroll
        for (int j = 0; j < 8; j++) {
            Oacc[j][0] *= alpha[0]; Oacc[j][1] *= alpha[0];
            Oacc[j][2] *= alpha[1]; Oacc[j][3] *= alpha[1];
        }

        uint32_t vb = kb + AKV_BYTES;
        #pragma unroll
        for (int kc = 0; kc < 4; kc++) {
            uint32_t ph[4];
            #pragma unroll
            for (int r = 0; r < 2; r++) {
                int j = 2 * kc + r;
                ph[2 * r]     = packhf(S[j][0], S[j][1]);
                ph[2 * r + 1] = packhf(S[j][2], S[j][3]);
            }
            #pragma unroll
            for (int p = 0; p < 4; p++) {
                uint32_t off = (uint32_t)(kc * 16 + vRow) * AROWB + p * 32 + vByte;
                uint32_t tvh[4];
                ldm4t(tvh, vb + off);
                mma16816(Oacc[2 * p],     ph, tvh);
                mma16816(Oacc[2 * p + 1], ph, tvh + 2);
            }
        }
        __syncthreads();
    }

    float inv0 = 1.f / lrow[0], inv1 = 1.f / lrow[1];
    #pragma unroll
    for (int j = 0; j < 8; j++) {
        int d = j * 8 + 2 * qd;
        size_t base0 = ((size_t)n * Kk + q0 + wm * 16 + g) * Mm + (size_t)h * Dd + d;
        size_t base1 = base0 + (size_t)8 * Mm;
        *(uint32_t*)(O + base0) = packhf(Oacc[j][0] * inv0, Oacc[j][1] * inv0);
        *(uint32_t*)(O + base1) = packhf(Oacc[j][2] * inv1, Oacc[j][3] * inv1);
    }
}

// ---------------- fused prep: all weight transposes + input conversions + bias concats ----
// Transpose tiles: 64 input rows x 32 input cols per block, vectorized fp16x2 output.
// grid layout (blocks):
//   [0, 3072)      : 6 qkv-type weights (512 tiles each): [1024,64] x16 z -> [64,1024]
//   [3072, 4096)   : Wo_s, Wo_c (512 each): [1024,1024] -> [1024,1024]
//   [4096, 6144)   : W1 (2048): [1024,4096] -> [4096,1024]
//   [6144, 8192)   : W2 (2048): [4096,1024] -> [1024,4096]
//   [8192, 10240)  : dec fp32->fp16 copy (2048 blocks x 2048 elems)
//   [10240, 12288) : enc fp32->fp16 copy
//   [12288, 12291) : b3 concat (3 blocks x 1024)
//   [12291, 12293) : b2 concat (2 blocks x 1024)
#define PREP_GRID 12293

__global__ __launch_bounds__(256) void prep_all(
    const float* __restrict__ dec, const float* __restrict__ enc,
    const float* __restrict__ Wq_s, const float* __restrict__ Wk_s, const float* __restrict__ Wv_s,
    const float* __restrict__ Wq_c, const float* __restrict__ Wk_c, const float* __restrict__ Wv_c,
    const float* __restrict__ Wo_s, const float* __restrict__ Wo_c,
    const float* __restrict__ W1, const float* __restrict__ W2,
    const float* __restrict__ bq_s, const float* __restrict__ bk_s, const float* __restrict__ bv_s,
    const float* __restrict__ bk_c, const float* __restrict__ bv_c,
    hf* __restrict__ w16, hf* __restrict__ d16, hf* __restrict__ e16,
    float* __restrict__ b3, float* __restrict__ b2c)
{
    int b = blockIdx.x;
    int tid = threadIdx.x;

    if (b < 8192) {
        // ---- transpose segment ----
        __shared__ float t[32][65];
        const float* src; hf* dst;
        int R, C, z = 0, tile;
        size_t inZ = 0, outZ = 0;
        if (b < 3072) {
            int w = b >> 9; tile = b & 511;
            const float* ws[6] = {Wq_s, Wk_s, Wv_s, Wq_c, Wk_c, Wv_c};
            src = ws[w]; dst = w16 + (size_t)w * 1048576;
            R = 1024; C = 64; inZ = 65536; outZ = 65536;
            z = tile >> 5; tile &= 31;            // 32 tiles per z (16 r x 2 c)
        } else if (b < 4096) {
            int w = (b - 3072) >> 9; tile = (b - 3072) & 511;
            src = w ? Wo_c : Wo_s; dst = w16 + (size_t)(6 + w) * 1048576;
            R = 1024; C = 1024;
        } else if (b < 6144) {
            tile = b - 4096;
            src = W1; dst = w16 + (size_t)WOFF_W1;
            R = 1024; C = 4096;
        } else {
            tile = b - 6144;
            src = W2; dst = w16 + (size_t)WOFF_W2;
            R = 4096; C = 1024;
        }
        int cTiles = C >> 5;
        int rt = tile / cTiles, ct = tile - rt * cTiles;
        int r0 = rt << 6, c0 = ct << 5;
        const float* ip = src + (size_t)z * inZ;
        hf* op = dst + (size_t)z * outZ;

        int tx = tid & 31, ty = tid >> 5;   // 32 x 8
        #pragma unroll
        for (int i = 0; i < 8; i++) {
            int row = ty + i * 8;           // 0..63
            t[tx][row] = ip[(size_t)(r0 + row) * C + c0 + tx];
        }
        __syncthreads();
        #pragma unroll
        for (int i = 0; i < 4; i++) {
            int cc = ty + i * 8;            // 0..31
            float v0 = t[cc][2 * tx];
            float v1 = t[cc][2 * tx + 1];
            size_t o = (size_t)(c0 + cc) * R + r0 + 2 * tx;
            *(uint32_t*)(op + o) = packhf(v0, v1);
        }
    } else if (b < 12288) {
        // ---- fp32 -> fp16 input conversion ----
        const float* src = (b < 10240) ? dec : enc;
        hf* dst = (b < 10240) ? d16 : e16;
        int blk = (b < 10240) ? (b - 8192) : (b - 10240);
        size_t i = ((size_t)blk * 256 + tid) * 8;
        float4 v0 = *(const float4*)(src + i);
        float4 v1 = *(const float4*)(src + i + 4);
        *(uint32_t*)(dst + i)     = packhf(v0.x, v0.y);
        *(uint32_t*)(dst + i + 2) = packhf(v0.z, v0.w);
        *(uint32_t*)(dst + i + 4) = packhf(v1.x, v1.y);
        *(uint32_t*)(dst + i + 6) = packhf(v1.z, v1.w);
    } else if (b < 12291) {
        // ---- b3 concat: [bq_s | bk_s | bv_s] ----
        int i = (b - 12288) * 1024 + tid * 4;
        #pragma unroll
        for (int c = 0; c < 4; c++) {
            int j = i + c;
            b3[j] = (j < 1024) ? bq_s[j] : ((j < 2048) ? bk_s[j - 1024] : bv_s[j - 2048]);
        }
    } else {
        // ---- b2 concat: [bk_c | bv_c] ----
        int i = (b - 12291) * 1024 + tid * 4;
        #pragma unroll
        for (int c = 0; c < 4; c++) {
            int j = i + c;
            b2c[j] = (j < 1024) ? bk_c[j] : bv_c[j - 1024];
        }
    }
}

// ---------------- LayerNorm (block per row, M=1024), optional fp16 out ----------------
__global__ void ln_kernel(const float* __restrict__ X, const float* __restrict__ g,
                          const float* __restrict__ b, float* __restrict__ Y,
                          hf* __restrict__ Yh)
{
    int row = blockIdx.x;
    int tid = threadIdx.x;
    const float* x = X + (size_t)row * Mm;
    float4 v = *(const float4*)(x + tid * 4);

    __shared__ float red[256];
    red[tid] = v.x + v.y + v.z + v.w;
    __syncthreads();
    for (int o = 128; o > 0; o >>= 1) {
        if (tid < o) red[tid] += red[tid + o];
        __syncthreads();
    }
    float mu = red[0] * (1.f / 1024.f);
    __syncthreads();

    float d0 = v.x - mu, d1 = v.y - mu, d2 = v.z - mu, d3 = v.w - mu;
    red[tid] = d0 * d0 + d1 * d1 + d2 * d2 + d3 * d3;
    __syncthreads();
    for (int o = 128; o > 0; o >>= 1) {
        if (tid < o) red[tid] += red[tid + o];
        __syncthreads();
    }
    float inv = rsqrtf(red[0] * (1.f / 1024.f) + 1e-5f);

    float4 gg = *(const float4*)(g + tid * 4);
    float4 bb = *(const float4*)(b + tid * 4);
    float y0 = d0 * inv * gg.x + bb.x;
    float y1 = d1 * inv * gg.y + bb.y;
    float y2 = d2 * inv * gg.z + bb.z;
    float y3 = d3 * inv * gg.w + bb.w;
    float4 yv = {y0, y1, y2, y3};
    *(float4*)(Y + (size_t)row * Mm + tid * 4) = yv;
    if (Yh) {
        size_t base = (size_t)row * Mm + tid * 4;
        *(uint32_t*)(Yh + base)     = packhf(y0, y1);
        *(uint32_t*)(Yh + base + 2) = packhf(y2, y3);
    }
}

// ---------------- host ----------------
static void launch_gemm(const hf* A, const hf* B,
                        const float* bias, const float* res,
                        float* Cf, hf* Ch,
                        int I, int Kd, int J, int relu)
{
    dim3 grid(J / 256, I / 128);
    gemm_tc<<<grid, 256, GSM_SIZE>>>(A, B, bias, res, Cf, Ch, Kd, J, relu);
}

extern "C" void kernel_launch(void* const* d_in, const int* in_sizes, int n_in,
                              void* d_out, int out_size)
{
    const float* dec  = (const float*)d_in[0];
    const float* enc  = (const float*)d_in[1];
    const float* Wq_s = (const float*)d_in[3];  const float* bq_s = (const float*)d_in[4];
    const float* Wk_s = (const float*)d_in[5];  const float* bk_s = (const float*)d_in[6];
    const float* Wv_s = (const float*)d_in[7];  const float* bv_s = (const float*)d_in[8];
    const float* Wo_s = (const float*)d_in[9];  const float* bo_s = (const float*)d_in[10];
    const float* Wq_c = (const float*)d_in[11]; const float* bq_c = (const float*)d_in[12];
    const float* Wk_c = (const float*)d_in[13]; const float* bk_c = (const float*)d_in[14];
    const float* Wv_c = (const float*)d_in[15]; const float* bv_c = (const float*)d_in[16];
    const float* Wo_c = (const float*)d_in[17]; const float* bo_c = (const float*)d_in[18];
    const float* W1   = (const float*)d_in[19]; const float* b1   = (const float*)d_in[20];
    const float* W2   = (const float*)d_in[21]; const float* b2   = (const float*)d_in[22];
    const float* g1   = (const float*)d_in[23]; const float* be1  = (const float*)d_in[24];
    const float* g2   = (const float*)d_in[25]; const float* be2  = (const float*)d_in[26];
    const float* g3   = (const float*)d_in[27]; const float* be3  = (const float*)d_in[28];
    float* out = (float*)d_out;

    cudaFuncSetAttribute(gemm_tc, cudaFuncAttributeMaxDynamicSharedMemorySize, GSM_SIZE);
    cudaFuncSetAttribute(attn_tc, cudaFuncAttributeMaxDynamicSharedMemorySize, ATTN_SMEM2);

    float *x, *y, *z, *b3, *b2c;
    hf *d16, *e16, *yh, *zh, *a16, *h16, *w16, *qkv, *kv, *q16;
    cudaGetSymbolAddress((void**)&x, g_x);
    cudaGetSymbolAddress((void**)&y, g_y);   cudaGetSymbolAddress((void**)&z, g_z);
    cudaGetSymbolAddress((void**)&b3, g_b3); cudaGetSymbolAddress((void**)&b2c, g_b2);
    cudaGetSymbolAddress((void**)&d16, g_d); cudaGetSymbolAddress((void**)&e16, g_e);
    cudaGetSymbolAddress((void**)&yh, g_yh); cudaGetSymbolAddress((void**)&zh, g_zh);
    cudaGetSymbolAddress((void**)&a16, g_a); cudaGetSymbolAddress((void**)&h16, g_h);
    cudaGetSymbolAddress((void**)&w16, g_w);
    cudaGetSymbolAddress((void**)&qkv, g_qkv);
    cudaGetSymbolAddress((void**)&kv, g_kv);
    cudaGetSymbolAddress((void**)&q16, g_q);

    // ---- fused prep: conversions + transposes + concats in ONE launch ----
    prep_all<<<PREP_GRID, 256>>>(dec, enc,
                                 Wq_s, Wk_s, Wv_s, Wq_c, Wk_c, Wv_c,
                                 Wo_s, Wo_c, W1, W2,
                                 bq_s, bk_s, bv_s, bk_c, bv_c,
                                 w16, d16, e16, b3, b2c);

    dim3 agrid(Kk / 128, Nn * Hh);

    // ---- self attention (fused QKV: J=3072) ----
    launch_gemm(d16, w16 + WOFF_QS, b3, nullptr, nullptr, qkv, NK, Mm, 3 * Mm, 0);
    attn_tc<<<agrid, 256, ATTN_SMEM2>>>(qkv, qkv + 1024, qkv + 2048, 3072, 3072, 1, a16);
    launch_gemm(a16, w16 + WOFF_OS, bo_s, dec, x, nullptr, NK, Mm, Mm, 0);
    ln_kernel<<<NK, 256>>>(x, g1, be1, y, yh);

    // ---- cross attention (fused KV: J=2048) ----
    launch_gemm(yh, w16 + WOFF_QC, bq_c, nullptr, nullptr, q16, NK, Mm, Mm, 0);
    launch_gemm(e16, w16 + WOFF_KC, b2c, nullptr, nullptr, kv, NK, Mm, 2 * Mm, 0);
    attn_tc<<<agrid, 256, ATTN_SMEM2>>>(q16, kv, kv + 1024, 1024, 2048, 0, a16);
    launch_gemm(a16, w16 + WOFF_OC, bo_c, y, x, nullptr, NK, Mm, Mm, 0);
    ln_kernel<<<NK, 256>>>(x, g2, be2, z, zh);

    // ---- feedforward ----
    launch_gemm(zh, w16 + WOFF_W1, b1, nullptr, nullptr, h16, NK, Mm, Ff, 1);
    launch_gemm(h16, w16 + WOFF_W2, b2, z, x, nullptr, NK, Ff, Mm, 0);
    ln_kernel<<<NK, 256>>>(x, g3, be3, out, nullptr);
}

// round 16
// speedup vs baseline: 7.0161x; 1.1773x over previous
#include <cuda_runtime.h>
#include <cuda_fp16.h>
#include <stdint.h>
#include <math.h>

#define Nn 4
#define Kk 1024
#define Mm 1024
#define Hh 16
#define Dd 64
#define Ff 4096
#define NK 4096   // Nn*Kk

typedef __half hf;

// ---------------- scratch (no allocations allowed) ----------------
__device__ float g_x[NK * Mm];
__device__ float g_y[NK * Mm];
__device__ float g_z[NK * Mm];
__device__ float g_b3[3 * Mm];
__device__ float g_b2[2 * Mm];

__device__ __align__(256) hf g_d[NK * Mm];          // dec fp16
__device__ __align__(256) hf g_e[NK * Mm];          // enc fp16
__device__ __align__(256) hf g_yh[NK * Mm];         // ln1 out fp16
__device__ __align__(256) hf g_zh[NK * Mm];         // ln2 out fp16
__device__ __align__(256) hf g_a[NK * Mm];          // attn out fp16
__device__ __align__(256) hf g_h[NK * Ff];          // ffn hidden fp16
__device__ __align__(256) hf g_qkv[NK * 3 * Mm];    // fused qkv
__device__ __align__(256) hf g_kv[NK * 2 * Mm];     // fused cross kv
__device__ __align__(256) hf g_q[NK * Mm];          // cross q
__device__ __align__(256) hf g_w[16 * 1024 * 1024]; // transposed weights fp16

// weight offsets (elements) in g_w
#define WOFF_QS (0 * 1048576)
#define WOFF_KS (1 * 1048576)
#define WOFF_VS (2 * 1048576)
#define WOFF_QC (3 * 1048576)
#define WOFF_KC (4 * 1048576)
#define WOFF_VC (5 * 1048576)
#define WOFF_OS (6 * 1048576)
#define WOFF_OC (7 * 1048576)
#define WOFF_W1 (8 * 1048576)
#define WOFF_W2 (12 * 1048576)

// ---------------- PTX helpers ----------------
__device__ __forceinline__ uint32_t smem_u32(const void* p) {
    uint32_t a;
    asm("{ .reg .u64 t; cvta.to.shared.u64 t, %1; cvt.u32.u64 %0, t; }" : "=r"(a) : "l"(p));
    return a;
}

__device__ __forceinline__ void cp16(uint32_t s, const void* g) {
    asm volatile("cp.async.cg.shared.global [%0], [%1], 16;" :: "r"(s), "l"(g));
}

__device__ __forceinline__ void ldm4(uint32_t* r, uint32_t addr) {
    asm volatile("ldmatrix.sync.aligned.m8n8.x4.shared.b16 {%0,%1,%2,%3}, [%4];"
                 : "=r"(r[0]), "=r"(r[1]), "=r"(r[2]), "=r"(r[3]) : "r"(addr));
}

__device__ __forceinline__ void ldm4t(uint32_t* r, uint32_t addr) {
    asm volatile("ldmatrix.sync.aligned.m8n8.x4.trans.shared.b16 {%0,%1,%2,%3}, [%4];"
                 : "=r"(r[0]), "=r"(r[1]), "=r"(r[2]), "=r"(r[3]) : "r"(addr));
}

__device__ __forceinline__ void mma16816(float* c, const uint32_t* a, const uint32_t* b) {
    asm volatile(
        "mma.sync.aligned.m16n8k16.row.col.f32.f16.f16.f32 "
        "{%0,%1,%2,%3}, {%4,%5,%6,%7}, {%8,%9}, {%0,%1,%2,%3};"
        : "+f"(c[0]), "+f"(c[1]), "+f"(c[2]), "+f"(c[3])
        : "r"(a[0]), "r"(a[1]), "r"(a[2]), "r"(a[3]), "r"(b[0]), "r"(b[1]));
}

// pack two f32 -> f16x2: lower half = first arg
__device__ __forceinline__ uint32_t packhf(float lo, float hi) {
    uint32_t r;
    asm("cvt.rn.f16x2.f32 %0, %1, %2;" : "=r"(r) : "f"(hi), "f"(lo));
    return r;
}

// ---------------- tensor-core GEMM: C[I,J] = A[I,Kd] @ B^T  (single fp16) ----------------
// Tile 128x128, 256 thr (8 warps, 2m x 4n, warp tile 64x32), BK=64, 2-stage,
// 144B row stride (conflict-free ldmatrix). 2 CTAs/SM via launch_bounds.
#define G_ROWB 144
#define G_AB (128 * G_ROWB)             // 18432
#define G_STAGE (2 * G_AB)              // 36864 (A + B)
#define GSM_SIZE (2 * G_STAGE)          // 73728

__global__ __launch_bounds__(256, 2) void gemm_tc(
    const hf* __restrict__ A, const hf* __restrict__ B,
    const float* __restrict__ bias, const float* __restrict__ res,
    float* __restrict__ Cf, hf* __restrict__ Ch,
    int Kd, int J, int relu)
{
    extern __shared__ char smem[];
    uint32_t sb = smem_u32(smem);
    int tid = threadIdx.x;
    int wid = tid >> 5, lane = tid & 31;
    int wm = wid >> 2, wn = wid & 3;            // warp grid 2 (M) x 4 (N)
    int i0 = blockIdx.y << 7, j0 = blockIdx.x << 7;

    size_t rowBytes = (size_t)Kd * 2;
    const char* gpA = (const char*)(A + (size_t)i0 * Kd);
    const char* gpB = (const char*)(B + (size_t)j0 * Kd);

    // per stage: A 128 rows x 8 cols of 16B (BK=64 -> 128B/row); same for B
    auto load_stage = [&](int s, int k0) {
        uint32_t base = sb + (s & 1) * G_STAGE;
        size_t gk = (size_t)k0 * 2;
        #pragma unroll
        for (int c = 0; c < 8; c++) {
            int idx = c * 256 + tid;
            if (c < 4) {
                int row = idx >> 3, col = idx & 7;
                cp16(base + row * G_ROWB + col * 16,
                     gpA + (size_t)row * rowBytes + gk + col * 16);
            } else {
                int i2 = idx - 1024;
                int row = i2 >> 3, col = i2 & 7;
                cp16(base + G_AB + row * G_ROWB + col * 16,
                     gpB + (size_t)row * rowBytes + gk + col * 16);
            }
        }
        asm volatile("cp.async.commit_group;" ::: "memory");
    };

    float acc[4][4][4] = {};

    int aRow = wm * 64 + (lane & 7) + ((lane >> 3) & 1) * 8;
    int aByte = ((lane >> 4) & 1) * 16;
    int bRow = wn * 32 + (lane & 7) + ((lane >> 4) & 1) * 8;
    int bByte = ((lane >> 3) & 1) * 16;

    int S = Kd >> 6;
    load_stage(0, 0);

    for (int s = 0; s < S; s++) {
        if (s + 1 < S) {
            load_stage(s + 1, (s + 1) << 6);
            asm volatile("cp.async.wait_group 1;" ::: "memory");
        } else {
            asm volatile("cp.async.wait_group 0;" ::: "memory");
        }
        __syncthreads();

        uint32_t stb = sb + (s & 1) * G_STAGE;

        #pragma unroll
        for (int ks = 0; ks < 4; ks++) {
            uint32_t ah[4][4];
            #pragma unroll
            for (int fm = 0; fm < 4; fm++) {
                uint32_t off = (uint32_t)(aRow + fm * 16) * G_ROWB + ks * 32 + aByte;
                ldm4(ah[fm], stb + off);
            }
            #pragma unroll
            for (int p = 0; p < 2; p++) {
                uint32_t off = (uint32_t)(bRow + p * 16) * G_ROWB + ks * 32 + bByte;
                uint32_t tb[4];
                ldm4(tb, stb + G_AB + off);
                #pragma unroll
                for (int fm = 0; fm < 4; fm++) {
                    mma16816(acc[fm][2 * p],     ah[fm], tb);
                    mma16816(acc[fm][2 * p + 1], ah[fm], tb + 2);
                }
            }
        }
        __syncthreads();
    }

    bool hb = bias != nullptr, hr = res != nullptr, hf_ = Cf != nullptr, hh = Ch != nullptr;
    int g = lane >> 2, q = lane & 3;
    #pragma unroll
    for (int fm = 0; fm < 4; fm++) {
        #pragma unroll
        for (int fn = 0; fn < 4; fn++) {
            int col = j0 + wn * 32 + fn * 8 + q * 2;
            #pragma unroll
            for (int half = 0; half < 2; half++) {
                int row = i0 + wm * 64 + fm * 16 + g + half * 8;
                size_t base = (size_t)row * J + col;
                float v0 = acc[fm][fn][half * 2 + 0];
                float v1 = acc[fm][fn][half * 2 + 1];
                if (hb) { v0 += bias[col]; v1 += bias[col + 1]; }
                if (hr) { v0 += res[base]; v1 += res[base + 1]; }
                if (relu) { v0 = fmaxf(v0, 0.f); v1 = fmaxf(v1, 0.f); }
                if (hf_) { Cf[base] = v0; Cf[base + 1] = v1; }
                if (hh)  { *(uint32_t*)(Ch + base) = packhf(v0, v1); }
            }
        }
    }
}

// ---------------- tensor-core flash attention (single fp16, strided layouts) ----------------
#define AROWB 144
#define AQ_BYTES (128 * AROWB)          // 18432
#define AKV_BYTES (64 * AROWB)          // 9216
#define ASTAGE (2 * AKV_BYTES)          // 18432: K, V
#define ATTN_SMEM2 (AQ_BYTES + 2 * ASTAGE)   // 55296

__global__ __launch_bounds__(256) void attn_tc(
    const hf* __restrict__ Q, const hf* __restrict__ Kp, const hf* __restrict__ Vp,
    int ldq, int ldkv,
    int causal, hf* __restrict__ O)
{
    extern __shared__ char smem[];
    uint32_t sb = smem_u32(smem);
    int tid = threadIdx.x, lane = tid & 31, wm = tid >> 5;
    int g = lane >> 2, qd = lane & 3;
    int nh = blockIdx.y;
    int n = nh >> 4, h = nh & 15;
    int q0 = blockIdx.x << 7;

    uint32_t sQ = sb;
    uint32_t sKV0 = sb + AQ_BYTES;

    const char* kvptr[2] = {(const char*)Kp, (const char*)Vp};
    size_t qOff0  = ((size_t)n * Kk) * ldq  + (size_t)h * Dd;
    size_t kvOff0 = ((size_t)n * Kk) * ldkv + (size_t)h * Dd;

    #pragma unroll
    for (int c = 0; c < 4; c++) {
        int idx = c * 256 + tid;
        int row = idx >> 3, col = idx & 7;
        cp16(sQ + row * AROWB + col * 16,
             (const char*)Q + (qOff0 + (size_t)(q0 + row) * ldq) * 2 + col * 16);
    }

    auto load_kv = [&](int s, int l0) {
        uint32_t base = sKV0 + (s & 1) * ASTAGE;
        #pragma unroll
        for (int c = 0; c < 4; c++) {
            int idx = c * 256 + tid;
            int arr = idx >> 9, rem = idx & 511, row = rem >> 3, col = rem & 7;
            cp16(base + arr * AKV_BYTES + row * AROWB + col * 16,
                 kvptr[arr] + (kvOff0 + (size_t)(l0 + row) * ldkv) * 2 + col * 16);
        }
        asm volatile("cp.async.commit_group;" ::: "memory");
    };
    load_kv(0, 0);

    int nt = causal ? ((q0 + 128) >> 6) : (Kk >> 6);

    int aRow = (lane & 7) + ((lane >> 3) & 1) * 8;
    int aByte = ((lane >> 4) & 1) * 16;
    int bRow = (lane & 7) + ((lane >> 4) & 1) * 8;
    int bByte = ((lane >> 3) & 1) * 16;
    int vRow = lane & 15;
    int vByte = ((lane >> 4) & 1) * 16;

    uint32_t qf[4][4];
    float Oacc[8][4] = {};
    float mrow[2] = {-1e30f, -1e30f};
    float lrow[2] = {0.f, 0.f};
    const float scale = 0.125f;

    for (int t = 0; t < nt; t++) {
        if (t + 1 < nt) {
            load_kv(t + 1, (t + 1) << 6);
            asm volatile("cp.async.wait_group 1;" ::: "memory");
        } else {
            asm volatile("cp.async.wait_group 0;" ::: "memory");
        }
        __syncthreads();

        if (t == 0) {
            #pragma unroll
            for (int kc = 0; kc < 4; kc++)
                ldm4(qf[kc], sQ + (uint32_t)(wm * 16 + aRow) * AROWB + kc * 32 + aByte);
        }

        uint32_t kb = sKV0 + (t & 1) * ASTAGE;
        int l0 = t << 6;

        float S[8][4] = {};
        #pragma unroll
        for (int kc = 0; kc < 4; kc++) {
            #pragma unroll
            for (int p = 0; p < 4; p++) {
                uint32_t off = (uint32_t)(p * 16 + bRow) * AROWB + kc * 32 + bByte;
                uint32_t th[4];
                ldm4(th, kb + off);
                mma16816(S[2 * p],     qf[kc], th);
                mma16816(S[2 * p + 1], qf[kc], th + 2);
            }
        }

        int qr0 = q0 + wm * 16 + g;
        bool needMask = causal && (l0 + 63 > q0 + wm * 16);
        #pragma unroll
        for (int j = 0; j < 8; j++) {
            int lg = l0 + j * 8 + 2 * qd;
            #pragma unroll
            for (int c = 0; c < 4; c++) {
                float v = S[j][c] * scale;
                if (needMask) {
                    int lq = lg + (c & 1);
                    int qq = qr0 + (c >> 1) * 8;
                    if (lq > qq) v = -1e30f;
                }
                S[j][c] = v;
            }
        }

        float alpha[2];
        #pragma unroll
        for (int hfi = 0; hfi < 2; hfi++) {
            float tm = -1e30f;
            #pragma unroll
            for (int j = 0; j < 8; j++) {
                tm = fmaxf(tm, S[j][2 * hfi]);
                tm = fmaxf(tm, S[j][2 * hfi + 1]);
            }
            tm = fmaxf(tm, __shfl_xor_sync(0xffffffffu, tm, 1));
            tm = fmaxf(tm, __shfl_xor_sync(0xffffffffu, tm, 2));
            float mnew = fmaxf(mrow[hfi], tm);
            alpha[hfi] = __expf(mrow[hfi] - mnew);
            mrow[hfi] = mnew;
            float rs = 0.f;
            #pragma unroll
            for (int j = 0; j < 8; j++) {
                float e0 = __expf(S[j][2 * hfi] - mnew);
                float e1 = __expf(S[j][2 * hfi + 1] - mnew);
                S[j][2 * hfi] = e0; S[j][2 * hfi + 1] = e1;
                rs += e0 + e1;
            }
            rs += __shfl_xor_sync(0xffffffffu, rs, 1);
            rs += __shfl_xor_sync(0xffffffffu, rs, 2);
            lrow[hfi] = lrow[hfi] * alpha[hfi] + rs;
        }
        #pragma unroll
        for (int j = 0; j < 8; j++) {
            Oacc[j][0] *= alpha[0]; Oacc[j][1] *= alpha[0];
            Oacc[j][2] *= alpha[1]; Oacc[j][3] *= alpha[1];
        }

        uint32_t vb = kb + AKV_BYTES;
        #pragma unroll
        for (int kc = 0; kc < 4; kc++) {
            uint32_t ph[4];
            #pragma unroll
            for (int r = 0; r < 2; r++) {
                int j = 2 * kc + r;
                ph[2 * r]     = packhf(S[j][0], S[j][1]);
                ph[2 * r + 1] = packhf(S[j][2], S[j][3]);
            }
            #pragma unroll
            for (int p = 0; p < 4; p++) {
                uint32_t off = (uint32_t)(kc * 16 + vRow) * AROWB + p * 32 + vByte;
                uint32_t tvh[4];
                ldm4t(tvh, vb + off);
                mma16816(Oacc[2 * p],     ph, tvh);
                mma16816(Oacc[2 * p + 1], ph, tvh + 2);
            }
        }
        __syncthreads();
    }

    float inv0 = 1.f / lrow[0], inv1 = 1.f / lrow[1];
    #pragma unroll
    for (int j = 0; j < 8; j++) {
        int d = j * 8 + 2 * qd;
        size_t base0 = ((size_t)n * Kk + q0 + wm * 16 + g) * Mm + (size_t)h * Dd + d;
        size_t base1 = base0 + (size_t)8 * Mm;
        *(uint32_t*)(O + base0) = packhf(Oacc[j][0] * inv0, Oacc[j][1] * inv0);
        *(uint32_t*)(O + base1) = packhf(Oacc[j][2] * inv1, Oacc[j][3] * inv1);
    }
}

// ---------------- fused prep (unchanged) ----------------
#define PREP_GRID 12293

__global__ __launch_bounds__(256) void prep_all(
    const float* __restrict__ dec, const float* __restrict__ enc,
    const float* __restrict__ Wq_s, const float* __restrict__ Wk_s, const float* __restrict__ Wv_s,
    const float* __restrict__ Wq_c, const float* __restrict__ Wk_c, const float* __restrict__ Wv_c,
    const float* __restrict__ Wo_s, const float* __restrict__ Wo_c,
    const float* __restrict__ W1, const float* __restrict__ W2,
    const float* __restrict__ bq_s, const float* __restrict__ bk_s, const float* __restrict__ bv_s,
    const float* __restrict__ bk_c, const float* __restrict__ bv_c,
    hf* __restrict__ w16, hf* __restrict__ d16, hf* __restrict__ e16,
    float* __restrict__ b3, float* __restrict__ b2c)
{
    int b = blockIdx.x;
    int tid = threadIdx.x;

    if (b < 8192) {
        __shared__ float t[32][65];
        const float* src; hf* dst;
        int R, C, z = 0, tile;
        size_t inZ = 0, outZ = 0;
        if (b < 3072) {
            int w = b >> 9; tile = b & 511;
            const float* ws[6] = {Wq_s, Wk_s, Wv_s, Wq_c, Wk_c, Wv_c};
            src = ws[w]; dst = w16 + (size_t)w * 1048576;
            R = 1024; C = 64; inZ = 65536; outZ = 65536;
            z = tile >> 5; tile &= 31;
        } else if (b < 4096) {
            int w = (b - 3072) >> 9; tile = (b - 3072) & 511;
            src = w ? Wo_c : Wo_s; dst = w16 + (size_t)(6 + w) * 1048576;
            R = 1024; C = 1024;
        } else if (b < 6144) {
            tile = b - 4096;
            src = W1; dst = w16 + (size_t)WOFF_W1;
            R = 1024; C = 4096;
        } else {
            tile = b - 6144;
            src = W2; dst = w16 + (size_t)WOFF_W2;
            R = 4096; C = 1024;
        }
        int cTiles = C >> 5;
        int rt = tile / cTiles, ct = tile - rt * cTiles;
        int r0 = rt << 6, c0 = ct << 5;
        const float* ip = src + (size_t)z * inZ;
        hf* op = dst + (size_t)z * outZ;

        int tx = tid & 31, ty = tid >> 5;
        #pragma unroll
        for (int i = 0; i < 8; i++) {
            int row = ty + i * 8;
            t[tx][row] = ip[(size_t)(r0 + row) * C + c0 + tx];
        }
        __syncthreads();
        #pragma unroll
        for (int i = 0; i < 4; i++) {
            int cc = ty + i * 8;
            float v0 = t[cc][2 * tx];
            float v1 = t[cc][2 * tx + 1];
            size_t o = (size_t)(c0 + cc) * R + r0 + 2 * tx;
            *(uint32_t*)(op + o) = packhf(v0, v1);
        }
    } else if (b < 12288) {
        const float* src = (b < 10240) ? dec : enc;
        hf* dst = (b < 10240) ? d16 : e16;
        int blk = (b < 10240) ? (b - 8192) : (b - 10240);
        size_t i = ((size_t)blk * 256 + tid) * 8;
        float4 v0 = *(const float4*)(src + i);
        float4 v1 = *(const float4*)(src + i + 4);
        *(uint32_t*)(dst + i)     = packhf(v0.x, v0.y);
        *(uint32_t*)(dst + i + 2) = packhf(v0.z, v0.w);
        *(uint32_t*)(dst + i + 4) = packhf(v1.x, v1.y);
        *(uint32_t*)(dst + i + 6) = packhf(v1.z, v1.w);
    } else if (b < 12291) {
        int i = (b - 12288) * 1024 + tid * 4;
        #pragma unroll
        for (int c = 0; c < 4; c++) {
            int j = i + c;
            b3[j] = (j < 1024) ? bq_s[j] : ((j < 2048) ? bk_s[j - 1024] : bv_s[j - 2048]);
        }
    } else {
        int i = (b - 12291) * 1024 + tid * 4;
        #pragma unroll
        for (int c = 0; c < 4; c++) {
            int j = i + c;
            b2c[j] = (j < 1024) ? bk_c[j] : bv_c[j - 1024];
        }
    }
}

// ---------------- LayerNorm (block per row, M=1024), optional fp16 out ----------------
__global__ void ln_kernel(const float* __restrict__ X, const float* __restrict__ g,
                          const float* __restrict__ b, float* __restrict__ Y,
                          hf* __restrict__ Yh)
{
    int row = blockIdx.x;
    int tid = threadIdx.x;
    const float* x = X + (size_t)row * Mm;
    float4 v = *(const float4*)(x + tid * 4);

    __shared__ float red[256];
    red[tid] = v.x + v.y + v.z + v.w;
    __syncthreads();
    for (int o = 128; o > 0; o >>= 1) {
        if (tid < o) red[tid] += red[tid + o];
        __syncthreads();
    }
    float mu = red[0] * (1.f / 1024.f);
    __syncthreads();

    float d0 = v.x - mu, d1 = v.y - mu, d2 = v.z - mu, d3 = v.w - mu;
    red[tid] = d0 * d0 + d1 * d1 + d2 * d2 + d3 * d3;
    __syncthreads();
    for (int o = 128; o > 0; o >>= 1) {
        if (tid < o) red[tid] += red[tid + o];
        __syncthreads();
    }
    float inv = rsqrtf(red[0] * (1.f / 1024.f) + 1e-5f);

    float4 gg = *(const float4*)(g + tid * 4);
    float4 bb = *(const float4*)(b + tid * 4);
    float y0 = d0 * inv * gg.x + bb.x;
    float y1 = d1 * inv * gg.y + bb.y;
    float y2 = d2 * inv * gg.z + bb.z;
    float y3 = d3 * inv * gg.w + bb.w;
    float4 yv = {y0, y1, y2, y3};
    *(float4*)(Y + (size_t)row * Mm + tid * 4) = yv;
    if (Yh) {
        size_t base = (size_t)row * Mm + tid * 4;
        *(uint32_t*)(Yh + base)     = packhf(y0, y1);
        *(uint32_t*)(Yh + base + 2) = packhf(y2, y3);
    }
}

// ---------------- host ----------------
static void launch_gemm(const hf* A, const hf* B,
                        const float* bias, const float* res,
                        float* Cf, hf* Ch,
                        int I, int Kd, int J, int relu)
{
    dim3 grid(J / 128, I / 128);
    gemm_tc<<<grid, 256, GSM_SIZE>>>(A, B, bias, res, Cf, Ch, Kd, J, relu);
}

extern "C" void kernel_launch(void* const* d_in, const int* in_sizes, int n_in,
                              void* d_out, int out_size)
{
    const float* dec  = (const float*)d_in[0];
    const float* enc  = (const float*)d_in[1];
    const float* Wq_s = (const float*)d_in[3];  const float* bq_s = (const float*)d_in[4];
    const float* Wk_s = (const float*)d_in[5];  const float* bk_s = (const float*)d_in[6];
    const float* Wv_s = (const float*)d_in[7];  const float* bv_s = (const float*)d_in[8];
    const float* Wo_s = (const float*)d_in[9];  const float* bo_s = (const float*)d_in[10];
    const float* Wq_c = (const float*)d_in[11]; const float* bq_c = (const float*)d_in[12];
    const float* Wk_c = (const float*)d_in[13]; const float* bk_c = (const float*)d_in[14];
    const float* Wv_c = (const float*)d_in[15]; const float* bv_c = (const float*)d_in[16];
    const float* Wo_c = (const float*)d_in[17]; const float* bo_c = (const float*)d_in[18];
    const float* W1   = (const float*)d_in[19]; const float* b1   = (const float*)d_in[20];
    const float* W2   = (const float*)d_in[21]; const float* b2   = (const float*)d_in[22];
    const float* g1   = (const float*)d_in[23]; const float* be1  = (const float*)d_in[24];
    const float* g2   = (const float*)d_in[25]; const float* be2  = (const float*)d_in[26];
    const float* g3   = (const float*)d_in[27]; const float* be3  = (const float*)d_in[28];
    float* out = (float*)d_out;

    cudaFuncSetAttribute(gemm_tc, cudaFuncAttributeMaxDynamicSharedMemorySize, GSM_SIZE);
    cudaFuncSetAttribute(attn_tc, cudaFuncAttributeMaxDynamicSharedMemorySize, ATTN_SMEM2);

    float *x, *y, *z, *b3, *b2c;
    hf *d16, *e16, *yh, *zh, *a16, *h16, *w16, *qkv, *kv, *q16;
    cudaGetSymbolAddress((void**)&x, g_x);
    cudaGetSymbolAddress((void**)&y, g_y);   cudaGetSymbolAddress((void**)&z, g_z);
    cudaGetSymbolAddress((void**)&b3, g_b3); cudaGetSymbolAddress((void**)&b2c, g_b2);
    cudaGetSymbolAddress((void**)&d16, g_d); cudaGetSymbolAddress((void**)&e16, g_e);
    cudaGetSymbolAddress((void**)&yh, g_yh); cudaGetSymbolAddress((void**)&zh, g_zh);
    cudaGetSymbolAddress((void**)&a16, g_a); cudaGetSymbolAddress((void**)&h16, g_h);
    cudaGetSymbolAddress((void**)&w16, g_w);
    cudaGetSymbolAddress((void**)&qkv, g_qkv);
    cudaGetSymbolAddress((void**)&kv, g_kv);
    cudaGetSymbolAddress((void**)&q16, g_q);

    // ---- fused prep ----
    prep_all<<<PREP_GRID, 256>>>(dec, enc,
                                 Wq_s, Wk_s, Wv_s, Wq_c, Wk_c, Wv_c,
                                 Wo_s, Wo_c, W1, W2,
                                 bq_s, bk_s, bv_s, bk_c, bv_c,
                                 w16, d16, e16, b3, b2c);

    dim3 agrid(Kk / 128, Nn * Hh);

    // ---- self attention (fused QKV: J=3072) ----
    launch_gemm(d16, w16 + WOFF_QS, b3, nullptr, nullptr, qkv, NK, Mm, 3 * Mm, 0);
    attn_tc<<<agrid, 256, ATTN_SMEM2>>>(qkv, qkv + 1024, qkv + 2048, 3072, 3072, 1, a16);
    launch_gemm(a16, w16 + WOFF_OS, bo_s, dec, x, nullptr, NK, Mm, Mm, 0);
    ln_kernel<<<NK, 256>>>(x, g1, be1, y, yh);

    // ---- cross attention (fused KV: J=2048) ----
    launch_gemm(yh, w16 + WOFF_QC, bq_c, nullptr, nullptr, q16, NK, Mm, Mm, 0);
    launch_gemm(e16, w16 + WOFF_KC, b2c, nullptr, nullptr, kv, NK, Mm, 2 * Mm, 0);
    attn_tc<<<agrid, 256, ATTN_SMEM2>>>(q16, kv, kv + 1024, 1024, 2048, 0, a16);
    launch_gemm(a16, w16 + WOFF_OC, bo_c, y, x, nullptr, NK, Mm, Mm, 0);
    ln_kernel<<<NK, 256>>>(x, g2, be2, z, zh);

    // ---- feedforward ----
    launch_gemm(zh, w16 + WOFF_W1, b1, nullptr, nullptr, h16, NK, Mm, Ff, 1);
    launch_gemm(h16, w16 + WOFF_W2, b2, z, x, nullptr, NK, Ff, Mm, 0);
    ln_kernel<<<NK, 256>>>(x, g3, be3, out, nullptr);
}